// round 1
// baseline (speedup 1.0000x reference)
#include <cuda_runtime.h>
#include <math.h>

#define NB 2
#define NS 2048
#define ND 1024
#define NH 16
#define NDH 64
#define MT (NB*NS)          // 4096 rows in all GEMMs

// Scratch (allocation-free rule: __device__ globals)
__device__ float g_q [NB*NH*NS*NDH];   // [B,H,S,DH]
__device__ float g_k [NB*NH*NS*NDH];
__device__ float g_v [NB*NH*NS*NDH];
__device__ float g_ao[NB*NS*ND];       // attention output in [B,S,D]

// ---------------------------------------------------------------------------
// GEMM body: 128x128 block tile, K-tile 16, 256 threads, 8x8 micro-tile.
// A natural-layout smem (padded, broadcast scalar reads), B k-major float4 reads.
// ---------------------------------------------------------------------------
#define GEMM_CORE(APTR, WPTR)                                                  \
    __shared__ float As[128][17];                                              \
    __shared__ float Bs[16][128];                                              \
    const int tid = threadIdx.x;                                               \
    const int tx = tid & 15, ty = tid >> 4;                                    \
    const int m0 = blockIdx.y * 128, n0 = blockIdx.x * 128;                    \
    float acc[8][8];                                                           \
    _Pragma("unroll")                                                          \
    for (int r = 0; r < 8; r++)                                                \
        _Pragma("unroll")                                                      \
        for (int c = 0; c < 8; c++) acc[r][c] = 0.f;                           \
    for (int k0 = 0; k0 < ND; k0 += 16) {                                      \
        _Pragma("unroll")                                                      \
        for (int i = 0; i < 8; i++) {                                          \
            int idx = tid + i * 256;                                           \
            int mm = idx >> 4, kk = idx & 15;                                  \
            As[mm][kk] = (APTR)[(size_t)(m0 + mm) * ND + k0 + kk];             \
        }                                                                      \
        _Pragma("unroll")                                                      \
        for (int i = 0; i < 8; i++) {                                          \
            int idx = tid + i * 256;                                           \
            int kk = idx >> 7, nn = idx & 127;                                 \
            Bs[kk][nn] = (WPTR)[(size_t)(k0 + kk) * ND + n0 + nn];             \
        }                                                                      \
        __syncthreads();                                                       \
        _Pragma("unroll")                                                      \
        for (int kk = 0; kk < 16; kk++) {                                      \
            float a[8];                                                        \
            _Pragma("unroll")                                                  \
            for (int r = 0; r < 8; r++) a[r] = As[ty * 8 + r][kk];             \
            float4 b0 = *(const float4*)&Bs[kk][tx * 8];                       \
            float4 b1 = *(const float4*)&Bs[kk][tx * 8 + 4];                   \
            float bb[8] = {b0.x, b0.y, b0.z, b0.w, b1.x, b1.y, b1.z, b1.w};    \
            _Pragma("unroll")                                                  \
            for (int r = 0; r < 8; r++)                                        \
                _Pragma("unroll")                                              \
                for (int c = 0; c < 8; c++)                                    \
                    acc[r][c] = fmaf(a[r], bb[c], acc[r][c]);                  \
        }                                                                      \
        __syncthreads();                                                       \
    }

// ---------------------------------------------------------------------------
// Fused QKV projection: z=0/1/2 -> Q/K/V. Writes [B,H,S,DH]; Q adds emotion.
// ---------------------------------------------------------------------------
__global__ __launch_bounds__(256) void qkv_gemm(
    const float* __restrict__ X,
    const float* __restrict__ Wq, const float* __restrict__ bq,
    const float* __restrict__ Wk, const float* __restrict__ bk,
    const float* __restrict__ Wv, const float* __restrict__ bv,
    const float* __restrict__ emo)
{
    const int z = blockIdx.z;
    const float* W    = (z == 0) ? Wq : (z == 1) ? Wk : Wv;
    const float* bias = (z == 0) ? bq : (z == 1) ? bk : bv;
    float* dst        = (z == 0) ? g_q : (z == 1) ? g_k : g_v;

    GEMM_CORE(X, W)

    #pragma unroll
    for (int r = 0; r < 8; r++) {
        int m = m0 + ty * 8 + r;
        int b = m >> 11;          // m / NS
        int s = m & (NS - 1);
        #pragma unroll
        for (int c = 0; c < 8; c++) {
            int n  = n0 + tx * 8 + c;
            int h  = n >> 6;
            int dh = n & 63;
            float v = acc[r][c] + bias[n];
            if (z == 0) v += emo[n];   // emo is [H,DH] contiguous == index n
            dst[(((size_t)b * NH + h) * NS + s) * NDH + dh] = v;
        }
    }
}

// ---------------------------------------------------------------------------
// Output projection: g_ao [4096,1024] @ Wo + bo -> out (row-major [B,S,D])
// ---------------------------------------------------------------------------
__global__ __launch_bounds__(256) void out_gemm(
    const float* __restrict__ Wo, const float* __restrict__ bo,
    float* __restrict__ out)
{
    GEMM_CORE(g_ao, Wo)

    #pragma unroll
    for (int r = 0; r < 8; r++) {
        int m = m0 + ty * 8 + r;
        #pragma unroll
        for (int c = 0; c < 8; c++) {
            int n = n0 + tx * 8 + c;
            out[(size_t)m * ND + n] = acc[r][c] + bo[n];
        }
    }
}

// ---------------------------------------------------------------------------
// Flash attention: 64 q-rows x 64 k-cols tiles, online softmax.
// smem: Qs [64][64] natural, KPs [64][65] (K tile, then reused for P), Vs [64][64].
// Thread grid 16x16, each thread owns a 4(rows) x 4(cols/dims) micro-tile.
// Row stats reduced over the 16 tx lanes via shfl (lanes 0-15 / 16-31 per warp).
// ---------------------------------------------------------------------------
#define ATT_SMEM_FLOATS (64*64 + 64*65 + 64*64)   // 12352 floats = 49408 B

__global__ __launch_bounds__(256) void attn_kernel(const int* __restrict__ mask)
{
    extern __shared__ float sm[];
    float* Qs  = sm;                 // [r*64 + d]
    float* KPs = sm + 64 * 64;       // K: [c*65 + d]; P: [r*65 + c]
    float* Vs  = sm + 64 * 64 + 64 * 65;  // [c*64 + d]

    const int bh = blockIdx.y;
    const int b  = bh / NH;
    const int h  = bh % NH;
    const int q0 = blockIdx.x * 64;
    const float* Qp = g_q + (size_t)bh * NS * NDH;
    const float* Kp = g_k + (size_t)bh * NS * NDH;
    const float* Vp = g_v + (size_t)bh * NS * NDH;
    const int* mrow = mask + b * NS;

    const int tid = threadIdx.x;
    const int tx = tid & 15, ty = tid >> 4;

    // Load Q tile (stays resident all iterations)
    for (int i = tid; i < 64 * 64; i += 256)
        Qs[i] = Qp[(size_t)(q0 + (i >> 6)) * NDH + (i & 63)];

    float m_run[4], l_run[4], o[4][4];
    #pragma unroll
    for (int r = 0; r < 4; r++) {
        m_run[r] = -1e30f; l_run[r] = 0.f;
        #pragma unroll
        for (int c = 0; c < 4; c++) o[r][c] = 0.f;
    }

    for (int kb = 0; kb < NS / 64; kb++) {
        const int k0g = kb * 64;
        __syncthreads();   // prev-iter P/V reads done (also covers Qs load)

        for (int i = tid; i < 64 * 64; i += 256) {
            int c = i >> 6, d = i & 63;
            KPs[c * 65 + d] = Kp[(size_t)(k0g + c) * NDH + d];
            Vs [c * 64 + d] = Vp[(size_t)(k0g + c) * NDH + d];
        }
        __syncthreads();

        // scores S = Q K^T  (k-dim = head dim, 64)
        float sc[4][4];
        #pragma unroll
        for (int r = 0; r < 4; r++)
            #pragma unroll
            for (int c = 0; c < 4; c++) sc[r][c] = 0.f;

        #pragma unroll 8
        for (int d = 0; d < 64; d++) {
            float a[4], bb[4];
            #pragma unroll
            for (int r = 0; r < 4; r++) a[r] = Qs[(ty * 4 + r) * 64 + d];
            #pragma unroll
            for (int c = 0; c < 4; c++) bb[c] = KPs[(tx * 4 + c) * 65 + d];
            #pragma unroll
            for (int r = 0; r < 4; r++)
                #pragma unroll
                for (int c = 0; c < 4; c++)
                    sc[r][c] = fmaf(a[r], bb[c], sc[r][c]);
        }

        // mask + scale
        int mk[4];
        #pragma unroll
        for (int c = 0; c < 4; c++) mk[c] = mrow[k0g + tx * 4 + c];
        #pragma unroll
        for (int r = 0; r < 4; r++)
            #pragma unroll
            for (int c = 0; c < 4; c++)
                sc[r][c] = mk[c] ? sc[r][c] * 0.125f : -1e30f;

        // online softmax per row (reduce across 16 tx lanes)
        #pragma unroll
        for (int r = 0; r < 4; r++) {
            float mloc = fmaxf(fmaxf(sc[r][0], sc[r][1]), fmaxf(sc[r][2], sc[r][3]));
            #pragma unroll
            for (int off = 8; off >= 1; off >>= 1)
                mloc = fmaxf(mloc, __shfl_xor_sync(0xffffffffu, mloc, off));
            float mnew = fmaxf(m_run[r], mloc);
            float ps = 0.f;
            #pragma unroll
            for (int c = 0; c < 4; c++) {
                float p = __expf(sc[r][c] - mnew);
                sc[r][c] = p;
                ps += p;
            }
            #pragma unroll
            for (int off = 8; off >= 1; off >>= 1)
                ps += __shfl_xor_sync(0xffffffffu, ps, off);
            float alpha = __expf(m_run[r] - mnew);
            l_run[r] = l_run[r] * alpha + ps;
            m_run[r] = mnew;
            #pragma unroll
            for (int c = 0; c < 4; c++) o[r][c] *= alpha;
        }

        __syncthreads();   // everyone finished reading K tile from KPs
        #pragma unroll
        for (int r = 0; r < 4; r++)
            #pragma unroll
            for (int c = 0; c < 4; c++)
                KPs[(ty * 4 + r) * 65 + (tx * 4 + c)] = sc[r][c];
        __syncthreads();

        // O += P V  (k-dim = key index, 64)
        #pragma unroll 8
        for (int c = 0; c < 64; c++) {
            float a[4], bb[4];
            #pragma unroll
            for (int r = 0; r < 4; r++) a[r] = KPs[(ty * 4 + r) * 65 + c];
            #pragma unroll
            for (int d = 0; d < 4; d++) bb[d] = Vs[c * 64 + tx * 4 + d];
            #pragma unroll
            for (int r = 0; r < 4; r++)
                #pragma unroll
                for (int d = 0; d < 4; d++)
                    o[r][d] = fmaf(a[r], bb[d], o[r][d]);
        }
    }

    // normalize + write [B,S,D]
    #pragma unroll
    for (int r = 0; r < 4; r++) {
        float inv = 1.0f / l_run[r];
        int srow = q0 + ty * 4 + r;
        #pragma unroll
        for (int d = 0; d < 4; d++)
            g_ao[((size_t)b * NS + srow) * ND + h * NDH + tx * 4 + d] = o[r][d] * inv;
    }
}

// ---------------------------------------------------------------------------
extern "C" void kernel_launch(void* const* d_in, const int* in_sizes, int n_in,
                              void* d_out, int out_size)
{
    const float* hs  = (const float*)d_in[0];
    const int*   msk = (const int*)  d_in[1];
    const float* Wq  = (const float*)d_in[2];
    const float* bq  = (const float*)d_in[3];
    const float* Wk  = (const float*)d_in[4];
    const float* bk  = (const float*)d_in[5];
    const float* Wv  = (const float*)d_in[6];
    const float* bv  = (const float*)d_in[7];
    const float* emo = (const float*)d_in[8];
    const float* Wo  = (const float*)d_in[9];
    const float* bo  = (const float*)d_in[10];
    float* out = (float*)d_out;

    // Eager (non-captured) device config; idempotent, deterministic.
    cudaFuncSetAttribute(attn_kernel, cudaFuncAttributeMaxDynamicSharedMemorySize,
                         ATT_SMEM_FLOATS * (int)sizeof(float));

    dim3 gqkv(ND / 128, MT / 128, 3);
    qkv_gemm<<<gqkv, 256>>>(hs, Wq, bq, Wk, bk, Wv, bv, emo);

    dim3 gatt(NS / 64, NB * NH);
    attn_kernel<<<gatt, 256, ATT_SMEM_FLOATS * (int)sizeof(float)>>>(msk);

    dim3 gout(ND / 128, MT / 128);
    out_gemm<<<gout, 256>>>(Wo, bo, out);
}

// round 3
// speedup vs baseline: 1.6030x; 1.6030x over previous
#include <cuda_runtime.h>
#include <cstdint>
#include <math.h>

#define NB 2
#define NS 2048
#define ND 1024
#define NH 16
#define NDH 64
#define MT (NB*NS)          // 4096 rows in all GEMMs

// Scratch (allocation-free rule: __device__ globals)
__device__ float g_q [NB*NH*NS*NDH];   // [B,H,S,DH]
__device__ float g_k [NB*NH*NS*NDH];
__device__ float g_v [NB*NH*NS*NDH];
__device__ float g_ao[NB*NS*ND];       // attention output in [B,S,D]

// ===========================================================================
// Portable tensor-core path: mma.sync m16n8k8 tf32 (valid on compute_103).
// ===========================================================================
__device__ __forceinline__ uint32_t smem_u32(const void* p) {
    uint32_t a;
    asm("{ .reg .u64 t; cvta.to.shared.u64 t, %1; cvt.u32.u64 %0, t; }"
        : "=r"(a) : "l"(p));
    return a;
}

__device__ __forceinline__ uint32_t f2tf32(float x) {
    uint32_t r;
    asm("cvt.rna.tf32.f32 %0, %1;" : "=r"(r) : "f"(x));
    return r;
}

__device__ __forceinline__ void mma_tf32(float (&c)[4],
                                         const uint32_t (&a)[4],
                                         const uint32_t (&b)[2]) {
    asm volatile(
        "mma.sync.aligned.m16n8k8.row.col.f32.tf32.tf32.f32 "
        "{%0,%1,%2,%3}, {%4,%5,%6,%7}, {%8,%9}, {%0,%1,%2,%3};"
        : "+f"(c[0]), "+f"(c[1]), "+f"(c[2]), "+f"(c[3])
        : "r"(a[0]), "r"(a[1]), "r"(a[2]), "r"(a[3]), "r"(b[0]), "r"(b[1]));
}

#define CP16(dst, src) \
    asm volatile("cp.async.cg.shared.global [%0], [%1], 16;" \
                 :: "r"(dst), "l"(src))
#define CP_COMMIT() asm volatile("cp.async.commit_group;" ::: "memory")
#define CP_WAIT1()  asm volatile("cp.async.wait_group 1;" ::: "memory")
#define CP_WAIT0()  asm volatile("cp.async.wait_group 0;" ::: "memory")

// smem geometry (floats): A[128][36] (bank 4g+tg bijective), B[32][136] (8tg+g)
#define A_STRIDE 36
#define B_STRIDE 136
#define A_BYTES  (128 * A_STRIDE * 4)   // 18432
#define B_BYTES  (32  * B_STRIDE * 4)   // 17408
#define STAGE_B  (A_BYTES + B_BYTES)    // 35840
#define GEMM_SMEM (2 * STAGE_B)         // 71680

// ---------------------------------------------------------------------------
// Core: acc[4][4][4] += A_blk[128,1024] @ W[1024,1024] tile (m0,n0).
// 256 threads; warp (wm=wid>>2, wn=wid&3) owns 64x32; 2-stage cp.async.
// ---------------------------------------------------------------------------
__device__ __forceinline__ void gemm_tf32_core(
    const float* __restrict__ A, const float* __restrict__ W,
    char* sm, int m0, int n0, float (&acc)[4][4][4])
{
    const int tid  = threadIdx.x;
    const int wid  = tid >> 5, lane = tid & 31;
    const int wm   = wid >> 2, wn = wid & 3;
    const int g    = lane >> 2, tg = lane & 3;

    #pragma unroll
    for (int mt = 0; mt < 4; mt++)
        #pragma unroll
        for (int nt = 0; nt < 4; nt++)
            #pragma unroll
            for (int i = 0; i < 4; i++) acc[mt][nt][i] = 0.f;

    const uint32_t sm_u = smem_u32(sm);

    auto issue_tile = [&](int kt, int bf) {
        const int k0 = kt * 32;
        const uint32_t as_u = sm_u + bf * STAGE_B;
        const uint32_t bs_u = as_u + A_BYTES;
        #pragma unroll
        for (int i = 0; i < 4; i++) {           // A: 128 rows x 32 f
            int f = tid + i * 256;
            int m = f >> 3, q = f & 7;
            CP16(as_u + m * (A_STRIDE * 4) + q * 16,
                 A + (size_t)(m0 + m) * ND + k0 + q * 4);
        }
        #pragma unroll
        for (int i = 0; i < 4; i++) {           // B: 32 rows x 128 f (no transpose)
            int f = tid + i * 256;
            int k = f >> 5, q = f & 31;
            CP16(bs_u + k * (B_STRIDE * 4) + q * 16,
                 W + (size_t)(k0 + k) * ND + n0 + q * 4);
        }
        CP_COMMIT();
    };

    issue_tile(0, 0);
    issue_tile(1, 1);

    for (int kt = 0; kt < 32; kt++) {
        const int bf = kt & 1;
        if (kt == 31) CP_WAIT0(); else CP_WAIT1();
        __syncthreads();

        const float* As = (const float*)(sm + bf * STAGE_B);
        const float* Bs = (const float*)(sm + bf * STAGE_B + A_BYTES);

        #pragma unroll
        for (int c = 0; c < 4; c++) {
            const int kk = c * 8;
            uint32_t a[4][4], b[4][2];
            #pragma unroll
            for (int mt = 0; mt < 4; mt++) {
                const float* ap = As + (size_t)(wm * 64 + mt * 16 + g) * A_STRIDE + kk + tg;
                a[mt][0] = f2tf32(ap[0]);
                a[mt][2] = f2tf32(ap[4]);
                a[mt][1] = f2tf32(ap[8 * A_STRIDE]);
                a[mt][3] = f2tf32(ap[8 * A_STRIDE + 4]);
            }
            #pragma unroll
            for (int nt = 0; nt < 4; nt++) {
                const float* bp = Bs + (size_t)(kk + tg) * B_STRIDE + wn * 32 + nt * 8 + g;
                b[nt][0] = f2tf32(bp[0]);
                b[nt][1] = f2tf32(bp[4 * B_STRIDE]);
            }
            #pragma unroll
            for (int mt = 0; mt < 4; mt++)
                #pragma unroll
                for (int nt = 0; nt < 4; nt++)
                    mma_tf32(acc[mt][nt], a[mt], b[nt]);
        }
        __syncthreads();
        if (kt + 2 < 32) issue_tile(kt + 2, bf);
    }
}

// ---------------------------------------------------------------------------
// QKV projection: z=0/1/2 -> Q/K/V written [B,H,S,DH]; Q adds emotion bias.
// ---------------------------------------------------------------------------
__global__ __launch_bounds__(256, 2) void qkv_gemm(
    const float* __restrict__ X,
    const float* __restrict__ Wq, const float* __restrict__ bq,
    const float* __restrict__ Wk, const float* __restrict__ bk,
    const float* __restrict__ Wv, const float* __restrict__ bv,
    const float* __restrict__ emo)
{
    extern __shared__ char sm[];
    const int z = blockIdx.z;
    const float* W    = (z == 0) ? Wq : (z == 1) ? Wk : Wv;
    const float* bias = (z == 0) ? bq : (z == 1) ? bk : bv;
    float* dst        = (z == 0) ? g_q : (z == 1) ? g_k : g_v;

    const int m0 = blockIdx.y * 128, n0 = blockIdx.x * 128;
    float acc[4][4][4];
    gemm_tf32_core(X, W, sm, m0, n0, acc);

    const int tid = threadIdx.x, wid = tid >> 5, lane = tid & 31;
    const int wm = wid >> 2, wn = wid & 3;
    const int g = lane >> 2, tg = lane & 3;

    #pragma unroll
    for (int mt = 0; mt < 4; mt++) {
        #pragma unroll
        for (int nt = 0; nt < 4; nt++) {
            const int n = n0 + wn * 32 + nt * 8 + 2 * tg;
            const int h = n >> 6, dh = n & 63;
            float b0 = bias[n]     + (z == 0 ? emo[n]     : 0.f);
            float b1 = bias[n + 1] + (z == 0 ? emo[n + 1] : 0.f);
            #pragma unroll
            for (int half = 0; half < 2; half++) {
                const int r = m0 + wm * 64 + mt * 16 + g + half * 8;
                const int bb = r >> 11, s = r & (NS - 1);
                float2 v = make_float2(acc[mt][nt][2 * half] + b0,
                                       acc[mt][nt][2 * half + 1] + b1);
                *(float2*)&dst[(((size_t)bb * NH + h) * NS + s) * NDH + dh] = v;
            }
        }
    }
}

// ---------------------------------------------------------------------------
// Output projection: g_ao @ Wo + bo -> out [B,S,D]
// ---------------------------------------------------------------------------
__global__ __launch_bounds__(256, 2) void out_gemm(
    const float* __restrict__ Wo, const float* __restrict__ bo,
    float* __restrict__ out)
{
    extern __shared__ char sm[];
    const int m0 = blockIdx.y * 128, n0 = blockIdx.x * 128;
    float acc[4][4][4];
    gemm_tf32_core(g_ao, Wo, sm, m0, n0, acc);

    const int tid = threadIdx.x, wid = tid >> 5, lane = tid & 31;
    const int wm = wid >> 2, wn = wid & 3;
    const int g = lane >> 2, tg = lane & 3;

    #pragma unroll
    for (int mt = 0; mt < 4; mt++) {
        #pragma unroll
        for (int nt = 0; nt < 4; nt++) {
            const int n = n0 + wn * 32 + nt * 8 + 2 * tg;
            float b0 = bo[n], b1 = bo[n + 1];
            #pragma unroll
            for (int half = 0; half < 2; half++) {
                const int r = m0 + wm * 64 + mt * 16 + g + half * 8;
                float2 v = make_float2(acc[mt][nt][2 * half] + b0,
                                       acc[mt][nt][2 * half + 1] + b1);
                *(float2*)&out[(size_t)r * ND + n] = v;
            }
        }
    }
}

// ---------------------------------------------------------------------------
// Flash attention (SIMT fp32, unchanged): 64x64 tiles, online softmax
// ---------------------------------------------------------------------------
#define ATT_SMEM_FLOATS (64*64 + 64*65 + 64*64)   // 49408 B

__global__ __launch_bounds__(256) void attn_kernel(const int* __restrict__ mask)
{
    extern __shared__ float smf[];
    float* Qs  = smf;
    float* KPs = smf + 64 * 64;
    float* Vs  = smf + 64 * 64 + 64 * 65;

    const int bh = blockIdx.y;
    const int b  = bh / NH;
    const int h  = bh % NH;
    const int q0 = blockIdx.x * 64;
    const float* Qp = g_q + (size_t)bh * NS * NDH;
    const float* Kp = g_k + (size_t)bh * NS * NDH;
    const float* Vp = g_v + (size_t)bh * NS * NDH;
    const int* mrow = mask + b * NS;

    const int tid = threadIdx.x;
    const int tx = tid & 15, ty = tid >> 4;

    for (int i = tid; i < 64 * 64; i += 256)
        Qs[i] = Qp[(size_t)(q0 + (i >> 6)) * NDH + (i & 63)];

    float m_run[4], l_run[4], o[4][4];
    #pragma unroll
    for (int r = 0; r < 4; r++) {
        m_run[r] = -1e30f; l_run[r] = 0.f;
        #pragma unroll
        for (int c = 0; c < 4; c++) o[r][c] = 0.f;
    }

    for (int kb = 0; kb < NS / 64; kb++) {
        const int k0g = kb * 64;
        __syncthreads();

        for (int i = tid; i < 64 * 64; i += 256) {
            int c = i >> 6, dd = i & 63;
            KPs[c * 65 + dd] = Kp[(size_t)(k0g + c) * NDH + dd];
            Vs [c * 64 + dd] = Vp[(size_t)(k0g + c) * NDH + dd];
        }
        __syncthreads();

        float sc[4][4];
        #pragma unroll
        for (int r = 0; r < 4; r++)
            #pragma unroll
            for (int c = 0; c < 4; c++) sc[r][c] = 0.f;

        #pragma unroll 8
        for (int dd = 0; dd < 64; dd++) {
            float a[4], bb[4];
            #pragma unroll
            for (int r = 0; r < 4; r++) a[r] = Qs[(ty * 4 + r) * 64 + dd];
            #pragma unroll
            for (int c = 0; c < 4; c++) bb[c] = KPs[(tx * 4 + c) * 65 + dd];
            #pragma unroll
            for (int r = 0; r < 4; r++)
                #pragma unroll
                for (int c = 0; c < 4; c++)
                    sc[r][c] = fmaf(a[r], bb[c], sc[r][c]);
        }

        int mk[4];
        #pragma unroll
        for (int c = 0; c < 4; c++) mk[c] = mrow[k0g + tx * 4 + c];
        #pragma unroll
        for (int r = 0; r < 4; r++)
            #pragma unroll
            for (int c = 0; c < 4; c++)
                sc[r][c] = mk[c] ? sc[r][c] * 0.125f : -1e30f;

        #pragma unroll
        for (int r = 0; r < 4; r++) {
            float mloc = fmaxf(fmaxf(sc[r][0], sc[r][1]), fmaxf(sc[r][2], sc[r][3]));
            #pragma unroll
            for (int off = 8; off >= 1; off >>= 1)
                mloc = fmaxf(mloc, __shfl_xor_sync(0xffffffffu, mloc, off));
            float mnew = fmaxf(m_run[r], mloc);
            float ps = 0.f;
            #pragma unroll
            for (int c = 0; c < 4; c++) {
                float p = __expf(sc[r][c] - mnew);
                sc[r][c] = p;
                ps += p;
            }
            #pragma unroll
            for (int off = 8; off >= 1; off >>= 1)
                ps += __shfl_xor_sync(0xffffffffu, ps, off);
            float alpha = __expf(m_run[r] - mnew);
            l_run[r] = l_run[r] * alpha + ps;
            m_run[r] = mnew;
            #pragma unroll
            for (int c = 0; c < 4; c++) o[r][c] *= alpha;
        }

        __syncthreads();
        #pragma unroll
        for (int r = 0; r < 4; r++)
            #pragma unroll
            for (int c = 0; c < 4; c++)
                KPs[(ty * 4 + r) * 65 + (tx * 4 + c)] = sc[r][c];
        __syncthreads();

        #pragma unroll 8
        for (int c = 0; c < 64; c++) {
            float a[4], bb[4];
            #pragma unroll
            for (int r = 0; r < 4; r++) a[r] = KPs[(ty * 4 + r) * 65 + c];
            #pragma unroll
            for (int dd = 0; dd < 4; dd++) bb[dd] = Vs[c * 64 + tx * 4 + dd];
            #pragma unroll
            for (int r = 0; r < 4; r++)
                #pragma unroll
                for (int dd = 0; dd < 4; dd++)
                    o[r][dd] = fmaf(a[r], bb[dd], o[r][dd]);
        }
    }

    #pragma unroll
    for (int r = 0; r < 4; r++) {
        float inv = 1.0f / l_run[r];
        int srow = q0 + ty * 4 + r;
        #pragma unroll
        for (int dd = 0; dd < 4; dd++)
            g_ao[((size_t)b * NS + srow) * ND + h * NDH + tx * 4 + dd] = o[r][dd] * inv;
    }
}

// ---------------------------------------------------------------------------
extern "C" void kernel_launch(void* const* d_in, const int* in_sizes, int n_in,
                              void* d_out, int out_size)
{
    const float* hs  = (const float*)d_in[0];
    const int*   msk = (const int*)  d_in[1];
    const float* Wq  = (const float*)d_in[2];
    const float* bq  = (const float*)d_in[3];
    const float* Wk  = (const float*)d_in[4];
    const float* bk  = (const float*)d_in[5];
    const float* Wv  = (const float*)d_in[6];
    const float* bv  = (const float*)d_in[7];
    const float* emo = (const float*)d_in[8];
    const float* Wo  = (const float*)d_in[9];
    const float* bo  = (const float*)d_in[10];
    float* out = (float*)d_out;

    cudaFuncSetAttribute(qkv_gemm, cudaFuncAttributeMaxDynamicSharedMemorySize, GEMM_SMEM);
    cudaFuncSetAttribute(out_gemm, cudaFuncAttributeMaxDynamicSharedMemorySize, GEMM_SMEM);
    cudaFuncSetAttribute(attn_kernel, cudaFuncAttributeMaxDynamicSharedMemorySize,
                         ATT_SMEM_FLOATS * (int)sizeof(float));

    dim3 gqkv(ND / 128, MT / 128, 3);
    qkv_gemm<<<gqkv, 256, GEMM_SMEM>>>(hs, Wq, bq, Wk, bk, Wv, bv, emo);

    dim3 gatt(NS / 64, NB * NH);
    attn_kernel<<<gatt, 256, ATT_SMEM_FLOATS * (int)sizeof(float)>>>(msk);

    dim3 gout(ND / 128, MT / 128);
    out_gemm<<<gout, 256, GEMM_SMEM>>>(Wo, bo, out);
}

// round 4
// speedup vs baseline: 2.5470x; 1.5889x over previous
#include <cuda_runtime.h>
#include <cuda_bf16.h>
#include <cstdint>
#include <math.h>

#define NB 2
#define NS 2048
#define ND 1024
#define NH 16
#define NDH 64
#define MT (NB*NS)          // 4096 rows in all GEMMs

// Scratch (allocation-free rule: __device__ globals)
__device__ float g_q [NB*NH*NS*NDH];   // [B,H,S,DH]
__device__ float g_k [NB*NH*NS*NDH];
__device__ float g_v [NB*NH*NS*NDH];
__device__ float g_ao[NB*NS*ND];       // attention output in [B,S,D]

// ===========================================================================
// Portable tensor-core helpers (valid on compute_103 target)
// ===========================================================================
__device__ __forceinline__ uint32_t smem_u32(const void* p) {
    uint32_t a;
    asm("{ .reg .u64 t; cvta.to.shared.u64 t, %1; cvt.u32.u64 %0, t; }"
        : "=r"(a) : "l"(p));
    return a;
}

__device__ __forceinline__ uint32_t f2tf32(float x) {
    uint32_t r;
    asm("cvt.rna.tf32.f32 %0, %1;" : "=r"(r) : "f"(x));
    return r;
}

__device__ __forceinline__ void mma_tf32(float (&c)[4],
                                         const uint32_t (&a)[4],
                                         const uint32_t (&b)[2]) {
    asm volatile(
        "mma.sync.aligned.m16n8k8.row.col.f32.tf32.tf32.f32 "
        "{%0,%1,%2,%3}, {%4,%5,%6,%7}, {%8,%9}, {%0,%1,%2,%3};"
        : "+f"(c[0]), "+f"(c[1]), "+f"(c[2]), "+f"(c[3])
        : "r"(a[0]), "r"(a[1]), "r"(a[2]), "r"(a[3]), "r"(b[0]), "r"(b[1]));
}

__device__ __forceinline__ void mma_bf16(float (&c)[4],
                                         const uint32_t (&a)[4],
                                         const uint32_t (&b)[2]) {
    asm volatile(
        "mma.sync.aligned.m16n8k16.row.col.f32.bf16.bf16.f32 "
        "{%0,%1,%2,%3}, {%4,%5,%6,%7}, {%8,%9}, {%0,%1,%2,%3};"
        : "+f"(c[0]), "+f"(c[1]), "+f"(c[2]), "+f"(c[3])
        : "r"(a[0]), "r"(a[1]), "r"(a[2]), "r"(a[3]), "r"(b[0]), "r"(b[1]));
}

// Split a pair of floats into packed bf16x2 hi + lo (x0 -> low half)
__device__ __forceinline__ void split2(float x0, float x1,
                                       uint32_t& hi, uint32_t& lo) {
    __nv_bfloat162 h = __floats2bfloat162_rn(x0, x1);
    float2 hf = __bfloat1622float2(h);
    __nv_bfloat162 l = __floats2bfloat162_rn(x0 - hf.x, x1 - hf.y);
    hi = *(uint32_t*)&h;
    lo = *(uint32_t*)&l;
}

#define CP16(dst, src) \
    asm volatile("cp.async.cg.shared.global [%0], [%1], 16;" \
                 :: "r"(dst), "l"(src))
#define CP_COMMIT() asm volatile("cp.async.commit_group;" ::: "memory")
#define CP_WAIT1()  asm volatile("cp.async.wait_group 1;" ::: "memory")
#define CP_WAIT0()  asm volatile("cp.async.wait_group 0;" ::: "memory")

// smem geometry (floats): A[128][36] (bank 4g+tg bijective), B[32][136] (8tg+g)
#define A_STRIDE 36
#define B_STRIDE 136
#define A_BYTES  (128 * A_STRIDE * 4)   // 18432
#define B_BYTES  (32  * B_STRIDE * 4)   // 17408
#define STAGE_B  (A_BYTES + B_BYTES)    // 35840
#define GEMM_SMEM (2 * STAGE_B)         // 71680

// ---------------------------------------------------------------------------
// tf32 GEMM core (unchanged from R3): 128x128 tile, 2-stage cp.async
// ---------------------------------------------------------------------------
__device__ __forceinline__ void gemm_tf32_core(
    const float* __restrict__ A, const float* __restrict__ W,
    char* sm, int m0, int n0, float (&acc)[4][4][4])
{
    const int tid  = threadIdx.x;
    const int wid  = tid >> 5, lane = tid & 31;
    const int wm   = wid >> 2, wn = wid & 3;
    const int g    = lane >> 2, tg = lane & 3;

    #pragma unroll
    for (int mt = 0; mt < 4; mt++)
        #pragma unroll
        for (int nt = 0; nt < 4; nt++)
            #pragma unroll
            for (int i = 0; i < 4; i++) acc[mt][nt][i] = 0.f;

    const uint32_t sm_u = smem_u32(sm);

    auto issue_tile = [&](int kt, int bf) {
        const int k0 = kt * 32;
        const uint32_t as_u = sm_u + bf * STAGE_B;
        const uint32_t bs_u = as_u + A_BYTES;
        #pragma unroll
        for (int i = 0; i < 4; i++) {
            int f = tid + i * 256;
            int m = f >> 3, q = f & 7;
            CP16(as_u + m * (A_STRIDE * 4) + q * 16,
                 A + (size_t)(m0 + m) * ND + k0 + q * 4);
        }
        #pragma unroll
        for (int i = 0; i < 4; i++) {
            int f = tid + i * 256;
            int k = f >> 5, q = f & 31;
            CP16(bs_u + k * (B_STRIDE * 4) + q * 16,
                 W + (size_t)(k0 + k) * ND + n0 + q * 4);
        }
        CP_COMMIT();
    };

    issue_tile(0, 0);
    issue_tile(1, 1);

    for (int kt = 0; kt < 32; kt++) {
        const int bf = kt & 1;
        if (kt == 31) CP_WAIT0(); else CP_WAIT1();
        __syncthreads();

        const float* As = (const float*)(sm + bf * STAGE_B);
        const float* Bs = (const float*)(sm + bf * STAGE_B + A_BYTES);

        #pragma unroll
        for (int c = 0; c < 4; c++) {
            const int kk = c * 8;
            uint32_t a[4][4], b[4][2];
            #pragma unroll
            for (int mt = 0; mt < 4; mt++) {
                const float* ap = As + (size_t)(wm * 64 + mt * 16 + g) * A_STRIDE + kk + tg;
                a[mt][0] = f2tf32(ap[0]);
                a[mt][2] = f2tf32(ap[4]);
                a[mt][1] = f2tf32(ap[8 * A_STRIDE]);
                a[mt][3] = f2tf32(ap[8 * A_STRIDE + 4]);
            }
            #pragma unroll
            for (int nt = 0; nt < 4; nt++) {
                const float* bp = Bs + (size_t)(kk + tg) * B_STRIDE + wn * 32 + nt * 8 + g;
                b[nt][0] = f2tf32(bp[0]);
                b[nt][1] = f2tf32(bp[4 * B_STRIDE]);
            }
            #pragma unroll
            for (int mt = 0; mt < 4; mt++)
                #pragma unroll
                for (int nt = 0; nt < 4; nt++)
                    mma_tf32(acc[mt][nt], a[mt], b[nt]);
        }
        __syncthreads();
        if (kt + 2 < 32) issue_tile(kt + 2, bf);
    }
}

// ---------------------------------------------------------------------------
// QKV projection: z=0/1/2 -> Q/K/V written [B,H,S,DH]; Q adds emotion bias.
// ---------------------------------------------------------------------------
__global__ __launch_bounds__(256, 2) void qkv_gemm(
    const float* __restrict__ X,
    const float* __restrict__ Wq, const float* __restrict__ bq,
    const float* __restrict__ Wk, const float* __restrict__ bk,
    const float* __restrict__ Wv, const float* __restrict__ bv,
    const float* __restrict__ emo)
{
    extern __shared__ char sm[];
    const int z = blockIdx.z;
    const float* W    = (z == 0) ? Wq : (z == 1) ? Wk : Wv;
    const float* bias = (z == 0) ? bq : (z == 1) ? bk : bv;
    float* dst        = (z == 0) ? g_q : (z == 1) ? g_k : g_v;

    const int m0 = blockIdx.y * 128, n0 = blockIdx.x * 128;
    float acc[4][4][4];
    gemm_tf32_core(X, W, sm, m0, n0, acc);

    const int tid = threadIdx.x, wid = tid >> 5, lane = tid & 31;
    const int wm = wid >> 2, wn = wid & 3;
    const int g = lane >> 2, tg = lane & 3;

    #pragma unroll
    for (int mt = 0; mt < 4; mt++) {
        #pragma unroll
        for (int nt = 0; nt < 4; nt++) {
            const int n = n0 + wn * 32 + nt * 8 + 2 * tg;
            const int h = n >> 6, dh = n & 63;
            float b0 = bias[n]     + (z == 0 ? emo[n]     : 0.f);
            float b1 = bias[n + 1] + (z == 0 ? emo[n + 1] : 0.f);
            #pragma unroll
            for (int half = 0; half < 2; half++) {
                const int r = m0 + wm * 64 + mt * 16 + g + half * 8;
                const int bb = r >> 11, s = r & (NS - 1);
                float2 v = make_float2(acc[mt][nt][2 * half] + b0,
                                       acc[mt][nt][2 * half + 1] + b1);
                *(float2*)&dst[(((size_t)bb * NH + h) * NS + s) * NDH + dh] = v;
            }
        }
    }
}

// ---------------------------------------------------------------------------
// Output projection: g_ao @ Wo + bo -> out [B,S,D]
// ---------------------------------------------------------------------------
__global__ __launch_bounds__(256, 2) void out_gemm(
    const float* __restrict__ Wo, const float* __restrict__ bo,
    float* __restrict__ out)
{
    extern __shared__ char sm[];
    const int m0 = blockIdx.y * 128, n0 = blockIdx.x * 128;
    float acc[4][4][4];
    gemm_tf32_core(g_ao, Wo, sm, m0, n0, acc);

    const int tid = threadIdx.x, wid = tid >> 5, lane = tid & 31;
    const int wm = wid >> 2, wn = wid & 3;
    const int g = lane >> 2, tg = lane & 3;

    #pragma unroll
    for (int mt = 0; mt < 4; mt++) {
        #pragma unroll
        for (int nt = 0; nt < 4; nt++) {
            const int n = n0 + wn * 32 + nt * 8 + 2 * tg;
            float b0 = bo[n], b1 = bo[n + 1];
            #pragma unroll
            for (int half = 0; half < 2; half++) {
                const int r = m0 + wm * 64 + mt * 16 + g + half * 8;
                float2 v = make_float2(acc[mt][nt][2 * half] + b0,
                                       acc[mt][nt][2 * half + 1] + b1);
                *(float2*)&out[(size_t)r * ND + n] = v;
            }
        }
    }
}

// ---------------------------------------------------------------------------
// Flash attention, bf16 3-term-split tensor cores.
// 128 q-rows/CTA, 8 warps, warp owns 16 rows x all 64 k-cols.
// K smem [kpos][d], V smem transposed [d][kpos]; stride 72 halves (bank-free).
// ---------------------------------------------------------------------------
#define KV_STRIDE 72

__global__ __launch_bounds__(256, 1) void attn_kernel(const int* __restrict__ mask)
{
    __shared__ unsigned short Ksm_hi[64 * KV_STRIDE];
    __shared__ unsigned short Ksm_lo[64 * KV_STRIDE];
    __shared__ unsigned short VT_hi [64 * KV_STRIDE];
    __shared__ unsigned short VT_lo [64 * KV_STRIDE];
    __shared__ float mb[64];

    const int bh = blockIdx.y;
    const int b  = bh >> 4;
    const int h  = bh & 15;
    const int q0 = blockIdx.x * 128;
    const float* Qp = g_q + (size_t)bh * NS * NDH;
    const float* Kp = g_k + (size_t)bh * NS * NDH;
    const float* Vp = g_v + (size_t)bh * NS * NDH;
    const int* mrow = mask + b * NS;

    const int tid = threadIdx.x, wid = tid >> 5, lane = tid & 31;
    const int g = lane >> 2, tg = lane & 3;

    // Q fragments (pre-scaled by 1/8), bf16 hi/lo, resident in registers
    uint32_t qh[4][4], ql[4][4];
    {
        const float* q0p = Qp + (size_t)(q0 + wid * 16 + g) * NDH;
        const float* q1p = q0p + 8 * NDH;
        #pragma unroll
        for (int kk = 0; kk < 4; kk++) {
            float2 x;
            x = *(const float2*)(q0p + kk * 16 + 2 * tg);
            split2(0.125f * x.x, 0.125f * x.y, qh[kk][0], ql[kk][0]);
            x = *(const float2*)(q1p + kk * 16 + 2 * tg);
            split2(0.125f * x.x, 0.125f * x.y, qh[kk][1], ql[kk][1]);
            x = *(const float2*)(q0p + kk * 16 + 2 * tg + 8);
            split2(0.125f * x.x, 0.125f * x.y, qh[kk][2], ql[kk][2]);
            x = *(const float2*)(q1p + kk * 16 + 2 * tg + 8);
            split2(0.125f * x.x, 0.125f * x.y, qh[kk][3], ql[kk][3]);
        }
    }

    float o[8][4];
    #pragma unroll
    for (int nt = 0; nt < 8; nt++)
        #pragma unroll
        for (int i = 0; i < 4; i++) o[nt][i] = 0.f;
    float mrun[2] = {-1e30f, -1e30f}, lrun[2] = {0.f, 0.f};

    for (int kb = 0; kb < NS / 64; kb++) {
        const int k0g = kb * 64;
        __syncthreads();   // previous iteration done reading smem

        // ---- load + convert K (natural) and V (transposed) tiles ----
        for (int i = tid; i < 1024; i += 256) {
            const int kp = i >> 4, dq = (i & 15) * 4;
            float4 kv = *(const float4*)(Kp + (size_t)(k0g + kp) * NDH + dq);
            uint32_t h0, l0, h1, l1;
            split2(kv.x, kv.y, h0, l0);
            split2(kv.z, kv.w, h1, l1);
            *(uint32_t*)&Ksm_hi[kp * KV_STRIDE + dq]     = h0;
            *(uint32_t*)&Ksm_hi[kp * KV_STRIDE + dq + 2] = h1;
            *(uint32_t*)&Ksm_lo[kp * KV_STRIDE + dq]     = l0;
            *(uint32_t*)&Ksm_lo[kp * KV_STRIDE + dq + 2] = l1;

            float4 vv = *(const float4*)(Vp + (size_t)(k0g + kp) * NDH + dq);
            #pragma unroll
            for (int e = 0; e < 4; e++) {
                float x = (&vv.x)[e];
                __nv_bfloat16 hh = __float2bfloat16_rn(x);
                float hf = __bfloat162float(hh);
                __nv_bfloat16 ll = __float2bfloat16_rn(x - hf);
                VT_hi[(dq + e) * KV_STRIDE + kp] = *(unsigned short*)&hh;
                VT_lo[(dq + e) * KV_STRIDE + kp] = *(unsigned short*)&ll;
            }
        }
        if (tid < 64) mb[tid] = mrow[k0g + tid] ? 0.f : -1e30f;
        __syncthreads();

        // ---- S = (Q/8) K^T via split bf16 mma ----
        float sc[8][4];
        #pragma unroll
        for (int nt = 0; nt < 8; nt++)
            #pragma unroll
            for (int i = 0; i < 4; i++) sc[nt][i] = 0.f;

        #pragma unroll
        for (int kk = 0; kk < 4; kk++) {
            #pragma unroll
            for (int nt = 0; nt < 8; nt++) {
                const int base = (nt * 8 + g) * KV_STRIDE + kk * 16 + 2 * tg;
                uint32_t bh2[2] = { *(const uint32_t*)&Ksm_hi[base],
                                    *(const uint32_t*)&Ksm_hi[base + 8] };
                uint32_t bl2[2] = { *(const uint32_t*)&Ksm_lo[base],
                                    *(const uint32_t*)&Ksm_lo[base + 8] };
                mma_bf16(sc[nt], qh[kk], bh2);
                mma_bf16(sc[nt], qh[kk], bl2);
                mma_bf16(sc[nt], ql[kk], bh2);
            }
        }

        // ---- mask bias ----
        #pragma unroll
        for (int nt = 0; nt < 8; nt++) {
            float2 mv = *(const float2*)&mb[nt * 8 + 2 * tg];
            sc[nt][0] += mv.x; sc[nt][1] += mv.y;
            sc[nt][2] += mv.x; sc[nt][3] += mv.y;
        }

        // ---- online softmax (rows g and g+8; quad shfl reduction) ----
        #pragma unroll
        for (int r = 0; r < 2; r++) {
            float mx = -1e30f;
            #pragma unroll
            for (int nt = 0; nt < 8; nt++)
                mx = fmaxf(mx, fmaxf(sc[nt][2 * r], sc[nt][2 * r + 1]));
            mx = fmaxf(mx, __shfl_xor_sync(0xffffffffu, mx, 1));
            mx = fmaxf(mx, __shfl_xor_sync(0xffffffffu, mx, 2));
            const float mn = fmaxf(mrun[r], mx);
            float sum = 0.f;
            #pragma unroll
            for (int nt = 0; nt < 8; nt++) {
                float p0 = __expf(sc[nt][2 * r]     - mn);
                float p1 = __expf(sc[nt][2 * r + 1] - mn);
                sc[nt][2 * r] = p0; sc[nt][2 * r + 1] = p1;
                sum += p0 + p1;
            }
            sum += __shfl_xor_sync(0xffffffffu, sum, 1);
            sum += __shfl_xor_sync(0xffffffffu, sum, 2);
            const float al = __expf(mrun[r] - mn);
            lrun[r] = lrun[r] * al + sum;
            mrun[r] = mn;
            #pragma unroll
            for (int nt = 0; nt < 8; nt++) {
                o[nt][2 * r]     *= al;
                o[nt][2 * r + 1] *= al;
            }
        }

        // ---- O += P V via split bf16 mma (P frags from S acc, reg-only) ----
        #pragma unroll
        for (int kk = 0; kk < 4; kk++) {
            uint32_t ph[4], pl[4];
            split2(sc[2 * kk][0],     sc[2 * kk][1],     ph[0], pl[0]);
            split2(sc[2 * kk][2],     sc[2 * kk][3],     ph[1], pl[1]);
            split2(sc[2 * kk + 1][0], sc[2 * kk + 1][1], ph[2], pl[2]);
            split2(sc[2 * kk + 1][2], sc[2 * kk + 1][3], ph[3], pl[3]);
            #pragma unroll
            for (int nt = 0; nt < 8; nt++) {
                const int base = (nt * 8 + g) * KV_STRIDE + kk * 16 + 2 * tg;
                uint32_t vh2[2] = { *(const uint32_t*)&VT_hi[base],
                                    *(const uint32_t*)&VT_hi[base + 8] };
                uint32_t vl2[2] = { *(const uint32_t*)&VT_lo[base],
                                    *(const uint32_t*)&VT_lo[base + 8] };
                mma_bf16(o[nt], ph, vh2);
                mma_bf16(o[nt], ph, vl2);
                mma_bf16(o[nt], pl, vh2);
            }
        }
    }

    // ---- normalize + write g_ao [B,S,D] ----
    const float inv0 = 1.0f / lrun[0];
    const float inv1 = 1.0f / lrun[1];
    const int r0 = q0 + wid * 16 + g;
    float* base0 = g_ao + ((size_t)b * NS + r0) * ND + h * NDH;
    float* base1 = base0 + 8 * (size_t)ND;
    #pragma unroll
    for (int nt = 0; nt < 8; nt++) {
        const int col = nt * 8 + 2 * tg;
        *(float2*)(base0 + col) = make_float2(o[nt][0] * inv0, o[nt][1] * inv0);
        *(float2*)(base1 + col) = make_float2(o[nt][2] * inv1, o[nt][3] * inv1);
    }
}

// ---------------------------------------------------------------------------
extern "C" void kernel_launch(void* const* d_in, const int* in_sizes, int n_in,
                              void* d_out, int out_size)
{
    const float* hs  = (const float*)d_in[0];
    const int*   msk = (const int*)  d_in[1];
    const float* Wq  = (const float*)d_in[2];
    const float* bq  = (const float*)d_in[3];
    const float* Wk  = (const float*)d_in[4];
    const float* bk  = (const float*)d_in[5];
    const float* Wv  = (const float*)d_in[6];
    const float* bv  = (const float*)d_in[7];
    const float* emo = (const float*)d_in[8];
    const float* Wo  = (const float*)d_in[9];
    const float* bo  = (const float*)d_in[10];
    float* out = (float*)d_out;

    cudaFuncSetAttribute(qkv_gemm, cudaFuncAttributeMaxDynamicSharedMemorySize, GEMM_SMEM);
    cudaFuncSetAttribute(out_gemm, cudaFuncAttributeMaxDynamicSharedMemorySize, GEMM_SMEM);

    dim3 gqkv(ND / 128, MT / 128, 3);
    qkv_gemm<<<gqkv, 256, GEMM_SMEM>>>(hs, Wq, bq, Wk, bk, Wv, bv, emo);

    dim3 gatt(NS / 128, NB * NH);
    attn_kernel<<<gatt, 256>>>(msk);

    dim3 gout(ND / 128, MT / 128);
    out_gemm<<<gout, 256, GEMM_SMEM>>>(Wo, bo, out);
}

// round 5
// speedup vs baseline: 3.1776x; 1.2476x over previous
#include <cuda_runtime.h>
#include <cuda_bf16.h>
#include <cstdint>
#include <math.h>

#define NB 2
#define NS 2048
#define ND 1024
#define NH 16
#define NDH 64
#define MT (NB*NS)          // 4096 rows in all GEMMs

// Scratch (allocation-free rule: __device__ globals)
__device__ float g_q [NB*NH*NS*NDH];   // [B,H,S,DH]
__device__ float g_k [NB*NH*NS*NDH];
__device__ float g_v [NB*NH*NS*NDH];
__device__ float g_ao[NB*NS*ND];       // attention output in [B,S,D]
// Pre-split bf16 K (natural [bh][s][d]) and V (transposed [bh][d][s])
__device__ unsigned short g_kh16 [NB*NH*NS*NDH];
__device__ unsigned short g_kl16 [NB*NH*NS*NDH];
__device__ unsigned short g_vth16[NB*NH*NS*NDH];
__device__ unsigned short g_vtl16[NB*NH*NS*NDH];

// ===========================================================================
// Portable tensor-core helpers (valid on compute_103 target)
// ===========================================================================
__device__ __forceinline__ uint32_t smem_u32(const void* p) {
    uint32_t a;
    asm("{ .reg .u64 t; cvta.to.shared.u64 t, %1; cvt.u32.u64 %0, t; }"
        : "=r"(a) : "l"(p));
    return a;
}

__device__ __forceinline__ uint32_t f2tf32(float x) {
    uint32_t r;
    asm("cvt.rna.tf32.f32 %0, %1;" : "=r"(r) : "f"(x));
    return r;
}

__device__ __forceinline__ void mma_tf32(float (&c)[4],
                                         const uint32_t (&a)[4],
                                         const uint32_t (&b)[2]) {
    asm volatile(
        "mma.sync.aligned.m16n8k8.row.col.f32.tf32.tf32.f32 "
        "{%0,%1,%2,%3}, {%4,%5,%6,%7}, {%8,%9}, {%0,%1,%2,%3};"
        : "+f"(c[0]), "+f"(c[1]), "+f"(c[2]), "+f"(c[3])
        : "r"(a[0]), "r"(a[1]), "r"(a[2]), "r"(a[3]), "r"(b[0]), "r"(b[1]));
}

__device__ __forceinline__ void mma_bf16(float (&c)[4],
                                         const uint32_t (&a)[4],
                                         const uint32_t (&b)[2]) {
    asm volatile(
        "mma.sync.aligned.m16n8k16.row.col.f32.bf16.bf16.f32 "
        "{%0,%1,%2,%3}, {%4,%5,%6,%7}, {%8,%9}, {%0,%1,%2,%3};"
        : "+f"(c[0]), "+f"(c[1]), "+f"(c[2]), "+f"(c[3])
        : "r"(a[0]), "r"(a[1]), "r"(a[2]), "r"(a[3]), "r"(b[0]), "r"(b[1]));
}

// Split a pair of floats into packed bf16x2 hi + lo (x0 -> low half)
__device__ __forceinline__ void split2(float x0, float x1,
                                       uint32_t& hi, uint32_t& lo) {
    __nv_bfloat162 h = __floats2bfloat162_rn(x0, x1);
    float2 hf = __bfloat1622float2(h);
    __nv_bfloat162 l = __floats2bfloat162_rn(x0 - hf.x, x1 - hf.y);
    hi = *(uint32_t*)&h;
    lo = *(uint32_t*)&l;
}

#define CP16(dst, src) \
    asm volatile("cp.async.cg.shared.global [%0], [%1], 16;" \
                 :: "r"(dst), "l"(src))
#define CP_COMMIT() asm volatile("cp.async.commit_group;" ::: "memory")
#define CP_WAIT1()  asm volatile("cp.async.wait_group 1;" ::: "memory")
#define CP_WAIT0()  asm volatile("cp.async.wait_group 0;" ::: "memory")

// smem geometry (floats): A[128][36] (bank 4g+tg bijective), B[32][136] (8tg+g)
#define A_STRIDE 36
#define B_STRIDE 136
#define A_BYTES  (128 * A_STRIDE * 4)   // 18432
#define B_BYTES  (32  * B_STRIDE * 4)   // 17408
#define STAGE_B  (A_BYTES + B_BYTES)    // 35840
#define GEMM_SMEM (2 * STAGE_B)         // 71680

// ---------------------------------------------------------------------------
// tf32 GEMM core (unchanged): 128x128 tile, 2-stage cp.async
// ---------------------------------------------------------------------------
__device__ __forceinline__ void gemm_tf32_core(
    const float* __restrict__ A, const float* __restrict__ W,
    char* sm, int m0, int n0, float (&acc)[4][4][4])
{
    const int tid  = threadIdx.x;
    const int wid  = tid >> 5, lane = tid & 31;
    const int wm   = wid >> 2, wn = wid & 3;
    const int g    = lane >> 2, tg = lane & 3;

    #pragma unroll
    for (int mt = 0; mt < 4; mt++)
        #pragma unroll
        for (int nt = 0; nt < 4; nt++)
            #pragma unroll
            for (int i = 0; i < 4; i++) acc[mt][nt][i] = 0.f;

    const uint32_t sm_u = smem_u32(sm);

    auto issue_tile = [&](int kt, int bf) {
        const int k0 = kt * 32;
        const uint32_t as_u = sm_u + bf * STAGE_B;
        const uint32_t bs_u = as_u + A_BYTES;
        #pragma unroll
        for (int i = 0; i < 4; i++) {
            int f = tid + i * 256;
            int m = f >> 3, q = f & 7;
            CP16(as_u + m * (A_STRIDE * 4) + q * 16,
                 A + (size_t)(m0 + m) * ND + k0 + q * 4);
        }
        #pragma unroll
        for (int i = 0; i < 4; i++) {
            int f = tid + i * 256;
            int k = f >> 5, q = f & 31;
            CP16(bs_u + k * (B_STRIDE * 4) + q * 16,
                 W + (size_t)(k0 + k) * ND + n0 + q * 4);
        }
        CP_COMMIT();
    };

    issue_tile(0, 0);
    issue_tile(1, 1);

    for (int kt = 0; kt < 32; kt++) {
        const int bf = kt & 1;
        if (kt == 31) CP_WAIT0(); else CP_WAIT1();
        __syncthreads();

        const float* As = (const float*)(sm + bf * STAGE_B);
        const float* Bs = (const float*)(sm + bf * STAGE_B + A_BYTES);

        #pragma unroll
        for (int c = 0; c < 4; c++) {
            const int kk = c * 8;
            uint32_t a[4][4], b[4][2];
            #pragma unroll
            for (int mt = 0; mt < 4; mt++) {
                const float* ap = As + (size_t)(wm * 64 + mt * 16 + g) * A_STRIDE + kk + tg;
                a[mt][0] = f2tf32(ap[0]);
                a[mt][2] = f2tf32(ap[4]);
                a[mt][1] = f2tf32(ap[8 * A_STRIDE]);
                a[mt][3] = f2tf32(ap[8 * A_STRIDE + 4]);
            }
            #pragma unroll
            for (int nt = 0; nt < 4; nt++) {
                const float* bp = Bs + (size_t)(kk + tg) * B_STRIDE + wn * 32 + nt * 8 + g;
                b[nt][0] = f2tf32(bp[0]);
                b[nt][1] = f2tf32(bp[4 * B_STRIDE]);
            }
            #pragma unroll
            for (int mt = 0; mt < 4; mt++)
                #pragma unroll
                for (int nt = 0; nt < 4; nt++)
                    mma_tf32(acc[mt][nt], a[mt], b[nt]);
        }
        __syncthreads();
        if (kt + 2 < 32) issue_tile(kt + 2, bf);
    }
}

// ---------------------------------------------------------------------------
// QKV projection: z=0/1/2 -> Q/K/V written [B,H,S,DH]; Q adds emotion bias.
// ---------------------------------------------------------------------------
__global__ __launch_bounds__(256, 2) void qkv_gemm(
    const float* __restrict__ X,
    const float* __restrict__ Wq, const float* __restrict__ bq,
    const float* __restrict__ Wk, const float* __restrict__ bk,
    const float* __restrict__ Wv, const float* __restrict__ bv,
    const float* __restrict__ emo)
{
    extern __shared__ char sm[];
    const int z = blockIdx.z;
    const float* W    = (z == 0) ? Wq : (z == 1) ? Wk : Wv;
    const float* bias = (z == 0) ? bq : (z == 1) ? bk : bv;
    float* dst        = (z == 0) ? g_q : (z == 1) ? g_k : g_v;

    const int m0 = blockIdx.y * 128, n0 = blockIdx.x * 128;
    float acc[4][4][4];
    gemm_tf32_core(X, W, sm, m0, n0, acc);

    const int tid = threadIdx.x, wid = tid >> 5, lane = tid & 31;
    const int wm = wid >> 2, wn = wid & 3;
    const int g = lane >> 2, tg = lane & 3;

    #pragma unroll
    for (int mt = 0; mt < 4; mt++) {
        #pragma unroll
        for (int nt = 0; nt < 4; nt++) {
            const int n = n0 + wn * 32 + nt * 8 + 2 * tg;
            const int h = n >> 6, dh = n & 63;
            float b0 = bias[n]     + (z == 0 ? emo[n]     : 0.f);
            float b1 = bias[n + 1] + (z == 0 ? emo[n + 1] : 0.f);
            #pragma unroll
            for (int half = 0; half < 2; half++) {
                const int r = m0 + wm * 64 + mt * 16 + g + half * 8;
                const int bb = r >> 11, s = r & (NS - 1);
                float2 v = make_float2(acc[mt][nt][2 * half] + b0,
                                       acc[mt][nt][2 * half + 1] + b1);
                *(float2*)&dst[(((size_t)bb * NH + h) * NS + s) * NDH + dh] = v;
            }
        }
    }
}

// ---------------------------------------------------------------------------
// Output projection: g_ao @ Wo + bo -> out [B,S,D]
// ---------------------------------------------------------------------------
__global__ __launch_bounds__(256, 2) void out_gemm(
    const float* __restrict__ Wo, const float* __restrict__ bo,
    float* __restrict__ out)
{
    extern __shared__ char sm[];
    const int m0 = blockIdx.y * 128, n0 = blockIdx.x * 128;
    float acc[4][4][4];
    gemm_tf32_core(g_ao, Wo, sm, m0, n0, acc);

    const int tid = threadIdx.x, wid = tid >> 5, lane = tid & 31;
    const int wm = wid >> 2, wn = wid & 3;
    const int g = lane >> 2, tg = lane & 3;

    #pragma unroll
    for (int mt = 0; mt < 4; mt++) {
        #pragma unroll
        for (int nt = 0; nt < 4; nt++) {
            const int n = n0 + wn * 32 + nt * 8 + 2 * tg;
            float b0 = bo[n], b1 = bo[n + 1];
            #pragma unroll
            for (int half = 0; half < 2; half++) {
                const int r = m0 + wm * 64 + mt * 16 + g + half * 8;
                float2 v = make_float2(acc[mt][nt][2 * half] + b0,
                                       acc[mt][nt][2 * half + 1] + b1);
                *(float2*)&out[(size_t)r * ND + n] = v;
            }
        }
    }
}

// ---------------------------------------------------------------------------
// KV prep: split K/V fp32 -> bf16 hi/lo once.  K natural [bh][s][d],
// V transposed [bh][d][s] (smem transpose keeps all gmem I/O coalesced).
// grid (NS/64, NB*NH), 256 threads.
// ---------------------------------------------------------------------------
__global__ __launch_bounds__(256) void kv_prep()
{
    __shared__ float vt[64 * 65];
    const int bh = blockIdx.y;
    const int s0 = blockIdx.x * 64;
    const float* Kp = g_k + ((size_t)bh * NS + s0) * NDH;
    const float* Vp = g_v + ((size_t)bh * NS + s0) * NDH;

    // K: natural layout, fp32 -> hi/lo
    for (int i = threadIdx.x; i < 2048; i += 256) {
        int s = i >> 5, d2 = (i & 31) * 2;
        float2 x = *(const float2*)(Kp + (size_t)s * NDH + d2);
        uint32_t h, l;
        split2(x.x, x.y, h, l);
        size_t off = ((size_t)bh * NS + s0 + s) * NDH + d2;
        *(uint32_t*)&g_kh16[off] = h;
        *(uint32_t*)&g_kl16[off] = l;
    }

    // V: coalesced load -> transposed smem
    for (int i = threadIdx.x; i < 4096; i += 256) {
        int s = i >> 6, d = i & 63;
        vt[d * 65 + s] = Vp[(size_t)s * NDH + d];
    }
    __syncthreads();

    // transposed write: [bh][d][s], coalesced along s
    for (int i = threadIdx.x; i < 2048; i += 256) {
        int d = i >> 5, s2 = (i & 31) * 2;
        uint32_t h, l;
        split2(vt[d * 65 + s2], vt[d * 65 + s2 + 1], h, l);
        size_t off = ((size_t)bh * NDH + d) * NS + s0 + s2;
        *(uint32_t*)&g_vth16[off] = h;
        *(uint32_t*)&g_vtl16[off] = l;
    }
}

// ---------------------------------------------------------------------------
// Flash attention, bf16 3-term-split tensor cores, pre-split K/V, cp.async
// double buffering. 128 q-rows/CTA, 8 warps, warp owns 16 rows x 64 k-cols.
// smem rows: 64 halves + 8 pad = 144B (quad bank map 4g+tg, bijective).
// ---------------------------------------------------------------------------
#define KV_STRIDE 72                  // halves per row
#define ARR_B     (64 * 144)          // 9216 B per array tile
#define ATT_STAGE (4 * ARR_B)         // KH, KL, VH, VL = 36864 B
#define ATT_SMEM  (2 * ATT_STAGE)     // 73728 B dynamic

__global__ __launch_bounds__(256) void attn_kernel(const int* __restrict__ mask)
{
    extern __shared__ char att_sm[];
    __shared__ float mb[2][64];

    const int bh = blockIdx.y;
    const int b  = bh >> 4;
    const int h  = bh & 15;
    const int q0 = blockIdx.x * 128;
    const float* Qp = g_q + (size_t)bh * NS * NDH;
    const unsigned short* KH = g_kh16  + (size_t)bh * NS * NDH;   // [s][d]
    const unsigned short* KL = g_kl16  + (size_t)bh * NS * NDH;
    const unsigned short* VH = g_vth16 + (size_t)bh * NS * NDH;   // [d][s]
    const unsigned short* VL = g_vtl16 + (size_t)bh * NS * NDH;
    const int* mrow = mask + b * NS;

    const int tid = threadIdx.x, wid = tid >> 5, lane = tid & 31;
    const int g = lane >> 2, tg = lane & 3;
    const uint32_t sb = smem_u32(att_sm);

    auto issue = [&](int kb, int bf) {
        const int k0g = kb * 64;
        const uint32_t st = sb + bf * ATT_STAGE;
        #pragma unroll
        for (int i = 0; i < 2; i++) {          // K hi/lo: rows = key pos
            int f = tid + i * 256;
            int row = f >> 3, q = f & 7;
            size_t go = (size_t)(k0g + row) * NDH + q * 8;
            CP16(st + 0 * ARR_B + row * 144 + q * 16, KH + go);
            CP16(st + 1 * ARR_B + row * 144 + q * 16, KL + go);
        }
        #pragma unroll
        for (int i = 0; i < 2; i++) {          // V^T hi/lo: rows = d
            int f = tid + i * 256;
            int row = f >> 3, q = f & 7;
            size_t go = (size_t)row * NS + k0g + q * 8;
            CP16(st + 2 * ARR_B + row * 144 + q * 16, VH + go);
            CP16(st + 3 * ARR_B + row * 144 + q * 16, VL + go);
        }
        CP_COMMIT();
    };

    // Q fragments (pre-scaled by 1/8), bf16 hi/lo, resident in registers
    uint32_t qh[4][4], ql[4][4];
    {
        const float* q0p = Qp + (size_t)(q0 + wid * 16 + g) * NDH;
        const float* q1p = q0p + 8 * NDH;
        #pragma unroll
        for (int kk = 0; kk < 4; kk++) {
            float2 x;
            x = *(const float2*)(q0p + kk * 16 + 2 * tg);
            split2(0.125f * x.x, 0.125f * x.y, qh[kk][0], ql[kk][0]);
            x = *(const float2*)(q1p + kk * 16 + 2 * tg);
            split2(0.125f * x.x, 0.125f * x.y, qh[kk][1], ql[kk][1]);
            x = *(const float2*)(q0p + kk * 16 + 2 * tg + 8);
            split2(0.125f * x.x, 0.125f * x.y, qh[kk][2], ql[kk][2]);
            x = *(const float2*)(q1p + kk * 16 + 2 * tg + 8);
            split2(0.125f * x.x, 0.125f * x.y, qh[kk][3], ql[kk][3]);
        }
    }

    float o[8][4];
    #pragma unroll
    for (int nt = 0; nt < 8; nt++)
        #pragma unroll
        for (int i = 0; i < 4; i++) o[nt][i] = 0.f;
    float mrun[2] = {-1e30f, -1e30f}, lrun[2] = {0.f, 0.f};

    issue(0, 0);

    for (int kb = 0; kb < NS / 64; kb++) {
        const int bf = kb & 1;
        if (kb + 1 < NS / 64) { issue(kb + 1, bf ^ 1); CP_WAIT1(); }
        else                  { CP_WAIT0(); }
        if (tid < 64) mb[bf][tid] = mrow[kb * 64 + tid] ? 0.f : -1e30f;
        __syncthreads();

        const unsigned short* Ksm_hi = (const unsigned short*)(att_sm + bf * ATT_STAGE);
        const unsigned short* Ksm_lo = Ksm_hi + 64 * KV_STRIDE;
        const unsigned short* VT_hi  = Ksm_lo + 64 * KV_STRIDE;
        const unsigned short* VT_lo  = VT_hi  + 64 * KV_STRIDE;

        // ---- S = (Q/8) K^T via split bf16 mma ----
        float sc[8][4];
        #pragma unroll
        for (int nt = 0; nt < 8; nt++)
            #pragma unroll
            for (int i = 0; i < 4; i++) sc[nt][i] = 0.f;

        #pragma unroll
        for (int kk = 0; kk < 4; kk++) {
            #pragma unroll
            for (int nt = 0; nt < 8; nt++) {
                const int base = (nt * 8 + g) * KV_STRIDE + kk * 16 + 2 * tg;
                uint32_t bh2[2] = { *(const uint32_t*)&Ksm_hi[base],
                                    *(const uint32_t*)&Ksm_hi[base + 8] };
                uint32_t bl2[2] = { *(const uint32_t*)&Ksm_lo[base],
                                    *(const uint32_t*)&Ksm_lo[base + 8] };
                mma_bf16(sc[nt], qh[kk], bh2);
                mma_bf16(sc[nt], qh[kk], bl2);
                mma_bf16(sc[nt], ql[kk], bh2);
            }
        }

        // ---- mask bias ----
        #pragma unroll
        for (int nt = 0; nt < 8; nt++) {
            float2 mv = *(const float2*)&mb[bf][nt * 8 + 2 * tg];
            sc[nt][0] += mv.x; sc[nt][1] += mv.y;
            sc[nt][2] += mv.x; sc[nt][3] += mv.y;
        }

        // ---- online softmax (rows g and g+8; quad shfl reduction) ----
        #pragma unroll
        for (int r = 0; r < 2; r++) {
            float mx = -1e30f;
            #pragma unroll
            for (int nt = 0; nt < 8; nt++)
                mx = fmaxf(mx, fmaxf(sc[nt][2 * r], sc[nt][2 * r + 1]));
            mx = fmaxf(mx, __shfl_xor_sync(0xffffffffu, mx, 1));
            mx = fmaxf(mx, __shfl_xor_sync(0xffffffffu, mx, 2));
            const float mn = fmaxf(mrun[r], mx);
            float sum = 0.f;
            #pragma unroll
            for (int nt = 0; nt < 8; nt++) {
                float p0 = __expf(sc[nt][2 * r]     - mn);
                float p1 = __expf(sc[nt][2 * r + 1] - mn);
                sc[nt][2 * r] = p0; sc[nt][2 * r + 1] = p1;
                sum += p0 + p1;
            }
            sum += __shfl_xor_sync(0xffffffffu, sum, 1);
            sum += __shfl_xor_sync(0xffffffffu, sum, 2);
            const float al = __expf(mrun[r] - mn);
            lrun[r] = lrun[r] * al + sum;
            mrun[r] = mn;
            #pragma unroll
            for (int nt = 0; nt < 8; nt++) {
                o[nt][2 * r]     *= al;
                o[nt][2 * r + 1] *= al;
            }
        }

        // ---- O += P V via split bf16 mma (P frags built in registers) ----
        #pragma unroll
        for (int kk = 0; kk < 4; kk++) {
            uint32_t ph[4], pl[4];
            split2(sc[2 * kk][0],     sc[2 * kk][1],     ph[0], pl[0]);
            split2(sc[2 * kk][2],     sc[2 * kk][3],     ph[1], pl[1]);
            split2(sc[2 * kk + 1][0], sc[2 * kk + 1][1], ph[2], pl[2]);
            split2(sc[2 * kk + 1][2], sc[2 * kk + 1][3], ph[3], pl[3]);
            #pragma unroll
            for (int nt = 0; nt < 8; nt++) {
                const int base = (nt * 8 + g) * KV_STRIDE + kk * 16 + 2 * tg;
                uint32_t vh2[2] = { *(const uint32_t*)&VT_hi[base],
                                    *(const uint32_t*)&VT_hi[base + 8] };
                uint32_t vl2[2] = { *(const uint32_t*)&VT_lo[base],
                                    *(const uint32_t*)&VT_lo[base + 8] };
                mma_bf16(o[nt], ph, vh2);
                mma_bf16(o[nt], ph, vl2);
                mma_bf16(o[nt], pl, vh2);
            }
        }
        __syncthreads();   // done reading this stage before it is reloaded
    }

    // ---- normalize + write g_ao [B,S,D] ----
    const float inv0 = 1.0f / lrun[0];
    const float inv1 = 1.0f / lrun[1];
    const int r0 = q0 + wid * 16 + g;
    float* base0 = g_ao + ((size_t)b * NS + r0) * ND + h * NDH;
    float* base1 = base0 + 8 * (size_t)ND;
    #pragma unroll
    for (int nt = 0; nt < 8; nt++) {
        const int col = nt * 8 + 2 * tg;
        *(float2*)(base0 + col) = make_float2(o[nt][0] * inv0, o[nt][1] * inv0);
        *(float2*)(base1 + col) = make_float2(o[nt][2] * inv1, o[nt][3] * inv1);
    }
}

// ---------------------------------------------------------------------------
extern "C" void kernel_launch(void* const* d_in, const int* in_sizes, int n_in,
                              void* d_out, int out_size)
{
    const float* hs  = (const float*)d_in[0];
    const int*   msk = (const int*)  d_in[1];
    const float* Wq  = (const float*)d_in[2];
    const float* bq  = (const float*)d_in[3];
    const float* Wk  = (const float*)d_in[4];
    const float* bk  = (const float*)d_in[5];
    const float* Wv  = (const float*)d_in[6];
    const float* bv  = (const float*)d_in[7];
    const float* emo = (const float*)d_in[8];
    const float* Wo  = (const float*)d_in[9];
    const float* bo  = (const float*)d_in[10];
    float* out = (float*)d_out;

    cudaFuncSetAttribute(qkv_gemm, cudaFuncAttributeMaxDynamicSharedMemorySize, GEMM_SMEM);
    cudaFuncSetAttribute(out_gemm, cudaFuncAttributeMaxDynamicSharedMemorySize, GEMM_SMEM);
    cudaFuncSetAttribute(attn_kernel, cudaFuncAttributeMaxDynamicSharedMemorySize, ATT_SMEM);

    dim3 gqkv(ND / 128, MT / 128, 3);
    qkv_gemm<<<gqkv, 256, GEMM_SMEM>>>(hs, Wq, bq, Wk, bk, Wv, bv, emo);

    dim3 gprep(NS / 64, NB * NH);
    kv_prep<<<gprep, 256>>>();

    dim3 gatt(NS / 128, NB * NH);
    attn_kernel<<<gatt, 256, ATT_SMEM>>>(msk);

    dim3 gout(ND / 128, MT / 128);
    out_gemm<<<gout, 256, GEMM_SMEM>>>(Wo, bo, out);
}

// round 6
// speedup vs baseline: 3.4728x; 1.0929x over previous
#include <cuda_runtime.h>
#include <cuda_bf16.h>
#include <cuda_fp16.h>
#include <cstdint>
#include <math.h>

#define NB 2
#define NS 2048
#define ND 1024
#define NH 16
#define NDH 64
#define MT (NB*NS)          // 4096 rows in all GEMMs

// Scratch (allocation-free rule: __device__ globals)
__device__ float g_q [NB*NH*NS*NDH];   // [B,H,S,DH]
__device__ float g_k [NB*NH*NS*NDH];
__device__ float g_v [NB*NH*NS*NDH];
__device__ float g_ao[NB*NS*ND];       // attention output [B,S,D], tf32-rounded
// tf32-pre-rounded GEMM operands
__device__ float g_x [MT*ND];
__device__ float g_wq[ND*ND];
__device__ float g_wk[ND*ND];
__device__ float g_wv[ND*ND];
__device__ float g_wo[ND*ND];
// Pre-split K: bf16 hi/lo (natural [bh][s][d]); V: fp16 hi/lo (transposed [bh][d][s])
__device__ unsigned short g_kh16 [NB*NH*NS*NDH];
__device__ unsigned short g_kl16 [NB*NH*NS*NDH];
__device__ unsigned short g_vth16[NB*NH*NS*NDH];
__device__ unsigned short g_vtl16[NB*NH*NS*NDH];

// ===========================================================================
// Portable tensor-core helpers (valid on compute_103 target)
// ===========================================================================
__device__ __forceinline__ uint32_t smem_u32(const void* p) {
    uint32_t a;
    asm("{ .reg .u64 t; cvta.to.shared.u64 t, %1; cvt.u32.u64 %0, t; }"
        : "=r"(a) : "l"(p));
    return a;
}

__device__ __forceinline__ float f_tf32r(float x) {   // rna round to tf32 grid
    uint32_t r;
    asm("cvt.rna.tf32.f32 %0, %1;" : "=r"(r) : "f"(x));
    return __uint_as_float(r);
}

__device__ __forceinline__ void mma_tf32(float (&c)[4],
                                         const uint32_t (&a)[4],
                                         const uint32_t (&b)[2]) {
    asm volatile(
        "mma.sync.aligned.m16n8k8.row.col.f32.tf32.tf32.f32 "
        "{%0,%1,%2,%3}, {%4,%5,%6,%7}, {%8,%9}, {%0,%1,%2,%3};"
        : "+f"(c[0]), "+f"(c[1]), "+f"(c[2]), "+f"(c[3])
        : "r"(a[0]), "r"(a[1]), "r"(a[2]), "r"(a[3]), "r"(b[0]), "r"(b[1]));
}

__device__ __forceinline__ void mma_bf16(float (&c)[4],
                                         const uint32_t (&a)[4],
                                         const uint32_t (&b)[2]) {
    asm volatile(
        "mma.sync.aligned.m16n8k16.row.col.f32.bf16.bf16.f32 "
        "{%0,%1,%2,%3}, {%4,%5,%6,%7}, {%8,%9}, {%0,%1,%2,%3};"
        : "+f"(c[0]), "+f"(c[1]), "+f"(c[2]), "+f"(c[3])
        : "r"(a[0]), "r"(a[1]), "r"(a[2]), "r"(a[3]), "r"(b[0]), "r"(b[1]));
}

__device__ __forceinline__ void mma_fp16(float (&c)[4],
                                         const uint32_t (&a)[4],
                                         const uint32_t (&b)[2]) {
    asm volatile(
        "mma.sync.aligned.m16n8k16.row.col.f32.f16.f16.f32 "
        "{%0,%1,%2,%3}, {%4,%5,%6,%7}, {%8,%9}, {%0,%1,%2,%3};"
        : "+f"(c[0]), "+f"(c[1]), "+f"(c[2]), "+f"(c[3])
        : "r"(a[0]), "r"(a[1]), "r"(a[2]), "r"(a[3]), "r"(b[0]), "r"(b[1]));
}

// Split a pair of floats into packed bf16x2 hi + lo (x0 -> low half)
__device__ __forceinline__ void split2(float x0, float x1,
                                       uint32_t& hi, uint32_t& lo) {
    __nv_bfloat162 h = __floats2bfloat162_rn(x0, x1);
    float2 hf = __bfloat1622float2(h);
    __nv_bfloat162 l = __floats2bfloat162_rn(x0 - hf.x, x1 - hf.y);
    hi = *(uint32_t*)&h;
    lo = *(uint32_t*)&l;
}

// Split a pair of floats into packed fp16x2 hi + lo
__device__ __forceinline__ void split2h(float x0, float x1,
                                        uint32_t& hi, uint32_t& lo) {
    __half2 h = __floats2half2_rn(x0, x1);
    float2 hf = __half22float2(h);
    __half2 l = __floats2half2_rn(x0 - hf.x, x1 - hf.y);
    hi = *(uint32_t*)&h;
    lo = *(uint32_t*)&l;
}

__device__ __forceinline__ uint32_t pack_h2(float x0, float x1) {
    __half2 h = __floats2half2_rn(x0, x1);
    return *(uint32_t*)&h;
}

#define CP16(dst, src) \
    asm volatile("cp.async.cg.shared.global [%0], [%1], 16;" \
                 :: "r"(dst), "l"(src))
#define CP_COMMIT() asm volatile("cp.async.commit_group;" ::: "memory")
#define CP_WAIT1()  asm volatile("cp.async.wait_group 1;" ::: "memory")
#define CP_WAIT0()  asm volatile("cp.async.wait_group 0;" ::: "memory")

// smem geometry (floats): A[128][36] (bank 4g+tg bijective), B[32][136] (8tg+g)
#define A_STRIDE 36
#define B_STRIDE 136
#define A_BYTES  (128 * A_STRIDE * 4)   // 18432
#define B_BYTES  (32  * B_STRIDE * 4)   // 17408
#define STAGE_B  (A_BYTES + B_BYTES)    // 35840
#define GEMM_SMEM (2 * STAGE_B)         // 71680

// ---------------------------------------------------------------------------
// tf32 GEMM core: operands are PRE-ROUNDED to the tf32 grid, so fragments are
// loaded raw (no cvt in the hot loop; HW truncation is a no-op).
// ---------------------------------------------------------------------------
__device__ __forceinline__ void gemm_tf32_core(
    const float* __restrict__ A, const float* __restrict__ W,
    char* sm, int m0, int n0, float (&acc)[4][4][4])
{
    const int tid  = threadIdx.x;
    const int wid  = tid >> 5, lane = tid & 31;
    const int wm   = wid >> 2, wn = wid & 3;
    const int g    = lane >> 2, tg = lane & 3;

    #pragma unroll
    for (int mt = 0; mt < 4; mt++)
        #pragma unroll
        for (int nt = 0; nt < 4; nt++)
            #pragma unroll
            for (int i = 0; i < 4; i++) acc[mt][nt][i] = 0.f;

    const uint32_t sm_u = smem_u32(sm);

    auto issue_tile = [&](int kt, int bf) {
        const int k0 = kt * 32;
        const uint32_t as_u = sm_u + bf * STAGE_B;
        const uint32_t bs_u = as_u + A_BYTES;
        #pragma unroll
        for (int i = 0; i < 4; i++) {
            int f = tid + i * 256;
            int m = f >> 3, q = f & 7;
            CP16(as_u + m * (A_STRIDE * 4) + q * 16,
                 A + (size_t)(m0 + m) * ND + k0 + q * 4);
        }
        #pragma unroll
        for (int i = 0; i < 4; i++) {
            int f = tid + i * 256;
            int k = f >> 5, q = f & 31;
            CP16(bs_u + k * (B_STRIDE * 4) + q * 16,
                 W + (size_t)(k0 + k) * ND + n0 + q * 4);
        }
        CP_COMMIT();
    };

    issue_tile(0, 0);
    issue_tile(1, 1);

    for (int kt = 0; kt < 32; kt++) {
        const int bf = kt & 1;
        if (kt == 31) CP_WAIT0(); else CP_WAIT1();
        __syncthreads();

        const uint32_t* As = (const uint32_t*)(sm + bf * STAGE_B);
        const uint32_t* Bs = (const uint32_t*)(sm + bf * STAGE_B + A_BYTES);

        #pragma unroll
        for (int c = 0; c < 4; c++) {
            const int kk = c * 8;
            uint32_t a[4][4], b[4][2];
            #pragma unroll
            for (int mt = 0; mt < 4; mt++) {
                const uint32_t* ap = As + (size_t)(wm * 64 + mt * 16 + g) * A_STRIDE + kk + tg;
                a[mt][0] = ap[0];
                a[mt][2] = ap[4];
                a[mt][1] = ap[8 * A_STRIDE];
                a[mt][3] = ap[8 * A_STRIDE + 4];
            }
            #pragma unroll
            for (int nt = 0; nt < 4; nt++) {
                const uint32_t* bp = Bs + (size_t)(kk + tg) * B_STRIDE + wn * 32 + nt * 8 + g;
                b[nt][0] = bp[0];
                b[nt][1] = bp[4 * B_STRIDE];
            }
            #pragma unroll
            for (int mt = 0; mt < 4; mt++)
                #pragma unroll
                for (int nt = 0; nt < 4; nt++)
                    mma_tf32(acc[mt][nt], a[mt], b[nt]);
        }
        __syncthreads();
        if (kt + 2 < 32) issue_tile(kt + 2, bf);
    }
}

// ---------------------------------------------------------------------------
// Round prep: X and the 4 weight matrices -> tf32-exact fp32 copies.
// 8M floats total; float4 I/O.
// ---------------------------------------------------------------------------
__global__ __launch_bounds__(256) void round_prep(
    const float* __restrict__ X,  const float* __restrict__ Wq,
    const float* __restrict__ Wk, const float* __restrict__ Wv,
    const float* __restrict__ Wo)
{
    const int z = blockIdx.y;
    const float* src = (z == 0) ? X : (z == 1) ? g_wq : (z == 2) ? g_wk
                      : (z == 3) ? g_wv : g_wo;   // placeholder, fixed below
    // select true src/dst
    const float* s = (z == 0) ? X : (z == 1) ? Wq : (z == 2) ? Wk
                   : (z == 3) ? Wv : Wo;
    float* d = (z == 0) ? g_x : (z == 1) ? g_wq : (z == 2) ? g_wk
             : (z == 3) ? g_wv : g_wo;
    const int n4 = (z == 0) ? (MT * ND / 4) : (ND * ND / 4);
    (void)src;
    for (int i = blockIdx.x * 256 + threadIdx.x; i < n4; i += gridDim.x * 256) {
        float4 v = ((const float4*)s)[i];
        v.x = f_tf32r(v.x); v.y = f_tf32r(v.y);
        v.z = f_tf32r(v.z); v.w = f_tf32r(v.w);
        ((float4*)d)[i] = v;
    }
}

// ---------------------------------------------------------------------------
// QKV projection: z=0/1/2 -> Q/K/V written [B,H,S,DH]; Q adds emotion bias.
// ---------------------------------------------------------------------------
__global__ __launch_bounds__(256, 2) void qkv_gemm(
    const float* __restrict__ bq, const float* __restrict__ bk,
    const float* __restrict__ bv, const float* __restrict__ emo)
{
    extern __shared__ char sm[];
    const int z = blockIdx.z;
    const float* W    = (z == 0) ? g_wq : (z == 1) ? g_wk : g_wv;
    const float* bias = (z == 0) ? bq : (z == 1) ? bk : bv;
    float* dst        = (z == 0) ? g_q : (z == 1) ? g_k : g_v;

    const int m0 = blockIdx.y * 128, n0 = blockIdx.x * 128;
    float acc[4][4][4];
    gemm_tf32_core(g_x, W, sm, m0, n0, acc);

    const int tid = threadIdx.x, wid = tid >> 5, lane = tid & 31;
    const int wm = wid >> 2, wn = wid & 3;
    const int g = lane >> 2, tg = lane & 3;

    #pragma unroll
    for (int mt = 0; mt < 4; mt++) {
        #pragma unroll
        for (int nt = 0; nt < 4; nt++) {
            const int n = n0 + wn * 32 + nt * 8 + 2 * tg;
            const int h = n >> 6, dh = n & 63;
            float b0 = bias[n]     + (z == 0 ? emo[n]     : 0.f);
            float b1 = bias[n + 1] + (z == 0 ? emo[n + 1] : 0.f);
            #pragma unroll
            for (int half = 0; half < 2; half++) {
                const int r = m0 + wm * 64 + mt * 16 + g + half * 8;
                const int bb = r >> 11, s = r & (NS - 1);
                float2 v = make_float2(acc[mt][nt][2 * half] + b0,
                                       acc[mt][nt][2 * half + 1] + b1);
                *(float2*)&dst[(((size_t)bb * NH + h) * NS + s) * NDH + dh] = v;
            }
        }
    }
}

// ---------------------------------------------------------------------------
// Output projection: g_ao (tf32-rounded by attn) @ g_wo + bo -> out [B,S,D]
// ---------------------------------------------------------------------------
__global__ __launch_bounds__(256, 2) void out_gemm(
    const float* __restrict__ bo, float* __restrict__ out)
{
    extern __shared__ char sm[];
    const int m0 = blockIdx.y * 128, n0 = blockIdx.x * 128;
    float acc[4][4][4];
    gemm_tf32_core(g_ao, g_wo, sm, m0, n0, acc);

    const int tid = threadIdx.x, wid = tid >> 5, lane = tid & 31;
    const int wm = wid >> 2, wn = wid & 3;
    const int g = lane >> 2, tg = lane & 3;

    #pragma unroll
    for (int mt = 0; mt < 4; mt++) {
        #pragma unroll
        for (int nt = 0; nt < 4; nt++) {
            const int n = n0 + wn * 32 + nt * 8 + 2 * tg;
            float b0 = bo[n], b1 = bo[n + 1];
            #pragma unroll
            for (int half = 0; half < 2; half++) {
                const int r = m0 + wm * 64 + mt * 16 + g + half * 8;
                float2 v = make_float2(acc[mt][nt][2 * half] + b0,
                                       acc[mt][nt][2 * half + 1] + b1);
                *(float2*)&out[(size_t)r * ND + n] = v;
            }
        }
    }
}

// ---------------------------------------------------------------------------
// KV prep: K fp32 -> bf16 hi/lo (natural [bh][s][d]);
//          V fp32 -> fp16 hi/lo (transposed [bh][d][s]).
// ---------------------------------------------------------------------------
__global__ __launch_bounds__(256) void kv_prep()
{
    __shared__ float vt[64 * 65];
    const int bh = blockIdx.y;
    const int s0 = blockIdx.x * 64;
    const float* Kp = g_k + ((size_t)bh * NS + s0) * NDH;
    const float* Vp = g_v + ((size_t)bh * NS + s0) * NDH;

    for (int i = threadIdx.x; i < 2048; i += 256) {
        int s = i >> 5, d2 = (i & 31) * 2;
        float2 x = *(const float2*)(Kp + (size_t)s * NDH + d2);
        uint32_t h, l;
        split2(x.x, x.y, h, l);
        size_t off = ((size_t)bh * NS + s0 + s) * NDH + d2;
        *(uint32_t*)&g_kh16[off] = h;
        *(uint32_t*)&g_kl16[off] = l;
    }

    for (int i = threadIdx.x; i < 4096; i += 256) {
        int s = i >> 6, d = i & 63;
        vt[d * 65 + s] = Vp[(size_t)s * NDH + d];
    }
    __syncthreads();

    for (int i = threadIdx.x; i < 2048; i += 256) {
        int d = i >> 5, s2 = (i & 31) * 2;
        uint32_t h, l;
        split2h(vt[d * 65 + s2], vt[d * 65 + s2 + 1], h, l);
        size_t off = ((size_t)bh * NDH + d) * NS + s0 + s2;
        *(uint32_t*)&g_vth16[off] = h;
        *(uint32_t*)&g_vtl16[off] = l;
    }
}

// ---------------------------------------------------------------------------
// Flash attention: S = bf16 3-term split (error ~1e-5);
//                  O = P(single fp16) x V(fp16 hi/lo 2-term).
// 128 q-rows/CTA, 8 warps; cp.async double-buffered K/V tiles.
// ---------------------------------------------------------------------------
#define KV_STRIDE 72                  // 16-bit elems per row
#define ARR_B     (64 * 144)          // 9216 B per array tile
#define ATT_STAGE (4 * ARR_B)         // KH, KL, VH, VL
#define ATT_SMEM  (2 * ATT_STAGE)     // 73728 B dynamic

__global__ __launch_bounds__(256) void attn_kernel(const int* __restrict__ mask)
{
    extern __shared__ char att_sm[];
    __shared__ float mb[2][64];

    const int bh = blockIdx.y;
    const int b  = bh >> 4;
    const int h  = bh & 15;
    const int q0 = blockIdx.x * 128;
    const float* Qp = g_q + (size_t)bh * NS * NDH;
    const unsigned short* KH = g_kh16  + (size_t)bh * NS * NDH;   // [s][d] bf16
    const unsigned short* KL = g_kl16  + (size_t)bh * NS * NDH;
    const unsigned short* VH = g_vth16 + (size_t)bh * NS * NDH;   // [d][s] fp16
    const unsigned short* VL = g_vtl16 + (size_t)bh * NS * NDH;
    const int* mrow = mask + b * NS;

    const int tid = threadIdx.x, wid = tid >> 5, lane = tid & 31;
    const int g = lane >> 2, tg = lane & 3;
    const uint32_t sb = smem_u32(att_sm);

    auto issue = [&](int kb, int bf) {
        const int k0g = kb * 64;
        const uint32_t st = sb + bf * ATT_STAGE;
        #pragma unroll
        for (int i = 0; i < 2; i++) {          // K hi/lo: rows = key pos
            int f = tid + i * 256;
            int row = f >> 3, q = f & 7;
            size_t go = (size_t)(k0g + row) * NDH + q * 8;
            CP16(st + 0 * ARR_B + row * 144 + q * 16, KH + go);
            CP16(st + 1 * ARR_B + row * 144 + q * 16, KL + go);
        }
        #pragma unroll
        for (int i = 0; i < 2; i++) {          // V^T hi/lo: rows = d
            int f = tid + i * 256;
            int row = f >> 3, q = f & 7;
            size_t go = (size_t)row * NS + k0g + q * 8;
            CP16(st + 2 * ARR_B + row * 144 + q * 16, VH + go);
            CP16(st + 3 * ARR_B + row * 144 + q * 16, VL + go);
        }
        CP_COMMIT();
    };

    // Q fragments (pre-scaled by 1/8), bf16 hi/lo, resident in registers
    uint32_t qh[4][4], ql[4][4];
    {
        const float* q0p = Qp + (size_t)(q0 + wid * 16 + g) * NDH;
        const float* q1p = q0p + 8 * NDH;
        #pragma unroll
        for (int kk = 0; kk < 4; kk++) {
            float2 x;
            x = *(const float2*)(q0p + kk * 16 + 2 * tg);
            split2(0.125f * x.x, 0.125f * x.y, qh[kk][0], ql[kk][0]);
            x = *(const float2*)(q1p + kk * 16 + 2 * tg);
            split2(0.125f * x.x, 0.125f * x.y, qh[kk][1], ql[kk][1]);
            x = *(const float2*)(q0p + kk * 16 + 2 * tg + 8);
            split2(0.125f * x.x, 0.125f * x.y, qh[kk][2], ql[kk][2]);
            x = *(const float2*)(q1p + kk * 16 + 2 * tg + 8);
            split2(0.125f * x.x, 0.125f * x.y, qh[kk][3], ql[kk][3]);
        }
    }

    float o[8][4];
    #pragma unroll
    for (int nt = 0; nt < 8; nt++)
        #pragma unroll
        for (int i = 0; i < 4; i++) o[nt][i] = 0.f;
    float mrun[2] = {-1e30f, -1e30f}, lrun[2] = {0.f, 0.f};

    issue(0, 0);

    for (int kb = 0; kb < NS / 64; kb++) {
        const int bf = kb & 1;
        if (kb + 1 < NS / 64) { issue(kb + 1, bf ^ 1); CP_WAIT1(); }
        else                  { CP_WAIT0(); }
        if (tid < 64) mb[bf][tid] = mrow[kb * 64 + tid] ? 0.f : -1e30f;
        __syncthreads();

        const unsigned short* Ksm_hi = (const unsigned short*)(att_sm + bf * ATT_STAGE);
        const unsigned short* Ksm_lo = Ksm_hi + 64 * KV_STRIDE;
        const unsigned short* VT_hi  = Ksm_lo + 64 * KV_STRIDE;
        const unsigned short* VT_lo  = VT_hi  + 64 * KV_STRIDE;

        // ---- S = (Q/8) K^T via bf16 3-term split ----
        float sc[8][4];
        #pragma unroll
        for (int nt = 0; nt < 8; nt++)
            #pragma unroll
            for (int i = 0; i < 4; i++) sc[nt][i] = 0.f;

        #pragma unroll
        for (int kk = 0; kk < 4; kk++) {
            #pragma unroll
            for (int nt = 0; nt < 8; nt++) {
                const int base = (nt * 8 + g) * KV_STRIDE + kk * 16 + 2 * tg;
                uint32_t bh2[2] = { *(const uint32_t*)&Ksm_hi[base],
                                    *(const uint32_t*)&Ksm_hi[base + 8] };
                uint32_t bl2[2] = { *(const uint32_t*)&Ksm_lo[base],
                                    *(const uint32_t*)&Ksm_lo[base + 8] };
                mma_bf16(sc[nt], qh[kk], bh2);
                mma_bf16(sc[nt], qh[kk], bl2);
                mma_bf16(sc[nt], ql[kk], bh2);
            }
        }

        // ---- mask bias ----
        #pragma unroll
        for (int nt = 0; nt < 8; nt++) {
            float2 mv = *(const float2*)&mb[bf][nt * 8 + 2 * tg];
            sc[nt][0] += mv.x; sc[nt][1] += mv.y;
            sc[nt][2] += mv.x; sc[nt][3] += mv.y;
        }

        // ---- online softmax (rows g and g+8; quad shfl reduction) ----
        #pragma unroll
        for (int r = 0; r < 2; r++) {
            float mx = -1e30f;
            #pragma unroll
            for (int nt = 0; nt < 8; nt++)
                mx = fmaxf(mx, fmaxf(sc[nt][2 * r], sc[nt][2 * r + 1]));
            mx = fmaxf(mx, __shfl_xor_sync(0xffffffffu, mx, 1));
            mx = fmaxf(mx, __shfl_xor_sync(0xffffffffu, mx, 2));
            const float mn = fmaxf(mrun[r], mx);
            float sum = 0.f;
            #pragma unroll
            for (int nt = 0; nt < 8; nt++) {
                float p0 = __expf(sc[nt][2 * r]     - mn);
                float p1 = __expf(sc[nt][2 * r + 1] - mn);
                sc[nt][2 * r] = p0; sc[nt][2 * r + 1] = p1;
                sum += p0 + p1;
            }
            sum += __shfl_xor_sync(0xffffffffu, sum, 1);
            sum += __shfl_xor_sync(0xffffffffu, sum, 2);
            const float al = __expf(mrun[r] - mn);
            lrun[r] = lrun[r] * al + sum;
            mrun[r] = mn;
            #pragma unroll
            for (int nt = 0; nt < 8; nt++) {
                o[nt][2 * r]     *= al;
                o[nt][2 * r + 1] *= al;
            }
        }

        // ---- O += P V : P single fp16, V fp16 hi/lo (2 mma per frag) ----
        #pragma unroll
        for (int kk = 0; kk < 4; kk++) {
            uint32_t ph[4];
            ph[0] = pack_h2(sc[2 * kk][0],     sc[2 * kk][1]);
            ph[1] = pack_h2(sc[2 * kk][2],     sc[2 * kk][3]);
            ph[2] = pack_h2(sc[2 * kk + 1][0], sc[2 * kk + 1][1]);
            ph[3] = pack_h2(sc[2 * kk + 1][2], sc[2 * kk + 1][3]);
            #pragma unroll
            for (int nt = 0; nt < 8; nt++) {
                const int base = (nt * 8 + g) * KV_STRIDE + kk * 16 + 2 * tg;
                uint32_t vh2[2] = { *(const uint32_t*)&VT_hi[base],
                                    *(const uint32_t*)&VT_hi[base + 8] };
                uint32_t vl2[2] = { *(const uint32_t*)&VT_lo[base],
                                    *(const uint32_t*)&VT_lo[base + 8] };
                mma_fp16(o[nt], ph, vh2);
                mma_fp16(o[nt], ph, vl2);
            }
        }
        __syncthreads();   // done reading this stage before it is reloaded
    }

    // ---- normalize + tf32-round + write g_ao [B,S,D] ----
    const float inv0 = 1.0f / lrun[0];
    const float inv1 = 1.0f / lrun[1];
    const int r0 = q0 + wid * 16 + g;
    float* base0 = g_ao + ((size_t)b * NS + r0) * ND + h * NDH;
    float* base1 = base0 + 8 * (size_t)ND;
    #pragma unroll
    for (int nt = 0; nt < 8; nt++) {
        const int col = nt * 8 + 2 * tg;
        *(float2*)(base0 + col) = make_float2(f_tf32r(o[nt][0] * inv0),
                                              f_tf32r(o[nt][1] * inv0));
        *(float2*)(base1 + col) = make_float2(f_tf32r(o[nt][2] * inv1),
                                              f_tf32r(o[nt][3] * inv1));
    }
}

// ---------------------------------------------------------------------------
extern "C" void kernel_launch(void* const* d_in, const int* in_sizes, int n_in,
                              void* d_out, int out_size)
{
    const float* hs  = (const float*)d_in[0];
    const int*   msk = (const int*)  d_in[1];
    const float* Wq  = (const float*)d_in[2];
    const float* bq  = (const float*)d_in[3];
    const float* Wk  = (const float*)d_in[4];
    const float* bk  = (const float*)d_in[5];
    const float* Wv  = (const float*)d_in[6];
    const float* bv  = (const float*)d_in[7];
    const float* emo = (const float*)d_in[8];
    const float* Wo  = (const float*)d_in[9];
    const float* bo  = (const float*)d_in[10];
    float* out = (float*)d_out;

    cudaFuncSetAttribute(qkv_gemm, cudaFuncAttributeMaxDynamicSharedMemorySize, GEMM_SMEM);
    cudaFuncSetAttribute(out_gemm, cudaFuncAttributeMaxDynamicSharedMemorySize, GEMM_SMEM);
    cudaFuncSetAttribute(attn_kernel, cudaFuncAttributeMaxDynamicSharedMemorySize, ATT_SMEM);

    dim3 gr(128, 5);
    round_prep<<<gr, 256>>>(hs, Wq, Wk, Wv, Wo);

    dim3 gqkv(ND / 128, MT / 128, 3);
    qkv_gemm<<<gqkv, 256, GEMM_SMEM>>>(bq, bk, bv, emo);

    dim3 gprep(NS / 64, NB * NH);
    kv_prep<<<gprep, 256>>>();

    dim3 gatt(NS / 128, NB * NH);
    attn_kernel<<<gatt, 256, ATT_SMEM>>>(msk);

    dim3 gout(ND / 128, MT / 128);
    out_gemm<<<gout, 256, GEMM_SMEM>>>(bo, out);
}

// round 7
// speedup vs baseline: 3.9692x; 1.1429x over previous
#include <cuda_runtime.h>
#include <cuda_bf16.h>
#include <cuda_fp16.h>
#include <cstdint>
#include <math.h>

#define NB 2
#define NS 2048
#define ND 1024
#define NH 16
#define NDH 64
#define MT (NB*NS)          // 4096 rows in all GEMMs

// Scratch (allocation-free rule: __device__ globals)
__device__ float g_q [NB*NH*NS*NDH];   // [B,H,S,DH]
__device__ float g_k [NB*NH*NS*NDH];
__device__ float g_v [NB*NH*NS*NDH];
__device__ float g_ao[NB*NS*ND];       // attention output [B,S,D], tf32-rounded
// tf32-pre-rounded GEMM operands
__device__ float g_x [MT*ND];
__device__ float g_wq[ND*ND];
__device__ float g_wk[ND*ND];
__device__ float g_wv[ND*ND];
__device__ float g_wo[ND*ND];
// K: single fp16 (natural [bh][s][d]); V: fp16 hi/lo (transposed [bh][d][s])
__device__ unsigned short g_kf16 [NB*NH*NS*NDH];
__device__ unsigned short g_vth16[NB*NH*NS*NDH];
__device__ unsigned short g_vtl16[NB*NH*NS*NDH];

// ===========================================================================
// Portable tensor-core helpers (valid on compute_103 target)
// ===========================================================================
__device__ __forceinline__ uint32_t smem_u32(const void* p) {
    uint32_t a;
    asm("{ .reg .u64 t; cvta.to.shared.u64 t, %1; cvt.u32.u64 %0, t; }"
        : "=r"(a) : "l"(p));
    return a;
}

__device__ __forceinline__ float f_tf32r(float x) {   // rna round to tf32 grid
    uint32_t r;
    asm("cvt.rna.tf32.f32 %0, %1;" : "=r"(r) : "f"(x));
    return __uint_as_float(r);
}

__device__ __forceinline__ void mma_tf32(float (&c)[4],
                                         const uint32_t (&a)[4],
                                         const uint32_t (&b)[2]) {
    asm volatile(
        "mma.sync.aligned.m16n8k8.row.col.f32.tf32.tf32.f32 "
        "{%0,%1,%2,%3}, {%4,%5,%6,%7}, {%8,%9}, {%0,%1,%2,%3};"
        : "+f"(c[0]), "+f"(c[1]), "+f"(c[2]), "+f"(c[3])
        : "r"(a[0]), "r"(a[1]), "r"(a[2]), "r"(a[3]), "r"(b[0]), "r"(b[1]));
}

__device__ __forceinline__ void mma_fp16(float (&c)[4],
                                         const uint32_t (&a)[4],
                                         const uint32_t (&b)[2]) {
    asm volatile(
        "mma.sync.aligned.m16n8k16.row.col.f32.f16.f16.f32 "
        "{%0,%1,%2,%3}, {%4,%5,%6,%7}, {%8,%9}, {%0,%1,%2,%3};"
        : "+f"(c[0]), "+f"(c[1]), "+f"(c[2]), "+f"(c[3])
        : "r"(a[0]), "r"(a[1]), "r"(a[2]), "r"(a[3]), "r"(b[0]), "r"(b[1]));
}

// Split a pair of floats into packed fp16x2 hi + lo
__device__ __forceinline__ void split2h(float x0, float x1,
                                        uint32_t& hi, uint32_t& lo) {
    __half2 h = __floats2half2_rn(x0, x1);
    float2 hf = __half22float2(h);
    __half2 l = __floats2half2_rn(x0 - hf.x, x1 - hf.y);
    hi = *(uint32_t*)&h;
    lo = *(uint32_t*)&l;
}

__device__ __forceinline__ uint32_t pack_h2(float x0, float x1) {
    __half2 h = __floats2half2_rn(x0, x1);
    return *(uint32_t*)&h;
}

#define CP16(dst, src) \
    asm volatile("cp.async.cg.shared.global [%0], [%1], 16;" \
                 :: "r"(dst), "l"(src))
#define CP_COMMIT() asm volatile("cp.async.commit_group;" ::: "memory")
#define CP_WAIT1()  asm volatile("cp.async.wait_group 1;" ::: "memory")
#define CP_WAIT0()  asm volatile("cp.async.wait_group 0;" ::: "memory")

// smem geometry (floats): A[128][36] (bank 4g+tg bijective), B[32][136] (8tg+g)
#define A_STRIDE 36
#define B_STRIDE 136
#define A_BYTES  (128 * A_STRIDE * 4)   // 18432
#define B_BYTES  (32  * B_STRIDE * 4)   // 17408
#define STAGE_B  (A_BYTES + B_BYTES)    // 35840
#define GEMM_SMEM (2 * STAGE_B)         // 71680

// ---------------------------------------------------------------------------
// tf32 GEMM core: operands PRE-ROUNDED to tf32 grid (no cvt in hot loop).
// ---------------------------------------------------------------------------
__device__ __forceinline__ void gemm_tf32_core(
    const float* __restrict__ A, const float* __restrict__ W,
    char* sm, int m0, int n0, float (&acc)[4][4][4])
{
    const int tid  = threadIdx.x;
    const int wid  = tid >> 5, lane = tid & 31;
    const int wm   = wid >> 2, wn = wid & 3;
    const int g    = lane >> 2, tg = lane & 3;

    #pragma unroll
    for (int mt = 0; mt < 4; mt++)
        #pragma unroll
        for (int nt = 0; nt < 4; nt++)
            #pragma unroll
            for (int i = 0; i < 4; i++) acc[mt][nt][i] = 0.f;

    const uint32_t sm_u = smem_u32(sm);

    auto issue_tile = [&](int kt, int bf) {
        const int k0 = kt * 32;
        const uint32_t as_u = sm_u + bf * STAGE_B;
        const uint32_t bs_u = as_u + A_BYTES;
        #pragma unroll
        for (int i = 0; i < 4; i++) {
            int f = tid + i * 256;
            int m = f >> 3, q = f & 7;
            CP16(as_u + m * (A_STRIDE * 4) + q * 16,
                 A + (size_t)(m0 + m) * ND + k0 + q * 4);
        }
        #pragma unroll
        for (int i = 0; i < 4; i++) {
            int f = tid + i * 256;
            int k = f >> 5, q = f & 31;
            CP16(bs_u + k * (B_STRIDE * 4) + q * 16,
                 W + (size_t)(k0 + k) * ND + n0 + q * 4);
        }
        CP_COMMIT();
    };

    issue_tile(0, 0);
    issue_tile(1, 1);

    for (int kt = 0; kt < 32; kt++) {
        const int bf = kt & 1;
        if (kt == 31) CP_WAIT0(); else CP_WAIT1();
        __syncthreads();

        const uint32_t* As = (const uint32_t*)(sm + bf * STAGE_B);
        const uint32_t* Bs = (const uint32_t*)(sm + bf * STAGE_B + A_BYTES);

        #pragma unroll
        for (int c = 0; c < 4; c++) {
            const int kk = c * 8;
            uint32_t a[4][4], b[4][2];
            #pragma unroll
            for (int mt = 0; mt < 4; mt++) {
                const uint32_t* ap = As + (size_t)(wm * 64 + mt * 16 + g) * A_STRIDE + kk + tg;
                a[mt][0] = ap[0];
                a[mt][2] = ap[4];
                a[mt][1] = ap[8 * A_STRIDE];
                a[mt][3] = ap[8 * A_STRIDE + 4];
            }
            #pragma unroll
            for (int nt = 0; nt < 4; nt++) {
                const uint32_t* bp = Bs + (size_t)(kk + tg) * B_STRIDE + wn * 32 + nt * 8 + g;
                b[nt][0] = bp[0];
                b[nt][1] = bp[4 * B_STRIDE];
            }
            #pragma unroll
            for (int mt = 0; mt < 4; mt++)
                #pragma unroll
                for (int nt = 0; nt < 4; nt++)
                    mma_tf32(acc[mt][nt], a[mt], b[nt]);
        }
        __syncthreads();
        if (kt + 2 < 32) issue_tile(kt + 2, bf);
    }
}

// ---------------------------------------------------------------------------
// Round prep: X and the 4 weight matrices -> tf32-exact fp32 copies.
// ---------------------------------------------------------------------------
__global__ __launch_bounds__(256) void round_prep(
    const float* __restrict__ X,  const float* __restrict__ Wq,
    const float* __restrict__ Wk, const float* __restrict__ Wv,
    const float* __restrict__ Wo)
{
    const int z = blockIdx.y;
    const float* s = (z == 0) ? X : (z == 1) ? Wq : (z == 2) ? Wk
                   : (z == 3) ? Wv : Wo;
    float* d = (z == 0) ? g_x : (z == 1) ? g_wq : (z == 2) ? g_wk
             : (z == 3) ? g_wv : g_wo;
    const int n4 = (z == 0) ? (MT * ND / 4) : (ND * ND / 4);
    for (int i = blockIdx.x * 256 + threadIdx.x; i < n4; i += gridDim.x * 256) {
        float4 v = ((const float4*)s)[i];
        v.x = f_tf32r(v.x); v.y = f_tf32r(v.y);
        v.z = f_tf32r(v.z); v.w = f_tf32r(v.w);
        ((float4*)d)[i] = v;
    }
}

// ---------------------------------------------------------------------------
// QKV projection: z=0/1/2 -> Q/K/V written [B,H,S,DH]; Q adds emotion bias.
// ---------------------------------------------------------------------------
__global__ __launch_bounds__(256, 2) void qkv_gemm(
    const float* __restrict__ bq, const float* __restrict__ bk,
    const float* __restrict__ bv, const float* __restrict__ emo)
{
    extern __shared__ char sm[];
    const int z = blockIdx.z;
    const float* W    = (z == 0) ? g_wq : (z == 1) ? g_wk : g_wv;
    const float* bias = (z == 0) ? bq : (z == 1) ? bk : bv;
    float* dst        = (z == 0) ? g_q : (z == 1) ? g_k : g_v;

    const int m0 = blockIdx.y * 128, n0 = blockIdx.x * 128;
    float acc[4][4][4];
    gemm_tf32_core(g_x, W, sm, m0, n0, acc);

    const int tid = threadIdx.x, wid = tid >> 5, lane = tid & 31;
    const int wm = wid >> 2, wn = wid & 3;
    const int g = lane >> 2, tg = lane & 3;

    #pragma unroll
    for (int mt = 0; mt < 4; mt++) {
        #pragma unroll
        for (int nt = 0; nt < 4; nt++) {
            const int n = n0 + wn * 32 + nt * 8 + 2 * tg;
            const int h = n >> 6, dh = n & 63;
            float b0 = bias[n]     + (z == 0 ? emo[n]     : 0.f);
            float b1 = bias[n + 1] + (z == 0 ? emo[n + 1] : 0.f);
            #pragma unroll
            for (int half = 0; half < 2; half++) {
                const int r = m0 + wm * 64 + mt * 16 + g + half * 8;
                const int bb = r >> 11, s = r & (NS - 1);
                float2 v = make_float2(acc[mt][nt][2 * half] + b0,
                                       acc[mt][nt][2 * half + 1] + b1);
                *(float2*)&dst[(((size_t)bb * NH + h) * NS + s) * NDH + dh] = v;
            }
        }
    }
}

// ---------------------------------------------------------------------------
// Output projection: g_ao (tf32-rounded by attn) @ g_wo + bo -> out [B,S,D]
// ---------------------------------------------------------------------------
__global__ __launch_bounds__(256, 2) void out_gemm(
    const float* __restrict__ bo, float* __restrict__ out)
{
    extern __shared__ char sm[];
    const int m0 = blockIdx.y * 128, n0 = blockIdx.x * 128;
    float acc[4][4][4];
    gemm_tf32_core(g_ao, g_wo, sm, m0, n0, acc);

    const int tid = threadIdx.x, wid = tid >> 5, lane = tid & 31;
    const int wm = wid >> 2, wn = wid & 3;
    const int g = lane >> 2, tg = lane & 3;

    #pragma unroll
    for (int mt = 0; mt < 4; mt++) {
        #pragma unroll
        for (int nt = 0; nt < 4; nt++) {
            const int n = n0 + wn * 32 + nt * 8 + 2 * tg;
            float b0 = bo[n], b1 = bo[n + 1];
            #pragma unroll
            for (int half = 0; half < 2; half++) {
                const int r = m0 + wm * 64 + mt * 16 + g + half * 8;
                float2 v = make_float2(acc[mt][nt][2 * half] + b0,
                                       acc[mt][nt][2 * half + 1] + b1);
                *(float2*)&out[(size_t)r * ND + n] = v;
            }
        }
    }
}

// ---------------------------------------------------------------------------
// KV prep: K fp32 -> single fp16 (natural [bh][s][d]);
//          V fp32 -> fp16 hi/lo (transposed [bh][d][s]).
// ---------------------------------------------------------------------------
__global__ __launch_bounds__(256) void kv_prep()
{
    __shared__ float vt[64 * 65];
    const int bh = blockIdx.y;
    const int s0 = blockIdx.x * 64;
    const float* Kp = g_k + ((size_t)bh * NS + s0) * NDH;
    const float* Vp = g_v + ((size_t)bh * NS + s0) * NDH;

    for (int i = threadIdx.x; i < 2048; i += 256) {
        int s = i >> 5, d2 = (i & 31) * 2;
        float2 x = *(const float2*)(Kp + (size_t)s * NDH + d2);
        size_t off = ((size_t)bh * NS + s0 + s) * NDH + d2;
        *(uint32_t*)&g_kf16[off] = pack_h2(x.x, x.y);
    }

    for (int i = threadIdx.x; i < 4096; i += 256) {
        int s = i >> 6, d = i & 63;
        vt[d * 65 + s] = Vp[(size_t)s * NDH + d];
    }
    __syncthreads();

    for (int i = threadIdx.x; i < 2048; i += 256) {
        int d = i >> 5, s2 = (i & 31) * 2;
        uint32_t h, l;
        split2h(vt[d * 65 + s2], vt[d * 65 + s2 + 1], h, l);
        size_t off = ((size_t)bh * NDH + d) * NS + s0 + s2;
        *(uint32_t*)&g_vth16[off] = h;
        *(uint32_t*)&g_vtl16[off] = l;
    }
}

// ---------------------------------------------------------------------------
// Flash attention:
//   S = Q(fp16 hi/lo, 2 mma) x K(single fp16)        [error ~1.4e-4 abs]
//   O = P(single fp16) x V(fp16 hi/lo, 2 mma)
// 128 q-rows/CTA, 8 warps, 2 CTAs/SM; cp.async double-buffered tiles.
// ---------------------------------------------------------------------------
#define KV_STRIDE 72                  // 16-bit elems per row (144B, bank-free)
#define ARR_B     (64 * 144)          // 9216 B per array tile
#define ATT_STAGE (3 * ARR_B)         // KF, VH, VL = 27648 B
#define ATT_SMEM  (2 * ATT_STAGE)     // 55296 B dynamic

__global__ __launch_bounds__(256, 2) void attn_kernel(const int* __restrict__ mask)
{
    extern __shared__ char att_sm[];
    __shared__ float mb[2][64];

    const int bh = blockIdx.y;
    const int b  = bh >> 4;
    const int h  = bh & 15;
    const int q0 = blockIdx.x * 128;
    const float* Qp = g_q + (size_t)bh * NS * NDH;
    const unsigned short* KF = g_kf16  + (size_t)bh * NS * NDH;   // [s][d] fp16
    const unsigned short* VH = g_vth16 + (size_t)bh * NS * NDH;   // [d][s] fp16
    const unsigned short* VL = g_vtl16 + (size_t)bh * NS * NDH;
    const int* mrow = mask + b * NS;

    const int tid = threadIdx.x, wid = tid >> 5, lane = tid & 31;
    const int g = lane >> 2, tg = lane & 3;
    const uint32_t sb = smem_u32(att_sm);

    auto issue = [&](int kb, int bf) {
        const int k0g = kb * 64;
        const uint32_t st = sb + bf * ATT_STAGE;
        #pragma unroll
        for (int i = 0; i < 2; i++) {
            int f = tid + i * 256;
            int row = f >> 3, q = f & 7;
            CP16(st + 0 * ARR_B + row * 144 + q * 16,
                 KF + (size_t)(k0g + row) * NDH + q * 8);           // K: rows = kpos
            CP16(st + 1 * ARR_B + row * 144 + q * 16,
                 VH + (size_t)row * NS + k0g + q * 8);              // V^T: rows = d
            CP16(st + 2 * ARR_B + row * 144 + q * 16,
                 VL + (size_t)row * NS + k0g + q * 8);
        }
        CP_COMMIT();
    };

    // Q fragments (pre-scaled by 1/8), fp16 hi/lo, resident in registers
    uint32_t qh[4][4], ql[4][4];
    {
        const float* q0p = Qp + (size_t)(q0 + wid * 16 + g) * NDH;
        const float* q1p = q0p + 8 * NDH;
        #pragma unroll
        for (int kk = 0; kk < 4; kk++) {
            float2 x;
            x = *(const float2*)(q0p + kk * 16 + 2 * tg);
            split2h(0.125f * x.x, 0.125f * x.y, qh[kk][0], ql[kk][0]);
            x = *(const float2*)(q1p + kk * 16 + 2 * tg);
            split2h(0.125f * x.x, 0.125f * x.y, qh[kk][1], ql[kk][1]);
            x = *(const float2*)(q0p + kk * 16 + 2 * tg + 8);
            split2h(0.125f * x.x, 0.125f * x.y, qh[kk][2], ql[kk][2]);
            x = *(const float2*)(q1p + kk * 16 + 2 * tg + 8);
            split2h(0.125f * x.x, 0.125f * x.y, qh[kk][3], ql[kk][3]);
        }
    }

    float o[8][4];
    #pragma unroll
    for (int nt = 0; nt < 8; nt++)
        #pragma unroll
        for (int i = 0; i < 4; i++) o[nt][i] = 0.f;
    float mrun[2] = {-1e30f, -1e30f}, lrun[2] = {0.f, 0.f};

    issue(0, 0);

    for (int kb = 0; kb < NS / 64; kb++) {
        const int bf = kb & 1;
        if (kb + 1 < NS / 64) { issue(kb + 1, bf ^ 1); CP_WAIT1(); }
        else                  { CP_WAIT0(); }
        if (tid < 64) mb[bf][tid] = mrow[kb * 64 + tid] ? 0.f : -1e30f;
        __syncthreads();

        const unsigned short* Ksm = (const unsigned short*)(att_sm + bf * ATT_STAGE);
        const unsigned short* VT_hi = Ksm   + 64 * KV_STRIDE;
        const unsigned short* VT_lo = VT_hi + 64 * KV_STRIDE;

        // ---- S = (Q/8) K^T : 2 fp16 mma per fragment ----
        float sc[8][4];
        #pragma unroll
        for (int nt = 0; nt < 8; nt++)
            #pragma unroll
            for (int i = 0; i < 4; i++) sc[nt][i] = 0.f;

        #pragma unroll
        for (int kk = 0; kk < 4; kk++) {
            #pragma unroll
            for (int nt = 0; nt < 8; nt++) {
                const int base = (nt * 8 + g) * KV_STRIDE + kk * 16 + 2 * tg;
                uint32_t kb2[2] = { *(const uint32_t*)&Ksm[base],
                                    *(const uint32_t*)&Ksm[base + 8] };
                mma_fp16(sc[nt], qh[kk], kb2);
                mma_fp16(sc[nt], ql[kk], kb2);
            }
        }

        // ---- mask bias ----
        #pragma unroll
        for (int nt = 0; nt < 8; nt++) {
            float2 mv = *(const float2*)&mb[bf][nt * 8 + 2 * tg];
            sc[nt][0] += mv.x; sc[nt][1] += mv.y;
            sc[nt][2] += mv.x; sc[nt][3] += mv.y;
        }

        // ---- online softmax (rows g and g+8; quad shfl reduction) ----
        #pragma unroll
        for (int r = 0; r < 2; r++) {
            float mx = -1e30f;
            #pragma unroll
            for (int nt = 0; nt < 8; nt++)
                mx = fmaxf(mx, fmaxf(sc[nt][2 * r], sc[nt][2 * r + 1]));
            mx = fmaxf(mx, __shfl_xor_sync(0xffffffffu, mx, 1));
            mx = fmaxf(mx, __shfl_xor_sync(0xffffffffu, mx, 2));
            const float mn = fmaxf(mrun[r], mx);
            float sum = 0.f;
            #pragma unroll
            for (int nt = 0; nt < 8; nt++) {
                float p0 = __expf(sc[nt][2 * r]     - mn);
                float p1 = __expf(sc[nt][2 * r + 1] - mn);
                sc[nt][2 * r] = p0; sc[nt][2 * r + 1] = p1;
                sum += p0 + p1;
            }
            sum += __shfl_xor_sync(0xffffffffu, sum, 1);
            sum += __shfl_xor_sync(0xffffffffu, sum, 2);
            const float al = __expf(mrun[r] - mn);
            lrun[r] = lrun[r] * al + sum;
            mrun[r] = mn;
            #pragma unroll
            for (int nt = 0; nt < 8; nt++) {
                o[nt][2 * r]     *= al;
                o[nt][2 * r + 1] *= al;
            }
        }

        // ---- O += P V : P single fp16, V fp16 hi/lo (2 mma per frag) ----
        #pragma unroll
        for (int kk = 0; kk < 4; kk++) {
            uint32_t ph[4];
            ph[0] = pack_h2(sc[2 * kk][0],     sc[2 * kk][1]);
            ph[1] = pack_h2(sc[2 * kk][2],     sc[2 * kk][3]);
            ph[2] = pack_h2(sc[2 * kk + 1][0], sc[2 * kk + 1][1]);
            ph[3] = pack_h2(sc[2 * kk + 1][2], sc[2 * kk + 1][3]);
            #pragma unroll
            for (int nt = 0; nt < 8; nt++) {
                const int base = (nt * 8 + g) * KV_STRIDE + kk * 16 + 2 * tg;
                uint32_t vh2[2] = { *(const uint32_t*)&VT_hi[base],
                                    *(const uint32_t*)&VT_hi[base + 8] };
                uint32_t vl2[2] = { *(const uint32_t*)&VT_lo[base],
                                    *(const uint32_t*)&VT_lo[base + 8] };
                mma_fp16(o[nt], ph, vh2);
                mma_fp16(o[nt], ph, vl2);
            }
        }
        __syncthreads();   // done reading this stage before it is reloaded
    }

    // ---- normalize + tf32-round + write g_ao [B,S,D] ----
    const float inv0 = 1.0f / lrun[0];
    const float inv1 = 1.0f / lrun[1];
    const int r0 = q0 + wid * 16 + g;
    float* base0 = g_ao + ((size_t)b * NS + r0) * ND + h * NDH;
    float* base1 = base0 + 8 * (size_t)ND;
    #pragma unroll
    for (int nt = 0; nt < 8; nt++) {
        const int col = nt * 8 + 2 * tg;
        *(float2*)(base0 + col) = make_float2(f_tf32r(o[nt][0] * inv0),
                                              f_tf32r(o[nt][1] * inv0));
        *(float2*)(base1 + col) = make_float2(f_tf32r(o[nt][2] * inv1),
                                              f_tf32r(o[nt][3] * inv1));
    }
}

// ---------------------------------------------------------------------------
extern "C" void kernel_launch(void* const* d_in, const int* in_sizes, int n_in,
                              void* d_out, int out_size)
{
    const float* hs  = (const float*)d_in[0];
    const int*   msk = (const int*)  d_in[1];
    const float* Wq  = (const float*)d_in[2];
    const float* bq  = (const float*)d_in[3];
    const float* Wk  = (const float*)d_in[4];
    const float* bk  = (const float*)d_in[5];
    const float* Wv  = (const float*)d_in[6];
    const float* bv  = (const float*)d_in[7];
    const float* emo = (const float*)d_in[8];
    const float* Wo  = (const float*)d_in[9];
    const float* bo  = (const float*)d_in[10];
    float* out = (float*)d_out;

    cudaFuncSetAttribute(qkv_gemm, cudaFuncAttributeMaxDynamicSharedMemorySize, GEMM_SMEM);
    cudaFuncSetAttribute(out_gemm, cudaFuncAttributeMaxDynamicSharedMemorySize, GEMM_SMEM);
    cudaFuncSetAttribute(attn_kernel, cudaFuncAttributeMaxDynamicSharedMemorySize, ATT_SMEM);

    dim3 gr(128, 5);
    round_prep<<<gr, 256>>>(hs, Wq, Wk, Wv, Wo);

    dim3 gqkv(ND / 128, MT / 128, 3);
    qkv_gemm<<<gqkv, 256, GEMM_SMEM>>>(bq, bk, bv, emo);

    dim3 gprep(NS / 64, NB * NH);
    kv_prep<<<gprep, 256>>>();

    dim3 gatt(NS / 128, NB * NH);
    attn_kernel<<<gatt, 256, ATT_SMEM>>>(msk);

    dim3 gout(ND / 128, MT / 128);
    out_gemm<<<gout, 256, GEMM_SMEM>>>(bo, out);
}

// round 8
// speedup vs baseline: 4.5237x; 1.1397x over previous
#include <cuda_runtime.h>
#include <cuda_bf16.h>
#include <cuda_fp16.h>
#include <cstdint>
#include <math.h>

#define NB 2
#define NS 2048
#define ND 1024
#define NH 16
#define NDH 64
#define MT (NB*NS)          // 4096 rows in all GEMMs
#define LOG2E 1.4426950408889634f

// Scratch (allocation-free rule: __device__ globals)
__device__ float g_q [NB*NH*NS*NDH];   // [B,H,S,DH]
__device__ float g_k [NB*NH*NS*NDH];
__device__ float g_v [NB*NH*NS*NDH];
__device__ float g_ao[NB*NS*ND];       // attention output [B,S,D], tf32-rounded
// tf32-pre-rounded GEMM operands
__device__ float g_x [MT*ND];
__device__ float g_wq[ND*ND];
__device__ float g_wk[ND*ND];
__device__ float g_wv[ND*ND];
__device__ float g_wo[ND*ND];
// K: single fp16 (natural [bh][s][d]); V: single fp16 (transposed [bh][d][s])
__device__ unsigned short g_kf16 [NB*NH*NS*NDH];
__device__ unsigned short g_vt16 [NB*NH*NS*NDH];

// ===========================================================================
// Portable tensor-core helpers (valid on compute_103 target)
// ===========================================================================
__device__ __forceinline__ uint32_t smem_u32(const void* p) {
    uint32_t a;
    asm("{ .reg .u64 t; cvta.to.shared.u64 t, %1; cvt.u32.u64 %0, t; }"
        : "=r"(a) : "l"(p));
    return a;
}

__device__ __forceinline__ float f_tf32r(float x) {   // rna round to tf32 grid
    uint32_t r;
    asm("cvt.rna.tf32.f32 %0, %1;" : "=r"(r) : "f"(x));
    return __uint_as_float(r);
}

__device__ __forceinline__ void mma_tf32(float (&c)[4],
                                         const uint32_t (&a)[4],
                                         const uint32_t (&b)[2]) {
    asm volatile(
        "mma.sync.aligned.m16n8k8.row.col.f32.tf32.tf32.f32 "
        "{%0,%1,%2,%3}, {%4,%5,%6,%7}, {%8,%9}, {%0,%1,%2,%3};"
        : "+f"(c[0]), "+f"(c[1]), "+f"(c[2]), "+f"(c[3])
        : "r"(a[0]), "r"(a[1]), "r"(a[2]), "r"(a[3]), "r"(b[0]), "r"(b[1]));
}

__device__ __forceinline__ void mma_fp16(float (&c)[4],
                                         const uint32_t (&a)[4],
                                         const uint32_t (&b)[2]) {
    asm volatile(
        "mma.sync.aligned.m16n8k16.row.col.f32.f16.f16.f32 "
        "{%0,%1,%2,%3}, {%4,%5,%6,%7}, {%8,%9}, {%0,%1,%2,%3};"
        : "+f"(c[0]), "+f"(c[1]), "+f"(c[2]), "+f"(c[3])
        : "r"(a[0]), "r"(a[1]), "r"(a[2]), "r"(a[3]), "r"(b[0]), "r"(b[1]));
}

// Split a pair of floats into packed fp16x2 hi + lo
__device__ __forceinline__ void split2h(float x0, float x1,
                                        uint32_t& hi, uint32_t& lo) {
    __half2 h = __floats2half2_rn(x0, x1);
    float2 hf = __half22float2(h);
    __half2 l = __floats2half2_rn(x0 - hf.x, x1 - hf.y);
    hi = *(uint32_t*)&h;
    lo = *(uint32_t*)&l;
}

__device__ __forceinline__ uint32_t pack_h2(float x0, float x1) {
    __half2 h = __floats2half2_rn(x0, x1);
    return *(uint32_t*)&h;
}

#define CP16(dst, src) \
    asm volatile("cp.async.cg.shared.global [%0], [%1], 16;" \
                 :: "r"(dst), "l"(src))
#define CP_COMMIT() asm volatile("cp.async.commit_group;" ::: "memory")
#define CP_WAIT1()  asm volatile("cp.async.wait_group 1;" ::: "memory")
#define CP_WAIT0()  asm volatile("cp.async.wait_group 0;" ::: "memory")

// smem geometry (floats): A[128][36] (bank 4g+tg bijective), B[32][136] (8tg+g)
#define A_STRIDE 36
#define B_STRIDE 136
#define A_BYTES  (128 * A_STRIDE * 4)   // 18432
#define B_BYTES  (32  * B_STRIDE * 4)   // 17408
#define STAGE_B  (A_BYTES + B_BYTES)    // 35840
#define GEMM_SMEM (2 * STAGE_B)         // 71680

// ---------------------------------------------------------------------------
// tf32 GEMM core: operands PRE-ROUNDED to tf32 grid (no cvt in hot loop).
// ---------------------------------------------------------------------------
__device__ __forceinline__ void gemm_tf32_core(
    const float* __restrict__ A, const float* __restrict__ W,
    char* sm, int m0, int n0, float (&acc)[4][4][4])
{
    const int tid  = threadIdx.x;
    const int wid  = tid >> 5, lane = tid & 31;
    const int wm   = wid >> 2, wn = wid & 3;
    const int g    = lane >> 2, tg = lane & 3;

    #pragma unroll
    for (int mt = 0; mt < 4; mt++)
        #pragma unroll
        for (int nt = 0; nt < 4; nt++)
            #pragma unroll
            for (int i = 0; i < 4; i++) acc[mt][nt][i] = 0.f;

    const uint32_t sm_u = smem_u32(sm);

    auto issue_tile = [&](int kt, int bf) {
        const int k0 = kt * 32;
        const uint32_t as_u = sm_u + bf * STAGE_B;
        const uint32_t bs_u = as_u + A_BYTES;
        #pragma unroll
        for (int i = 0; i < 4; i++) {
            int f = tid + i * 256;
            int m = f >> 3, q = f & 7;
            CP16(as_u + m * (A_STRIDE * 4) + q * 16,
                 A + (size_t)(m0 + m) * ND + k0 + q * 4);
        }
        #pragma unroll
        for (int i = 0; i < 4; i++) {
            int f = tid + i * 256;
            int k = f >> 5, q = f & 31;
            CP16(bs_u + k * (B_STRIDE * 4) + q * 16,
                 W + (size_t)(k0 + k) * ND + n0 + q * 4);
        }
        CP_COMMIT();
    };

    issue_tile(0, 0);
    issue_tile(1, 1);

    for (int kt = 0; kt < 32; kt++) {
        const int bf = kt & 1;
        if (kt == 31) CP_WAIT0(); else CP_WAIT1();
        __syncthreads();

        const uint32_t* As = (const uint32_t*)(sm + bf * STAGE_B);
        const uint32_t* Bs = (const uint32_t*)(sm + bf * STAGE_B + A_BYTES);

        #pragma unroll
        for (int c = 0; c < 4; c++) {
            const int kk = c * 8;
            uint32_t a[4][4], b[4][2];
            #pragma unroll
            for (int mt = 0; mt < 4; mt++) {
                const uint32_t* ap = As + (size_t)(wm * 64 + mt * 16 + g) * A_STRIDE + kk + tg;
                a[mt][0] = ap[0];
                a[mt][2] = ap[4];
                a[mt][1] = ap[8 * A_STRIDE];
                a[mt][3] = ap[8 * A_STRIDE + 4];
            }
            #pragma unroll
            for (int nt = 0; nt < 4; nt++) {
                const uint32_t* bp = Bs + (size_t)(kk + tg) * B_STRIDE + wn * 32 + nt * 8 + g;
                b[nt][0] = bp[0];
                b[nt][1] = bp[4 * B_STRIDE];
            }
            #pragma unroll
            for (int mt = 0; mt < 4; mt++)
                #pragma unroll
                for (int nt = 0; nt < 4; nt++)
                    mma_tf32(acc[mt][nt], a[mt], b[nt]);
        }
        __syncthreads();
        if (kt + 2 < 32) issue_tile(kt + 2, bf);
    }
}

// ---------------------------------------------------------------------------
// Round prep: X and the 4 weight matrices -> tf32-exact fp32 copies.
// ---------------------------------------------------------------------------
__global__ __launch_bounds__(256) void round_prep(
    const float* __restrict__ X,  const float* __restrict__ Wq,
    const float* __restrict__ Wk, const float* __restrict__ Wv,
    const float* __restrict__ Wo)
{
    const int z = blockIdx.y;
    const float* s = (z == 0) ? X : (z == 1) ? Wq : (z == 2) ? Wk
                   : (z == 3) ? Wv : Wo;
    float* d = (z == 0) ? g_x : (z == 1) ? g_wq : (z == 2) ? g_wk
             : (z == 3) ? g_wv : g_wo;
    const int n4 = (z == 0) ? (MT * ND / 4) : (ND * ND / 4);
    for (int i = blockIdx.x * 256 + threadIdx.x; i < n4; i += gridDim.x * 256) {
        float4 v = ((const float4*)s)[i];
        v.x = f_tf32r(v.x); v.y = f_tf32r(v.y);
        v.z = f_tf32r(v.z); v.w = f_tf32r(v.w);
        ((float4*)d)[i] = v;
    }
}

// ---------------------------------------------------------------------------
// QKV projection: z=0/1/2 -> Q/K/V written [B,H,S,DH]; Q adds emotion bias.
// ---------------------------------------------------------------------------
__global__ __launch_bounds__(256, 2) void qkv_gemm(
    const float* __restrict__ bq, const float* __restrict__ bk,
    const float* __restrict__ bv, const float* __restrict__ emo)
{
    extern __shared__ char sm[];
    const int z = blockIdx.z;
    const float* W    = (z == 0) ? g_wq : (z == 1) ? g_wk : g_wv;
    const float* bias = (z == 0) ? bq : (z == 1) ? bk : bv;
    float* dst        = (z == 0) ? g_q : (z == 1) ? g_k : g_v;

    const int m0 = blockIdx.y * 128, n0 = blockIdx.x * 128;
    float acc[4][4][4];
    gemm_tf32_core(g_x, W, sm, m0, n0, acc);

    const int tid = threadIdx.x, wid = tid >> 5, lane = tid & 31;
    const int wm = wid >> 2, wn = wid & 3;
    const int g = lane >> 2, tg = lane & 3;

    #pragma unroll
    for (int mt = 0; mt < 4; mt++) {
        #pragma unroll
        for (int nt = 0; nt < 4; nt++) {
            const int n = n0 + wn * 32 + nt * 8 + 2 * tg;
            const int h = n >> 6, dh = n & 63;
            float b0 = bias[n]     + (z == 0 ? emo[n]     : 0.f);
            float b1 = bias[n + 1] + (z == 0 ? emo[n + 1] : 0.f);
            #pragma unroll
            for (int half = 0; half < 2; half++) {
                const int r = m0 + wm * 64 + mt * 16 + g + half * 8;
                const int bb = r >> 11, s = r & (NS - 1);
                float2 v = make_float2(acc[mt][nt][2 * half] + b0,
                                       acc[mt][nt][2 * half + 1] + b1);
                *(float2*)&dst[(((size_t)bb * NH + h) * NS + s) * NDH + dh] = v;
            }
        }
    }
}

// ---------------------------------------------------------------------------
// Output projection: g_ao (tf32-rounded by attn) @ g_wo + bo -> out [B,S,D]
// ---------------------------------------------------------------------------
__global__ __launch_bounds__(256, 2) void out_gemm(
    const float* __restrict__ bo, float* __restrict__ out)
{
    extern __shared__ char sm[];
    const int m0 = blockIdx.y * 128, n0 = blockIdx.x * 128;
    float acc[4][4][4];
    gemm_tf32_core(g_ao, g_wo, sm, m0, n0, acc);

    const int tid = threadIdx.x, wid = tid >> 5, lane = tid & 31;
    const int wm = wid >> 2, wn = wid & 3;
    const int g = lane >> 2, tg = lane & 3;

    #pragma unroll
    for (int mt = 0; mt < 4; mt++) {
        #pragma unroll
        for (int nt = 0; nt < 4; nt++) {
            const int n = n0 + wn * 32 + nt * 8 + 2 * tg;
            float b0 = bo[n], b1 = bo[n + 1];
            #pragma unroll
            for (int half = 0; half < 2; half++) {
                const int r = m0 + wm * 64 + mt * 16 + g + half * 8;
                float2 v = make_float2(acc[mt][nt][2 * half] + b0,
                                       acc[mt][nt][2 * half + 1] + b1);
                *(float2*)&out[(size_t)r * ND + n] = v;
            }
        }
    }
}

// ---------------------------------------------------------------------------
// KV prep: K fp32 -> fp16 (natural [bh][s][d]); V fp32 -> fp16 ([bh][d][s]).
// ---------------------------------------------------------------------------
__global__ __launch_bounds__(256) void kv_prep()
{
    __shared__ float vt[64 * 65];
    const int bh = blockIdx.y;
    const int s0 = blockIdx.x * 64;
    const float* Kp = g_k + ((size_t)bh * NS + s0) * NDH;
    const float* Vp = g_v + ((size_t)bh * NS + s0) * NDH;

    for (int i = threadIdx.x; i < 2048; i += 256) {
        int s = i >> 5, d2 = (i & 31) * 2;
        float2 x = *(const float2*)(Kp + (size_t)s * NDH + d2);
        size_t off = ((size_t)bh * NS + s0 + s) * NDH + d2;
        *(uint32_t*)&g_kf16[off] = pack_h2(x.x, x.y);
    }

    for (int i = threadIdx.x; i < 4096; i += 256) {
        int s = i >> 6, d = i & 63;
        vt[d * 65 + s] = Vp[(size_t)s * NDH + d];
    }
    __syncthreads();

    for (int i = threadIdx.x; i < 2048; i += 256) {
        int d = i >> 5, s2 = (i & 31) * 2;
        size_t off = ((size_t)bh * NDH + d) * NS + s0 + s2;
        *(uint32_t*)&g_vt16[off] = pack_h2(vt[d * 65 + s2], vt[d * 65 + s2 + 1]);
    }
}

// ---------------------------------------------------------------------------
// Flash attention:
//   S = Q(fp16 hi/lo, 2 mma) x K(single fp16); log2-domain scores
//   O = P(single fp16) x V(single fp16, 1 mma)
// 128 q-rows/CTA, 8 warps, 2 CTAs/SM; cp.async double-buffered tiles.
// ---------------------------------------------------------------------------
#define KV_STRIDE 72                  // 16-bit elems per row (144B, bank-free)
#define ARR_B     (64 * 144)          // 9216 B per array tile
#define ATT_STAGE (2 * ARR_B)         // KF, VT = 18432 B
#define ATT_SMEM  (2 * ATT_STAGE)     // 36864 B dynamic

__global__ __launch_bounds__(256, 2) void attn_kernel(const int* __restrict__ mask)
{
    extern __shared__ char att_sm[];
    __shared__ float mb[2][64];

    const int bh = blockIdx.y;
    const int b  = bh >> 4;
    const int h  = bh & 15;
    const int q0 = blockIdx.x * 128;
    const float* Qp = g_q + (size_t)bh * NS * NDH;
    const unsigned short* KF = g_kf16 + (size_t)bh * NS * NDH;   // [s][d] fp16
    const unsigned short* VT = g_vt16 + (size_t)bh * NS * NDH;   // [d][s] fp16
    const int* mrow = mask + b * NS;

    const int tid = threadIdx.x, wid = tid >> 5, lane = tid & 31;
    const int g = lane >> 2, tg = lane & 3;
    const uint32_t sb = smem_u32(att_sm);

    auto issue = [&](int kb, int bf) {
        const int k0g = kb * 64;
        const uint32_t st = sb + bf * ATT_STAGE;
        #pragma unroll
        for (int i = 0; i < 2; i++) {
            int f = tid + i * 256;
            int row = f >> 3, q = f & 7;
            CP16(st + 0 * ARR_B + row * 144 + q * 16,
                 KF + (size_t)(k0g + row) * NDH + q * 8);           // K: rows = kpos
            CP16(st + 1 * ARR_B + row * 144 + q * 16,
                 VT + (size_t)row * NS + k0g + q * 8);              // V^T: rows = d
        }
        CP_COMMIT();
    };

    // Q fragments (pre-scaled by log2e/8), fp16 hi/lo, resident in registers
    const float qs = 0.125f * LOG2E;
    uint32_t qh[4][4], ql[4][4];
    {
        const float* q0p = Qp + (size_t)(q0 + wid * 16 + g) * NDH;
        const float* q1p = q0p + 8 * NDH;
        #pragma unroll
        for (int kk = 0; kk < 4; kk++) {
            float2 x;
            x = *(const float2*)(q0p + kk * 16 + 2 * tg);
            split2h(qs * x.x, qs * x.y, qh[kk][0], ql[kk][0]);
            x = *(const float2*)(q1p + kk * 16 + 2 * tg);
            split2h(qs * x.x, qs * x.y, qh[kk][1], ql[kk][1]);
            x = *(const float2*)(q0p + kk * 16 + 2 * tg + 8);
            split2h(qs * x.x, qs * x.y, qh[kk][2], ql[kk][2]);
            x = *(const float2*)(q1p + kk * 16 + 2 * tg + 8);
            split2h(qs * x.x, qs * x.y, qh[kk][3], ql[kk][3]);
        }
    }

    float o[8][4];
    #pragma unroll
    for (int nt = 0; nt < 8; nt++)
        #pragma unroll
        for (int i = 0; i < 4; i++) o[nt][i] = 0.f;
    float mrun[2] = {-1e30f, -1e30f}, lrun[2] = {0.f, 0.f};

    issue(0, 0);

    for (int kb = 0; kb < NS / 64; kb++) {
        const int bf = kb & 1;
        if (kb + 1 < NS / 64) { issue(kb + 1, bf ^ 1); CP_WAIT1(); }
        else                  { CP_WAIT0(); }
        if (tid < 64) mb[bf][tid] = mrow[kb * 64 + tid] ? 0.f : -1e30f;
        __syncthreads();

        const unsigned short* Ksm = (const unsigned short*)(att_sm + bf * ATT_STAGE);
        const unsigned short* VTs = Ksm + 64 * KV_STRIDE;

        // ---- S (log2 domain) = Q K^T : 2 fp16 mma per fragment ----
        float sc[8][4];
        #pragma unroll
        for (int nt = 0; nt < 8; nt++)
            #pragma unroll
            for (int i = 0; i < 4; i++) sc[nt][i] = 0.f;

        #pragma unroll
        for (int kk = 0; kk < 4; kk++) {
            #pragma unroll
            for (int nt = 0; nt < 8; nt++) {
                const int base = (nt * 8 + g) * KV_STRIDE + kk * 16 + 2 * tg;
                uint32_t kb2[2] = { *(const uint32_t*)&Ksm[base],
                                    *(const uint32_t*)&Ksm[base + 8] };
                mma_fp16(sc[nt], qh[kk], kb2);
                mma_fp16(sc[nt], ql[kk], kb2);
            }
        }

        // ---- mask bias ----
        #pragma unroll
        for (int nt = 0; nt < 8; nt++) {
            float2 mv = *(const float2*)&mb[bf][nt * 8 + 2 * tg];
            sc[nt][0] += mv.x; sc[nt][1] += mv.y;
            sc[nt][2] += mv.x; sc[nt][3] += mv.y;
        }

        // ---- online softmax, log2 domain (rows g, g+8; quad shfl) ----
        #pragma unroll
        for (int r = 0; r < 2; r++) {
            float mx = -1e30f;
            #pragma unroll
            for (int nt = 0; nt < 8; nt++)
                mx = fmaxf(mx, fmaxf(sc[nt][2 * r], sc[nt][2 * r + 1]));
            mx = fmaxf(mx, __shfl_xor_sync(0xffffffffu, mx, 1));
            mx = fmaxf(mx, __shfl_xor_sync(0xffffffffu, mx, 2));
            const float mn = fmaxf(mrun[r], mx);
            float sum = 0.f;
            #pragma unroll
            for (int nt = 0; nt < 8; nt++) {
                float p0 = exp2f(sc[nt][2 * r]     - mn);
                float p1 = exp2f(sc[nt][2 * r + 1] - mn);
                sc[nt][2 * r] = p0; sc[nt][2 * r + 1] = p1;
                sum += p0 + p1;
            }
            sum += __shfl_xor_sync(0xffffffffu, sum, 1);
            sum += __shfl_xor_sync(0xffffffffu, sum, 2);
            const float al = exp2f(mrun[r] - mn);
            lrun[r] = lrun[r] * al + sum;
            mrun[r] = mn;
            #pragma unroll
            for (int nt = 0; nt < 8; nt++) {
                o[nt][2 * r]     *= al;
                o[nt][2 * r + 1] *= al;
            }
        }

        // ---- O += P V : single fp16 mma per fragment ----
        #pragma unroll
        for (int kk = 0; kk < 4; kk++) {
            uint32_t ph[4];
            ph[0] = pack_h2(sc[2 * kk][0],     sc[2 * kk][1]);
            ph[1] = pack_h2(sc[2 * kk][2],     sc[2 * kk][3]);
            ph[2] = pack_h2(sc[2 * kk + 1][0], sc[2 * kk + 1][1]);
            ph[3] = pack_h2(sc[2 * kk + 1][2], sc[2 * kk + 1][3]);
            #pragma unroll
            for (int nt = 0; nt < 8; nt++) {
                const int base = (nt * 8 + g) * KV_STRIDE + kk * 16 + 2 * tg;
                uint32_t v2[2] = { *(const uint32_t*)&VTs[base],
                                   *(const uint32_t*)&VTs[base + 8] };
                mma_fp16(o[nt], ph, v2);
            }
        }
        __syncthreads();   // done reading this stage before it is reloaded
    }

    // ---- normalize + tf32-round + write g_ao [B,S,D] ----
    const float inv0 = 1.0f / lrun[0];
    const float inv1 = 1.0f / lrun[1];
    const int r0 = q0 + wid * 16 + g;
    float* base0 = g_ao + ((size_t)b * NS + r0) * ND + h * NDH;
    float* base1 = base0 + 8 * (size_t)ND;
    #pragma unroll
    for (int nt = 0; nt < 8; nt++) {
        const int col = nt * 8 + 2 * tg;
        *(float2*)(base0 + col) = make_float2(f_tf32r(o[nt][0] * inv0),
                                              f_tf32r(o[nt][1] * inv0));
        *(float2*)(base1 + col) = make_float2(f_tf32r(o[nt][2] * inv1),
                                              f_tf32r(o[nt][3] * inv1));
    }
}

// ---------------------------------------------------------------------------
extern "C" void kernel_launch(void* const* d_in, const int* in_sizes, int n_in,
                              void* d_out, int out_size)
{
    const float* hs  = (const float*)d_in[0];
    const int*   msk = (const int*)  d_in[1];
    const float* Wq  = (const float*)d_in[2];
    const float* bq  = (const float*)d_in[3];
    const float* Wk  = (const float*)d_in[4];
    const float* bk  = (const float*)d_in[5];
    const float* Wv  = (const float*)d_in[6];
    const float* bv  = (const float*)d_in[7];
    const float* emo = (const float*)d_in[8];
    const float* Wo  = (const float*)d_in[9];
    const float* bo  = (const float*)d_in[10];
    float* out = (float*)d_out;

    cudaFuncSetAttribute(qkv_gemm, cudaFuncAttributeMaxDynamicSharedMemorySize, GEMM_SMEM);
    cudaFuncSetAttribute(out_gemm, cudaFuncAttributeMaxDynamicSharedMemorySize, GEMM_SMEM);
    cudaFuncSetAttribute(attn_kernel, cudaFuncAttributeMaxDynamicSharedMemorySize, ATT_SMEM);

    dim3 gr(128, 5);
    round_prep<<<gr, 256>>>(hs, Wq, Wk, Wv, Wo);

    dim3 gqkv(ND / 128, MT / 128, 3);
    qkv_gemm<<<gqkv, 256, GEMM_SMEM>>>(bq, bk, bv, emo);

    dim3 gprep(NS / 64, NB * NH);
    kv_prep<<<gprep, 256>>>();

    dim3 gatt(NS / 128, NB * NH);
    attn_kernel<<<gatt, 256, ATT_SMEM>>>(msk);

    dim3 gout(ND / 128, MT / 128);
    out_gemm<<<gout, 256, GEMM_SMEM>>>(bo, out);
}

// round 9
// speedup vs baseline: 5.2578x; 1.1623x over previous
#include <cuda_runtime.h>
#include <cuda_bf16.h>
#include <cuda_fp16.h>
#include <cstdint>
#include <math.h>

#define NB 2
#define NS 2048
#define ND 1024
#define NH 16
#define NDH 64
#define MT (NB*NS)          // 4096 rows in all GEMMs
#define LOG2E 1.4426950408889634f

// Scratch (allocation-free rule: __device__ globals)
__device__ float g_q [NB*NH*NS*NDH];   // [B,H,S,DH] fp32
__device__ float g_ao[NB*NS*ND];       // attention output [B,S,D], tf32-rounded
// tf32-pre-rounded GEMM operands
__device__ float g_x [MT*ND];
__device__ float g_wq[ND*ND];
__device__ float g_wk[ND*ND];
__device__ float g_wv[ND*ND];
__device__ float g_wo[ND*ND];
// K: fp16 (natural [bh][s][d]); V: fp16 (transposed [bh][d][s]) — written by qkv epilogue
__device__ unsigned short g_kf16 [NB*NH*NS*NDH];
__device__ unsigned short g_vt16 [NB*NH*NS*NDH];

// ===========================================================================
// Portable tensor-core helpers (valid on compute_103 target)
// ===========================================================================
__device__ __forceinline__ uint32_t smem_u32(const void* p) {
    uint32_t a;
    asm("{ .reg .u64 t; cvta.to.shared.u64 t, %1; cvt.u32.u64 %0, t; }"
        : "=r"(a) : "l"(p));
    return a;
}

__device__ __forceinline__ float f_tf32r(float x) {   // rna round to tf32 grid
    uint32_t r;
    asm("cvt.rna.tf32.f32 %0, %1;" : "=r"(r) : "f"(x));
    return __uint_as_float(r);
}

__device__ __forceinline__ float ex2f(float x) {      // bare MUFU.EX2, ftz
    float y;
    asm("ex2.approx.ftz.f32 %0, %1;" : "=f"(y) : "f"(x));
    return y;
}

__device__ __forceinline__ void mma_tf32(float (&c)[4],
                                         const uint32_t (&a)[4],
                                         const uint32_t (&b)[2]) {
    asm volatile(
        "mma.sync.aligned.m16n8k8.row.col.f32.tf32.tf32.f32 "
        "{%0,%1,%2,%3}, {%4,%5,%6,%7}, {%8,%9}, {%0,%1,%2,%3};"
        : "+f"(c[0]), "+f"(c[1]), "+f"(c[2]), "+f"(c[3])
        : "r"(a[0]), "r"(a[1]), "r"(a[2]), "r"(a[3]), "r"(b[0]), "r"(b[1]));
}

__device__ __forceinline__ void mma_fp16(float (&c)[4],
                                         const uint32_t (&a)[4],
                                         const uint32_t (&b)[2]) {
    asm volatile(
        "mma.sync.aligned.m16n8k16.row.col.f32.f16.f16.f32 "
        "{%0,%1,%2,%3}, {%4,%5,%6,%7}, {%8,%9}, {%0,%1,%2,%3};"
        : "+f"(c[0]), "+f"(c[1]), "+f"(c[2]), "+f"(c[3])
        : "r"(a[0]), "r"(a[1]), "r"(a[2]), "r"(a[3]), "r"(b[0]), "r"(b[1]));
}

__device__ __forceinline__ uint32_t pack_h2(float x0, float x1) {
    __half2 h = __floats2half2_rn(x0, x1);
    return *(uint32_t*)&h;
}

#define CP16(dst, src) \
    asm volatile("cp.async.cg.shared.global [%0], [%1], 16;" \
                 :: "r"(dst), "l"(src))
#define CP_COMMIT() asm volatile("cp.async.commit_group;" ::: "memory")
#define CP_WAIT1()  asm volatile("cp.async.wait_group 1;" ::: "memory")
#define CP_WAIT0()  asm volatile("cp.async.wait_group 0;" ::: "memory")

// smem geometry (floats): A[128][36] (bank 4g+tg bijective), B[32][136] (8tg+g)
#define A_STRIDE 36
#define B_STRIDE 136
#define A_BYTES  (128 * A_STRIDE * 4)   // 18432
#define B_BYTES  (32  * B_STRIDE * 4)   // 17408
#define STAGE_B  (A_BYTES + B_BYTES)    // 35840
#define GEMM_SMEM (2 * STAGE_B)         // 71680

// ---------------------------------------------------------------------------
// tf32 GEMM core: operands PRE-ROUNDED to tf32 grid (no cvt in hot loop).
// ---------------------------------------------------------------------------
__device__ __forceinline__ void gemm_tf32_core(
    const float* __restrict__ A, const float* __restrict__ W,
    char* sm, int m0, int n0, float (&acc)[4][4][4])
{
    const int tid  = threadIdx.x;
    const int wid  = tid >> 5, lane = tid & 31;
    const int wm   = wid >> 2, wn = wid & 3;
    const int g    = lane >> 2, tg = lane & 3;

    #pragma unroll
    for (int mt = 0; mt < 4; mt++)
        #pragma unroll
        for (int nt = 0; nt < 4; nt++)
            #pragma unroll
            for (int i = 0; i < 4; i++) acc[mt][nt][i] = 0.f;

    const uint32_t sm_u = smem_u32(sm);

    auto issue_tile = [&](int kt, int bf) {
        const int k0 = kt * 32;
        const uint32_t as_u = sm_u + bf * STAGE_B;
        const uint32_t bs_u = as_u + A_BYTES;
        #pragma unroll
        for (int i = 0; i < 4; i++) {
            int f = tid + i * 256;
            int m = f >> 3, q = f & 7;
            CP16(as_u + m * (A_STRIDE * 4) + q * 16,
                 A + (size_t)(m0 + m) * ND + k0 + q * 4);
        }
        #pragma unroll
        for (int i = 0; i < 4; i++) {
            int f = tid + i * 256;
            int k = f >> 5, q = f & 31;
            CP16(bs_u + k * (B_STRIDE * 4) + q * 16,
                 W + (size_t)(k0 + k) * ND + n0 + q * 4);
        }
        CP_COMMIT();
    };

    issue_tile(0, 0);
    issue_tile(1, 1);

    for (int kt = 0; kt < 32; kt++) {
        const int bf = kt & 1;
        if (kt == 31) CP_WAIT0(); else CP_WAIT1();
        __syncthreads();

        const uint32_t* As = (const uint32_t*)(sm + bf * STAGE_B);
        const uint32_t* Bs = (const uint32_t*)(sm + bf * STAGE_B + A_BYTES);

        #pragma unroll
        for (int c = 0; c < 4; c++) {
            const int kk = c * 8;
            uint32_t a[4][4], b[4][2];
            #pragma unroll
            for (int mt = 0; mt < 4; mt++) {
                const uint32_t* ap = As + (size_t)(wm * 64 + mt * 16 + g) * A_STRIDE + kk + tg;
                a[mt][0] = ap[0];
                a[mt][2] = ap[4];
                a[mt][1] = ap[8 * A_STRIDE];
                a[mt][3] = ap[8 * A_STRIDE + 4];
            }
            #pragma unroll
            for (int nt = 0; nt < 4; nt++) {
                const uint32_t* bp = Bs + (size_t)(kk + tg) * B_STRIDE + wn * 32 + nt * 8 + g;
                b[nt][0] = bp[0];
                b[nt][1] = bp[4 * B_STRIDE];
            }
            #pragma unroll
            for (int mt = 0; mt < 4; mt++)
                #pragma unroll
                for (int nt = 0; nt < 4; nt++)
                    mma_tf32(acc[mt][nt], a[mt], b[nt]);
        }
        __syncthreads();
        if (kt + 2 < 32) issue_tile(kt + 2, bf);
    }
}

// ---------------------------------------------------------------------------
// Round prep: X and the 4 weight matrices -> tf32-exact fp32 copies.
// ---------------------------------------------------------------------------
__global__ __launch_bounds__(256) void round_prep(
    const float* __restrict__ X,  const float* __restrict__ Wq,
    const float* __restrict__ Wk, const float* __restrict__ Wv,
    const float* __restrict__ Wo)
{
    const int z = blockIdx.y;
    const float* s = (z == 0) ? X : (z == 1) ? Wq : (z == 2) ? Wk
                   : (z == 3) ? Wv : Wo;
    float* d = (z == 0) ? g_x : (z == 1) ? g_wq : (z == 2) ? g_wk
             : (z == 3) ? g_wv : g_wo;
    const int n4 = (z == 0) ? (MT * ND / 4) : (ND * ND / 4);
    for (int i = blockIdx.x * 256 + threadIdx.x; i < n4; i += gridDim.x * 256) {
        float4 v = ((const float4*)s)[i];
        v.x = f_tf32r(v.x); v.y = f_tf32r(v.y);
        v.z = f_tf32r(v.z); v.w = f_tf32r(v.w);
        ((float4*)d)[i] = v;
    }
}

// ---------------------------------------------------------------------------
// QKV projection: z=0 -> Q fp32 [B,H,S,DH] (+bias+emotion);
//                 z=1 -> K fp16 [bh][s][d];
//                 z=2 -> V fp16 transposed [bh][d][s] (via smem transpose).
// ---------------------------------------------------------------------------
__global__ __launch_bounds__(256, 2) void qkv_gemm(
    const float* __restrict__ bq, const float* __restrict__ bk,
    const float* __restrict__ bv, const float* __restrict__ emo)
{
    extern __shared__ char sm[];
    const int z = blockIdx.z;
    const float* W    = (z == 0) ? g_wq : (z == 1) ? g_wk : g_wv;
    const float* bias = (z == 0) ? bq : (z == 1) ? bk : bv;

    const int m0 = blockIdx.y * 128, n0 = blockIdx.x * 128;
    float acc[4][4][4];
    gemm_tf32_core(g_x, W, sm, m0, n0, acc);

    const int tid = threadIdx.x, wid = tid >> 5, lane = tid & 31;
    const int wm = wid >> 2, wn = wid & 3;
    const int g = lane >> 2, tg = lane & 3;

    if (z == 0) {
        #pragma unroll
        for (int mt = 0; mt < 4; mt++) {
            #pragma unroll
            for (int nt = 0; nt < 4; nt++) {
                const int n = n0 + wn * 32 + nt * 8 + 2 * tg;
                const int h = n >> 6, dh = n & 63;
                float b0 = bias[n]     + emo[n];
                float b1 = bias[n + 1] + emo[n + 1];
                #pragma unroll
                for (int half = 0; half < 2; half++) {
                    const int r = m0 + wm * 64 + mt * 16 + g + half * 8;
                    const int bb = r >> 11, s = r & (NS - 1);
                    float2 v = make_float2(acc[mt][nt][2 * half] + b0,
                                           acc[mt][nt][2 * half + 1] + b1);
                    *(float2*)&g_q[(((size_t)bb * NH + h) * NS + s) * NDH + dh] = v;
                }
            }
        }
    } else if (z == 1) {
        // K fp16 natural: pairs contiguous along d
        #pragma unroll
        for (int mt = 0; mt < 4; mt++) {
            #pragma unroll
            for (int nt = 0; nt < 4; nt++) {
                const int n = n0 + wn * 32 + nt * 8 + 2 * tg;
                const int h = n >> 6, dh = n & 63;
                float b0 = bias[n], b1 = bias[n + 1];
                #pragma unroll
                for (int half = 0; half < 2; half++) {
                    const int r = m0 + wm * 64 + mt * 16 + g + half * 8;
                    const int bb = r >> 11, s = r & (NS - 1);
                    uint32_t v = pack_h2(acc[mt][nt][2 * half] + b0,
                                         acc[mt][nt][2 * half + 1] + b1);
                    *(uint32_t*)&g_kf16[(((size_t)bb * NH + h) * NS + s) * NDH + dh] = v;
                }
            }
        }
    } else {
        // V fp16 transposed: registers -> smem [n_local][s_local] -> coalesced out
        unsigned short* vt = (unsigned short*)sm;   // stride 136 ushorts
        #pragma unroll
        for (int mt = 0; mt < 4; mt++) {
            #pragma unroll
            for (int nt = 0; nt < 4; nt++) {
                const int nl = wn * 32 + nt * 8 + 2 * tg;
                float b0 = bias[n0 + nl], b1 = bias[n0 + nl + 1];
                #pragma unroll
                for (int half = 0; half < 2; half++) {
                    const int sl = wm * 64 + mt * 16 + g + half * 8;
                    vt[nl * 136 + sl]       = __half_as_ushort(
                        __float2half_rn(acc[mt][nt][2 * half] + b0));
                    vt[(nl + 1) * 136 + sl] = __half_as_ushort(
                        __float2half_rn(acc[mt][nt][2 * half + 1] + b1));
                }
            }
        }
        __syncthreads();
        const int bb = m0 >> 11, sbase = m0 & (NS - 1);
        for (int i = tid; i < 128 * 64; i += 256) {
            const int nl = i >> 6, s2 = (i & 63) * 2;
            const int n = n0 + nl, h = n >> 6, dh = n & 63;
            *(uint32_t*)&g_vt16[(((size_t)bb * NH + h) * NDH + dh) * NS + sbase + s2] =
                *(const uint32_t*)&vt[nl * 136 + s2];
        }
    }
}

// ---------------------------------------------------------------------------
// Output projection: g_ao (tf32-rounded by attn) @ g_wo + bo -> out [B,S,D]
// ---------------------------------------------------------------------------
__global__ __launch_bounds__(256, 2) void out_gemm(
    const float* __restrict__ bo, float* __restrict__ out)
{
    extern __shared__ char sm[];
    const int m0 = blockIdx.y * 128, n0 = blockIdx.x * 128;
    float acc[4][4][4];
    gemm_tf32_core(g_ao, g_wo, sm, m0, n0, acc);

    const int tid = threadIdx.x, wid = tid >> 5, lane = tid & 31;
    const int wm = wid >> 2, wn = wid & 3;
    const int g = lane >> 2, tg = lane & 3;

    #pragma unroll
    for (int mt = 0; mt < 4; mt++) {
        #pragma unroll
        for (int nt = 0; nt < 4; nt++) {
            const int n = n0 + wn * 32 + nt * 8 + 2 * tg;
            float b0 = bo[n], b1 = bo[n + 1];
            #pragma unroll
            for (int half = 0; half < 2; half++) {
                const int r = m0 + wm * 64 + mt * 16 + g + half * 8;
                float2 v = make_float2(acc[mt][nt][2 * half] + b0,
                                       acc[mt][nt][2 * half + 1] + b1);
                *(float2*)&out[(size_t)r * ND + n] = v;
            }
        }
    }
}

// ---------------------------------------------------------------------------
// Flash attention:
//   S = Q(single fp16) x K(single fp16); log2-domain scores (1 mma / frag)
//   O = P(single fp16) x V(single fp16)                     (1 mma / frag)
// 128 q-rows/CTA, 8 warps, 2 CTAs/SM; cp.async double-buffered tiles.
// ---------------------------------------------------------------------------
#define KV_STRIDE 72                  // 16-bit elems per row (144B, bank-free)
#define ARR_B     (64 * 144)          // 9216 B per array tile
#define ATT_STAGE (2 * ARR_B)         // KF, VT = 18432 B
#define ATT_SMEM  (2 * ATT_STAGE)     // 36864 B dynamic

__global__ __launch_bounds__(256, 2) void attn_kernel(const int* __restrict__ mask)
{
    extern __shared__ char att_sm[];
    __shared__ float mb[2][64];

    const int bh = blockIdx.y;
    const int b  = bh >> 4;
    const int h  = bh & 15;
    const int q0 = blockIdx.x * 128;
    const float* Qp = g_q + (size_t)bh * NS * NDH;
    const unsigned short* KF = g_kf16 + (size_t)bh * NS * NDH;   // [s][d] fp16
    const unsigned short* VT = g_vt16 + (size_t)bh * NS * NDH;   // [d][s] fp16
    const int* mrow = mask + b * NS;

    const int tid = threadIdx.x, wid = tid >> 5, lane = tid & 31;
    const int g = lane >> 2, tg = lane & 3;
    const uint32_t sb = smem_u32(att_sm);

    auto issue = [&](int kb, int bf) {
        const int k0g = kb * 64;
        const uint32_t st = sb + bf * ATT_STAGE;
        #pragma unroll
        for (int i = 0; i < 2; i++) {
            int f = tid + i * 256;
            int row = f >> 3, q = f & 7;
            CP16(st + 0 * ARR_B + row * 144 + q * 16,
                 KF + (size_t)(k0g + row) * NDH + q * 8);           // K: rows = kpos
            CP16(st + 1 * ARR_B + row * 144 + q * 16,
                 VT + (size_t)row * NS + k0g + q * 8);              // V^T: rows = d
        }
        CP_COMMIT();
    };

    // Q fragments (pre-scaled by log2e/8), single fp16, resident in registers
    const float qs = 0.125f * LOG2E;
    uint32_t qh[4][4];
    {
        const float* q0p = Qp + (size_t)(q0 + wid * 16 + g) * NDH;
        const float* q1p = q0p + 8 * NDH;
        #pragma unroll
        for (int kk = 0; kk < 4; kk++) {
            float2 x;
            x = *(const float2*)(q0p + kk * 16 + 2 * tg);
            qh[kk][0] = pack_h2(qs * x.x, qs * x.y);
            x = *(const float2*)(q1p + kk * 16 + 2 * tg);
            qh[kk][1] = pack_h2(qs * x.x, qs * x.y);
            x = *(const float2*)(q0p + kk * 16 + 2 * tg + 8);
            qh[kk][2] = pack_h2(qs * x.x, qs * x.y);
            x = *(const float2*)(q1p + kk * 16 + 2 * tg + 8);
            qh[kk][3] = pack_h2(qs * x.x, qs * x.y);
        }
    }

    float o[8][4];
    #pragma unroll
    for (int nt = 0; nt < 8; nt++)
        #pragma unroll
        for (int i = 0; i < 4; i++) o[nt][i] = 0.f;
    float mrun[2] = {-1e30f, -1e30f}, lrun[2] = {0.f, 0.f};

    issue(0, 0);

    for (int kb = 0; kb < NS / 64; kb++) {
        const int bf = kb & 1;
        if (kb + 1 < NS / 64) { issue(kb + 1, bf ^ 1); CP_WAIT1(); }
        else                  { CP_WAIT0(); }
        if (tid < 64) mb[bf][tid] = mrow[kb * 64 + tid] ? 0.f : -1e30f;
        __syncthreads();

        const unsigned short* Ksm = (const unsigned short*)(att_sm + bf * ATT_STAGE);
        const unsigned short* VTs = Ksm + 64 * KV_STRIDE;

        // ---- S (log2 domain) = Q K^T : 1 fp16 mma per fragment ----
        float sc[8][4];
        #pragma unroll
        for (int nt = 0; nt < 8; nt++)
            #pragma unroll
            for (int i = 0; i < 4; i++) sc[nt][i] = 0.f;

        #pragma unroll
        for (int kk = 0; kk < 4; kk++) {
            #pragma unroll
            for (int nt = 0; nt < 8; nt++) {
                const int base = (nt * 8 + g) * KV_STRIDE + kk * 16 + 2 * tg;
                uint32_t kb2[2] = { *(const uint32_t*)&Ksm[base],
                                    *(const uint32_t*)&Ksm[base + 8] };
                mma_fp16(sc[nt], qh[kk], kb2);
            }
        }

        // ---- mask bias ----
        #pragma unroll
        for (int nt = 0; nt < 8; nt++) {
            float2 mv = *(const float2*)&mb[bf][nt * 8 + 2 * tg];
            sc[nt][0] += mv.x; sc[nt][1] += mv.y;
            sc[nt][2] += mv.x; sc[nt][3] += mv.y;
        }

        // ---- online softmax, log2 domain (rows g, g+8; quad shfl) ----
        #pragma unroll
        for (int r = 0; r < 2; r++) {
            float mx = -1e30f;
            #pragma unroll
            for (int nt = 0; nt < 8; nt++)
                mx = fmaxf(mx, fmaxf(sc[nt][2 * r], sc[nt][2 * r + 1]));
            mx = fmaxf(mx, __shfl_xor_sync(0xffffffffu, mx, 1));
            mx = fmaxf(mx, __shfl_xor_sync(0xffffffffu, mx, 2));
            const float mn = fmaxf(mrun[r], mx);
            float sum = 0.f;
            #pragma unroll
            for (int nt = 0; nt < 8; nt++) {
                float p0 = ex2f(sc[nt][2 * r]     - mn);
                float p1 = ex2f(sc[nt][2 * r + 1] - mn);
                sc[nt][2 * r] = p0; sc[nt][2 * r + 1] = p1;
                sum += p0 + p1;
            }
            sum += __shfl_xor_sync(0xffffffffu, sum, 1);
            sum += __shfl_xor_sync(0xffffffffu, sum, 2);
            const float al = ex2f(mrun[r] - mn);
            lrun[r] = lrun[r] * al + sum;
            mrun[r] = mn;
            #pragma unroll
            for (int nt = 0; nt < 8; nt++) {
                o[nt][2 * r]     *= al;
                o[nt][2 * r + 1] *= al;
            }
        }

        // ---- O += P V : single fp16 mma per fragment ----
        #pragma unroll
        for (int kk = 0; kk < 4; kk++) {
            uint32_t ph[4];
            ph[0] = pack_h2(sc[2 * kk][0],     sc[2 * kk][1]);
            ph[1] = pack_h2(sc[2 * kk][2],     sc[2 * kk][3]);
            ph[2] = pack_h2(sc[2 * kk + 1][0], sc[2 * kk + 1][1]);
            ph[3] = pack_h2(sc[2 * kk + 1][2], sc[2 * kk + 1][3]);
            #pragma unroll
            for (int nt = 0; nt < 8; nt++) {
                const int base = (nt * 8 + g) * KV_STRIDE + kk * 16 + 2 * tg;
                uint32_t v2[2] = { *(const uint32_t*)&VTs[base],
                                   *(const uint32_t*)&VTs[base + 8] };
                mma_fp16(o[nt], ph, v2);
            }
        }
        __syncthreads();   // done reading this stage before it is reloaded
    }

    // ---- normalize + tf32-round + write g_ao [B,S,D] ----
    const float inv0 = 1.0f / lrun[0];
    const float inv1 = 1.0f / lrun[1];
    const int r0 = q0 + wid * 16 + g;
    float* base0 = g_ao + ((size_t)b * NS + r0) * ND + h * NDH;
    float* base1 = base0 + 8 * (size_t)ND;
    #pragma unroll
    for (int nt = 0; nt < 8; nt++) {
        const int col = nt * 8 + 2 * tg;
        *(float2*)(base0 + col) = make_float2(f_tf32r(o[nt][0] * inv0),
                                              f_tf32r(o[nt][1] * inv0));
        *(float2*)(base1 + col) = make_float2(f_tf32r(o[nt][2] * inv1),
                                              f_tf32r(o[nt][3] * inv1));
    }
}

// ---------------------------------------------------------------------------
extern "C" void kernel_launch(void* const* d_in, const int* in_sizes, int n_in,
                              void* d_out, int out_size)
{
    const float* hs  = (const float*)d_in[0];
    const int*   msk = (const int*)  d_in[1];
    const float* Wq  = (const float*)d_in[2];
    const float* bq  = (const float*)d_in[3];
    const float* Wk  = (const float*)d_in[4];
    const float* bk  = (const float*)d_in[5];
    const float* Wv  = (const float*)d_in[6];
    const float* bv  = (const float*)d_in[7];
    const float* emo = (const float*)d_in[8];
    const float* Wo  = (const float*)d_in[9];
    const float* bo  = (const float*)d_in[10];
    float* out = (float*)d_out;

    cudaFuncSetAttribute(qkv_gemm, cudaFuncAttributeMaxDynamicSharedMemorySize, GEMM_SMEM);
    cudaFuncSetAttribute(out_gemm, cudaFuncAttributeMaxDynamicSharedMemorySize, GEMM_SMEM);
    cudaFuncSetAttribute(attn_kernel, cudaFuncAttributeMaxDynamicSharedMemorySize, ATT_SMEM);

    dim3 gr(128, 5);
    round_prep<<<gr, 256>>>(hs, Wq, Wk, Wv, Wo);

    dim3 gqkv(ND / 128, MT / 128, 3);
    qkv_gemm<<<gqkv, 256, GEMM_SMEM>>>(bq, bk, bv, emo);

    dim3 gatt(NS / 128, NB * NH);
    attn_kernel<<<gatt, 256, ATT_SMEM>>>(msk);

    dim3 gout(ND / 128, MT / 128);
    out_gemm<<<gout, 256, GEMM_SMEM>>>(bo, out);
}

// round 10
// speedup vs baseline: 5.3130x; 1.0105x over previous
#include <cuda_runtime.h>
#include <cuda_bf16.h>
#include <cuda_fp16.h>
#include <cstdint>
#include <math.h>

#define NB 2
#define NS 2048
#define ND 1024
#define NH 16
#define NDH 64
#define MT (NB*NS)          // 4096 rows in all GEMMs
#define LOG2E 1.4426950408889634f

// Scratch (allocation-free rule: __device__ globals)
__device__ float g_q [NB*NH*NS*NDH];   // [B,H,S,DH] fp32
__device__ float g_ao[NB*NS*ND];       // attention output [B,S,D], tf32-rounded
// tf32-pre-rounded GEMM operands
__device__ float g_x [MT*ND];
__device__ float g_wq[ND*ND];
__device__ float g_wk[ND*ND];
__device__ float g_wv[ND*ND];
__device__ float g_wo[ND*ND];
// K: fp16 (natural [bh][s][d]); V: fp16 (transposed [bh][d][s]) — written by qkv epilogue
__device__ unsigned short g_kf16 [NB*NH*NS*NDH];
__device__ unsigned short g_vt16 [NB*NH*NS*NDH];

// ===========================================================================
// Portable tensor-core helpers (valid on compute_103 target)
// ===========================================================================
__device__ __forceinline__ uint32_t smem_u32(const void* p) {
    uint32_t a;
    asm("{ .reg .u64 t; cvta.to.shared.u64 t, %1; cvt.u32.u64 %0, t; }"
        : "=r"(a) : "l"(p));
    return a;
}

__device__ __forceinline__ float f_tf32r(float x) {   // rna round to tf32 grid
    uint32_t r;
    asm("cvt.rna.tf32.f32 %0, %1;" : "=r"(r) : "f"(x));
    return __uint_as_float(r);
}

__device__ __forceinline__ float ex2f(float x) {      // bare MUFU.EX2, ftz
    float y;
    asm("ex2.approx.ftz.f32 %0, %1;" : "=f"(y) : "f"(x));
    return y;
}

__device__ __forceinline__ void mma_tf32(float (&c)[4],
                                         const uint32_t (&a)[4],
                                         const uint32_t (&b)[2]) {
    asm volatile(
        "mma.sync.aligned.m16n8k8.row.col.f32.tf32.tf32.f32 "
        "{%0,%1,%2,%3}, {%4,%5,%6,%7}, {%8,%9}, {%0,%1,%2,%3};"
        : "+f"(c[0]), "+f"(c[1]), "+f"(c[2]), "+f"(c[3])
        : "r"(a[0]), "r"(a[1]), "r"(a[2]), "r"(a[3]), "r"(b[0]), "r"(b[1]));
}

__device__ __forceinline__ void mma_fp16(float (&c)[4],
                                         const uint32_t (&a)[4],
                                         const uint32_t (&b)[2]) {
    asm volatile(
        "mma.sync.aligned.m16n8k16.row.col.f32.f16.f16.f32 "
        "{%0,%1,%2,%3}, {%4,%5,%6,%7}, {%8,%9}, {%0,%1,%2,%3};"
        : "+f"(c[0]), "+f"(c[1]), "+f"(c[2]), "+f"(c[3])
        : "r"(a[0]), "r"(a[1]), "r"(a[2]), "r"(a[3]), "r"(b[0]), "r"(b[1]));
}

__device__ __forceinline__ uint32_t pack_h2(float x0, float x1) {
    __half2 h = __floats2half2_rn(x0, x1);
    return *(uint32_t*)&h;
}

#define CP16(dst, src) \
    asm volatile("cp.async.cg.shared.global [%0], [%1], 16;" \
                 :: "r"(dst), "l"(src))
#define CP_COMMIT() asm volatile("cp.async.commit_group;" ::: "memory")
#define CP_WAIT1()  asm volatile("cp.async.wait_group 1;" ::: "memory")
#define CP_WAIT0()  asm volatile("cp.async.wait_group 0;" ::: "memory")

// smem geometry (floats): A[128][36] (bank 4g+tg bijective), B[32][136] (8tg+g)
#define A_STRIDE 36
#define B_STRIDE 136
#define A_BYTES  (128 * A_STRIDE * 4)   // 18432
#define B_BYTES  (32  * B_STRIDE * 4)   // 17408
#define STAGE_B  (A_BYTES + B_BYTES)    // 35840
#define GEMM_SMEM (3 * STAGE_B)         // 107520 (3-stage)

// ---------------------------------------------------------------------------
// tf32 GEMM core: operands PRE-ROUNDED to tf32 grid (no cvt in hot loop).
// 3-stage cp.async pipeline, ONE __syncthreads per k-tile:
//   top-of-iter barrier proves buffer (kt-1)%3 fully drained -> safe target
//   for issue(kt+2).
// ---------------------------------------------------------------------------
__device__ __forceinline__ void gemm_tf32_core(
    const float* __restrict__ A, const float* __restrict__ W,
    char* sm, int m0, int n0, float (&acc)[4][4][4])
{
    const int tid  = threadIdx.x;
    const int wid  = tid >> 5, lane = tid & 31;
    const int wm   = wid >> 2, wn = wid & 3;
    const int g    = lane >> 2, tg = lane & 3;

    #pragma unroll
    for (int mt = 0; mt < 4; mt++)
        #pragma unroll
        for (int nt = 0; nt < 4; nt++)
            #pragma unroll
            for (int i = 0; i < 4; i++) acc[mt][nt][i] = 0.f;

    const uint32_t sm_u = smem_u32(sm);

    auto issue_tile = [&](int kt, int bf) {
        const int k0 = kt * 32;
        const uint32_t as_u = sm_u + bf * STAGE_B;
        const uint32_t bs_u = as_u + A_BYTES;
        #pragma unroll
        for (int i = 0; i < 4; i++) {
            int f = tid + i * 256;
            int m = f >> 3, q = f & 7;
            CP16(as_u + m * (A_STRIDE * 4) + q * 16,
                 A + (size_t)(m0 + m) * ND + k0 + q * 4);
        }
        #pragma unroll
        for (int i = 0; i < 4; i++) {
            int f = tid + i * 256;
            int k = f >> 5, q = f & 31;
            CP16(bs_u + k * (B_STRIDE * 4) + q * 16,
                 W + (size_t)(k0 + k) * ND + n0 + q * 4);
        }
        CP_COMMIT();
    };

    issue_tile(0, 0);
    issue_tile(1, 1);

    for (int kt = 0; kt < 32; kt++) {
        const int bf = kt % 3;
        if (kt == 31) CP_WAIT0(); else CP_WAIT1();
        __syncthreads();
        if (kt + 2 < 32) issue_tile(kt + 2, (kt + 2) % 3);

        const uint32_t* As = (const uint32_t*)(sm + bf * STAGE_B);
        const uint32_t* Bs = (const uint32_t*)(sm + bf * STAGE_B + A_BYTES);

        #pragma unroll
        for (int c = 0; c < 4; c++) {
            const int kk = c * 8;
            uint32_t a[4][4], b[4][2];
            #pragma unroll
            for (int mt = 0; mt < 4; mt++) {
                const uint32_t* ap = As + (size_t)(wm * 64 + mt * 16 + g) * A_STRIDE + kk + tg;
                a[mt][0] = ap[0];
                a[mt][2] = ap[4];
                a[mt][1] = ap[8 * A_STRIDE];
                a[mt][3] = ap[8 * A_STRIDE + 4];
            }
            #pragma unroll
            for (int nt = 0; nt < 4; nt++) {
                const uint32_t* bp = Bs + (size_t)(kk + tg) * B_STRIDE + wn * 32 + nt * 8 + g;
                b[nt][0] = bp[0];
                b[nt][1] = bp[4 * B_STRIDE];
            }
            #pragma unroll
            for (int mt = 0; mt < 4; mt++)
                #pragma unroll
                for (int nt = 0; nt < 4; nt++)
                    mma_tf32(acc[mt][nt], a[mt], b[nt]);
        }
        // no trailing barrier: next iteration's top barrier covers reuse
    }
    __syncthreads();   // protect smem reuse by epilogue (V transpose path)
}

// ---------------------------------------------------------------------------
// Round prep: X and the 4 weight matrices -> tf32-exact fp32 copies.
// ---------------------------------------------------------------------------
__global__ __launch_bounds__(256) void round_prep(
    const float* __restrict__ X,  const float* __restrict__ Wq,
    const float* __restrict__ Wk, const float* __restrict__ Wv,
    const float* __restrict__ Wo)
{
    const int z = blockIdx.y;
    const float* s = (z == 0) ? X : (z == 1) ? Wq : (z == 2) ? Wk
                   : (z == 3) ? Wv : Wo;
    float* d = (z == 0) ? g_x : (z == 1) ? g_wq : (z == 2) ? g_wk
             : (z == 3) ? g_wv : g_wo;
    const int n4 = (z == 0) ? (MT * ND / 4) : (ND * ND / 4);
    for (int i = blockIdx.x * 256 + threadIdx.x; i < n4; i += gridDim.x * 256) {
        float4 v = ((const float4*)s)[i];
        v.x = f_tf32r(v.x); v.y = f_tf32r(v.y);
        v.z = f_tf32r(v.z); v.w = f_tf32r(v.w);
        ((float4*)d)[i] = v;
    }
}

// ---------------------------------------------------------------------------
// QKV projection: z=0 -> Q fp32 [B,H,S,DH] (+bias+emotion);
//                 z=1 -> K fp16 [bh][s][d];
//                 z=2 -> V fp16 transposed [bh][d][s] (via smem transpose).
// ---------------------------------------------------------------------------
__global__ __launch_bounds__(256, 2) void qkv_gemm(
    const float* __restrict__ bq, const float* __restrict__ bk,
    const float* __restrict__ bv, const float* __restrict__ emo)
{
    extern __shared__ char sm[];
    const int z = blockIdx.z;
    const float* W    = (z == 0) ? g_wq : (z == 1) ? g_wk : g_wv;
    const float* bias = (z == 0) ? bq : (z == 1) ? bk : bv;

    const int m0 = blockIdx.y * 128, n0 = blockIdx.x * 128;
    float acc[4][4][4];
    gemm_tf32_core(g_x, W, sm, m0, n0, acc);

    const int tid = threadIdx.x, wid = tid >> 5, lane = tid & 31;
    const int wm = wid >> 2, wn = wid & 3;
    const int g = lane >> 2, tg = lane & 3;

    if (z == 0) {
        #pragma unroll
        for (int mt = 0; mt < 4; mt++) {
            #pragma unroll
            for (int nt = 0; nt < 4; nt++) {
                const int n = n0 + wn * 32 + nt * 8 + 2 * tg;
                const int h = n >> 6, dh = n & 63;
                float b0 = bias[n]     + emo[n];
                float b1 = bias[n + 1] + emo[n + 1];
                #pragma unroll
                for (int half = 0; half < 2; half++) {
                    const int r = m0 + wm * 64 + mt * 16 + g + half * 8;
                    const int bb = r >> 11, s = r & (NS - 1);
                    float2 v = make_float2(acc[mt][nt][2 * half] + b0,
                                           acc[mt][nt][2 * half + 1] + b1);
                    *(float2*)&g_q[(((size_t)bb * NH + h) * NS + s) * NDH + dh] = v;
                }
            }
        }
    } else if (z == 1) {
        // K fp16 natural: pairs contiguous along d
        #pragma unroll
        for (int mt = 0; mt < 4; mt++) {
            #pragma unroll
            for (int nt = 0; nt < 4; nt++) {
                const int n = n0 + wn * 32 + nt * 8 + 2 * tg;
                const int h = n >> 6, dh = n & 63;
                float b0 = bias[n], b1 = bias[n + 1];
                #pragma unroll
                for (int half = 0; half < 2; half++) {
                    const int r = m0 + wm * 64 + mt * 16 + g + half * 8;
                    const int bb = r >> 11, s = r & (NS - 1);
                    uint32_t v = pack_h2(acc[mt][nt][2 * half] + b0,
                                         acc[mt][nt][2 * half + 1] + b1);
                    *(uint32_t*)&g_kf16[(((size_t)bb * NH + h) * NS + s) * NDH + dh] = v;
                }
            }
        }
    } else {
        // V fp16 transposed: registers -> smem [n_local][s_local] -> coalesced out
        unsigned short* vt = (unsigned short*)sm;   // stride 136 ushorts
        #pragma unroll
        for (int mt = 0; mt < 4; mt++) {
            #pragma unroll
            for (int nt = 0; nt < 4; nt++) {
                const int nl = wn * 32 + nt * 8 + 2 * tg;
                float b0 = bias[n0 + nl], b1 = bias[n0 + nl + 1];
                #pragma unroll
                for (int half = 0; half < 2; half++) {
                    const int sl = wm * 64 + mt * 16 + g + half * 8;
                    vt[nl * 136 + sl]       = __half_as_ushort(
                        __float2half_rn(acc[mt][nt][2 * half] + b0));
                    vt[(nl + 1) * 136 + sl] = __half_as_ushort(
                        __float2half_rn(acc[mt][nt][2 * half + 1] + b1));
                }
            }
        }
        __syncthreads();
        const int bb = m0 >> 11, sbase = m0 & (NS - 1);
        for (int i = tid; i < 128 * 64; i += 256) {
            const int nl = i >> 6, s2 = (i & 63) * 2;
            const int n = n0 + nl, h = n >> 6, dh = n & 63;
            *(uint32_t*)&g_vt16[(((size_t)bb * NH + h) * NDH + dh) * NS + sbase + s2] =
                *(const uint32_t*)&vt[nl * 136 + s2];
        }
    }
}

// ---------------------------------------------------------------------------
// Output projection: g_ao (tf32-rounded by attn) @ g_wo + bo -> out [B,S,D]
// ---------------------------------------------------------------------------
__global__ __launch_bounds__(256, 2) void out_gemm(
    const float* __restrict__ bo, float* __restrict__ out)
{
    extern __shared__ char sm[];
    const int m0 = blockIdx.y * 128, n0 = blockIdx.x * 128;
    float acc[4][4][4];
    gemm_tf32_core(g_ao, g_wo, sm, m0, n0, acc);

    const int tid = threadIdx.x, wid = tid >> 5, lane = tid & 31;
    const int wm = wid >> 2, wn = wid & 3;
    const int g = lane >> 2, tg = lane & 3;

    #pragma unroll
    for (int mt = 0; mt < 4; mt++) {
        #pragma unroll
        for (int nt = 0; nt < 4; nt++) {
            const int n = n0 + wn * 32 + nt * 8 + 2 * tg;
            float b0 = bo[n], b1 = bo[n + 1];
            #pragma unroll
            for (int half = 0; half < 2; half++) {
                const int r = m0 + wm * 64 + mt * 16 + g + half * 8;
                float2 v = make_float2(acc[mt][nt][2 * half] + b0,
                                       acc[mt][nt][2 * half + 1] + b1);
                *(float2*)&out[(size_t)r * ND + n] = v;
            }
        }
    }
}

// ---------------------------------------------------------------------------
// Flash attention:
//   S = Q(single fp16) x K(single fp16); log2-domain scores (1 mma / frag)
//   O = P(single fp16) x V(single fp16)                     (1 mma / frag)
// 128 q-rows/CTA, 8 warps, 2 CTAs/SM; 3-stage cp.async, ONE barrier/tile.
// ---------------------------------------------------------------------------
#define KV_STRIDE 72                  // 16-bit elems per row (144B, bank-free)
#define ARR_B     (64 * 144)          // 9216 B per array tile
#define ATT_STAGE (2 * ARR_B)         // KF, VT = 18432 B
#define ATT_SMEM  (3 * ATT_STAGE)     // 55296 B dynamic (3-stage)

__global__ __launch_bounds__(256, 2) void attn_kernel(const int* __restrict__ mask)
{
    extern __shared__ char att_sm[];
    __shared__ float mb[3][64];

    const int bh = blockIdx.y;
    const int b  = bh >> 4;
    const int h  = bh & 15;
    const int q0 = blockIdx.x * 128;
    const float* Qp = g_q + (size_t)bh * NS * NDH;
    const unsigned short* KF = g_kf16 + (size_t)bh * NS * NDH;   // [s][d] fp16
    const unsigned short* VT = g_vt16 + (size_t)bh * NS * NDH;   // [d][s] fp16
    const int* mrow = mask + b * NS;

    const int tid = threadIdx.x, wid = tid >> 5, lane = tid & 31;
    const int g = lane >> 2, tg = lane & 3;
    const uint32_t sb = smem_u32(att_sm);

    auto issue = [&](int kb, int bf) {
        const int k0g = kb * 64;
        const uint32_t st = sb + bf * ATT_STAGE;
        #pragma unroll
        for (int i = 0; i < 2; i++) {
            int f = tid + i * 256;
            int row = f >> 3, q = f & 7;
            CP16(st + 0 * ARR_B + row * 144 + q * 16,
                 KF + (size_t)(k0g + row) * NDH + q * 8);           // K: rows = kpos
            CP16(st + 1 * ARR_B + row * 144 + q * 16,
                 VT + (size_t)row * NS + k0g + q * 8);              // V^T: rows = d
        }
        CP_COMMIT();
    };

    // Q fragments (pre-scaled by log2e/8), single fp16, resident in registers
    const float qs = 0.125f * LOG2E;
    uint32_t qh[4][4];
    {
        const float* q0p = Qp + (size_t)(q0 + wid * 16 + g) * NDH;
        const float* q1p = q0p + 8 * NDH;
        #pragma unroll
        for (int kk = 0; kk < 4; kk++) {
            float2 x;
            x = *(const float2*)(q0p + kk * 16 + 2 * tg);
            qh[kk][0] = pack_h2(qs * x.x, qs * x.y);
            x = *(const float2*)(q1p + kk * 16 + 2 * tg);
            qh[kk][1] = pack_h2(qs * x.x, qs * x.y);
            x = *(const float2*)(q0p + kk * 16 + 2 * tg + 8);
            qh[kk][2] = pack_h2(qs * x.x, qs * x.y);
            x = *(const float2*)(q1p + kk * 16 + 2 * tg + 8);
            qh[kk][3] = pack_h2(qs * x.x, qs * x.y);
        }
    }

    float o[8][4];
    #pragma unroll
    for (int nt = 0; nt < 8; nt++)
        #pragma unroll
        for (int i = 0; i < 4; i++) o[nt][i] = 0.f;
    float mrun[2] = {-1e30f, -1e30f}, lrun[2] = {0.f, 0.f};

    issue(0, 0);
    issue(1, 1);
    if (tid < 64) {
        mb[0][tid] = mrow[tid]      ? 0.f : -1e30f;
        mb[1][tid] = mrow[64 + tid] ? 0.f : -1e30f;
    }

    for (int kb = 0; kb < NS / 64; kb++) {
        const int bf = kb % 3;
        if (kb == NS / 64 - 1) CP_WAIT0(); else CP_WAIT1();
        __syncthreads();
        if (kb + 2 < NS / 64) {
            issue(kb + 2, (kb + 2) % 3);
            if (tid < 64)
                mb[(kb + 2) % 3][tid] = mrow[(kb + 2) * 64 + tid] ? 0.f : -1e30f;
        }

        const unsigned short* Ksm = (const unsigned short*)(att_sm + bf * ATT_STAGE);
        const unsigned short* VTs = Ksm + 64 * KV_STRIDE;

        // ---- S (log2 domain) = Q K^T : 1 fp16 mma per fragment ----
        float sc[8][4];
        #pragma unroll
        for (int nt = 0; nt < 8; nt++)
            #pragma unroll
            for (int i = 0; i < 4; i++) sc[nt][i] = 0.f;

        #pragma unroll
        for (int kk = 0; kk < 4; kk++) {
            #pragma unroll
            for (int nt = 0; nt < 8; nt++) {
                const int base = (nt * 8 + g) * KV_STRIDE + kk * 16 + 2 * tg;
                uint32_t kb2[2] = { *(const uint32_t*)&Ksm[base],
                                    *(const uint32_t*)&Ksm[base + 8] };
                mma_fp16(sc[nt], qh[kk], kb2);
            }
        }

        // ---- mask bias ----
        #pragma unroll
        for (int nt = 0; nt < 8; nt++) {
            float2 mv = *(const float2*)&mb[bf][nt * 8 + 2 * tg];
            sc[nt][0] += mv.x; sc[nt][1] += mv.y;
            sc[nt][2] += mv.x; sc[nt][3] += mv.y;
        }

        // ---- online softmax, log2 domain (rows g, g+8; quad shfl) ----
        #pragma unroll
        for (int r = 0; r < 2; r++) {
            float mx = -1e30f;
            #pragma unroll
            for (int nt = 0; nt < 8; nt++)
                mx = fmaxf(mx, fmaxf(sc[nt][2 * r], sc[nt][2 * r + 1]));
            mx = fmaxf(mx, __shfl_xor_sync(0xffffffffu, mx, 1));
            mx = fmaxf(mx, __shfl_xor_sync(0xffffffffu, mx, 2));
            const float mn = fmaxf(mrun[r], mx);
            float sum = 0.f;
            #pragma unroll
            for (int nt = 0; nt < 8; nt++) {
                float p0 = ex2f(sc[nt][2 * r]     - mn);
                float p1 = ex2f(sc[nt][2 * r + 1] - mn);
                sc[nt][2 * r] = p0; sc[nt][2 * r + 1] = p1;
                sum += p0 + p1;
            }
            sum += __shfl_xor_sync(0xffffffffu, sum, 1);
            sum += __shfl_xor_sync(0xffffffffu, sum, 2);
            const float al = ex2f(mrun[r] - mn);
            lrun[r] = lrun[r] * al + sum;
            mrun[r] = mn;
            #pragma unroll
            for (int nt = 0; nt < 8; nt++) {
                o[nt][2 * r]     *= al;
                o[nt][2 * r + 1] *= al;
            }
        }

        // ---- O += P V : single fp16 mma per fragment ----
        #pragma unroll
        for (int kk = 0; kk < 4; kk++) {
            uint32_t ph[4];
            ph[0] = pack_h2(sc[2 * kk][0],     sc[2 * kk][1]);
            ph[1] = pack_h2(sc[2 * kk][2],     sc[2 * kk][3]);
            ph[2] = pack_h2(sc[2 * kk + 1][0], sc[2 * kk + 1][1]);
            ph[3] = pack_h2(sc[2 * kk + 1][2], sc[2 * kk + 1][3]);
            #pragma unroll
            for (int nt = 0; nt < 8; nt++) {
                const int base = (nt * 8 + g) * KV_STRIDE + kk * 16 + 2 * tg;
                uint32_t v2[2] = { *(const uint32_t*)&VTs[base],
                                   *(const uint32_t*)&VTs[base + 8] };
                mma_fp16(o[nt], ph, v2);
            }
        }
        // no trailing barrier: next iteration's top barrier covers reuse
    }

    // ---- normalize + tf32-round + write g_ao [B,S,D] ----
    const float inv0 = 1.0f / lrun[0];
    const float inv1 = 1.0f / lrun[1];
    const int r0 = q0 + wid * 16 + g;
    float* base0 = g_ao + ((size_t)b * NS + r0) * ND + h * NDH;
    float* base1 = base0 + 8 * (size_t)ND;
    #pragma unroll
    for (int nt = 0; nt < 8; nt++) {
        const int col = nt * 8 + 2 * tg;
        *(float2*)(base0 + col) = make_float2(f_tf32r(o[nt][0] * inv0),
                                              f_tf32r(o[nt][1] * inv0));
        *(float2*)(base1 + col) = make_float2(f_tf32r(o[nt][2] * inv1),
                                              f_tf32r(o[nt][3] * inv1));
    }
}

// ---------------------------------------------------------------------------
extern "C" void kernel_launch(void* const* d_in, const int* in_sizes, int n_in,
                              void* d_out, int out_size)
{
    const float* hs  = (const float*)d_in[0];
    const int*   msk = (const int*)  d_in[1];
    const float* Wq  = (const float*)d_in[2];
    const float* bq  = (const float*)d_in[3];
    const float* Wk  = (const float*)d_in[4];
    const float* bk  = (const float*)d_in[5];
    const float* Wv  = (const float*)d_in[6];
    const float* bv  = (const float*)d_in[7];
    const float* emo = (const float*)d_in[8];
    const float* Wo  = (const float*)d_in[9];
    const float* bo  = (const float*)d_in[10];
    float* out = (float*)d_out;

    cudaFuncSetAttribute(qkv_gemm, cudaFuncAttributeMaxDynamicSharedMemorySize, GEMM_SMEM);
    cudaFuncSetAttribute(out_gemm, cudaFuncAttributeMaxDynamicSharedMemorySize, GEMM_SMEM);
    cudaFuncSetAttribute(attn_kernel, cudaFuncAttributeMaxDynamicSharedMemorySize, ATT_SMEM);

    dim3 gr(128, 5);
    round_prep<<<gr, 256>>>(hs, Wq, Wk, Wv, Wo);

    dim3 gqkv(ND / 128, MT / 128, 3);
    qkv_gemm<<<gqkv, 256, GEMM_SMEM>>>(bq, bk, bv, emo);

    dim3 gatt(NS / 128, NB * NH);
    attn_kernel<<<gatt, 256, ATT_SMEM>>>(msk);

    dim3 gout(ND / 128, MT / 128);
    out_gemm<<<gout, 256, GEMM_SMEM>>>(bo, out);
}

// round 11
// speedup vs baseline: 5.6736x; 1.0679x over previous
#include <cuda_runtime.h>
#include <cuda_bf16.h>
#include <cuda_fp16.h>
#include <cstdint>
#include <math.h>

#define NB 2
#define NS 2048
#define ND 1024
#define NH 16
#define NDH 64
#define MT (NB*NS)          // 4096 rows in all GEMMs
#define LOG2E 1.4426950408889634f

// Scratch (allocation-free rule: __device__ globals)
__device__ float g_q [NB*NH*NS*NDH];   // [B,H,S,DH] fp32 (row-major)
__device__ float g_ao[MT*ND];          // attention output, A-FRAGMENT layout
// tf32-pre-rounded GEMM operands in FRAGMENT layouts:
//  A-layout [mb][kb][tile 4096f], B-layout [nb][kb][tile 4096f]
__device__ float g_x [MT*ND];
__device__ float g_wq[ND*ND];
__device__ float g_wk[ND*ND];
__device__ float g_wv[ND*ND];
__device__ float g_wo[ND*ND];
// K: fp16 (natural [bh][s][d]); V: fp16 (transposed [bh][d][s])
__device__ unsigned short g_kf16 [NB*NH*NS*NDH];
__device__ unsigned short g_vt16 [NB*NH*NS*NDH];

// ===========================================================================
// Helpers
// ===========================================================================
__device__ __forceinline__ uint32_t smem_u32(const void* p) {
    uint32_t a;
    asm("{ .reg .u64 t; cvta.to.shared.u64 t, %1; cvt.u32.u64 %0, t; }"
        : "=r"(a) : "l"(p));
    return a;
}

__device__ __forceinline__ float f_tf32r(float x) {   // rna round to tf32 grid
    uint32_t r;
    asm("cvt.rna.tf32.f32 %0, %1;" : "=r"(r) : "f"(x));
    return __uint_as_float(r);
}

__device__ __forceinline__ float ex2f(float x) {      // bare MUFU.EX2, ftz
    float y;
    asm("ex2.approx.ftz.f32 %0, %1;" : "=f"(y) : "f"(x));
    return y;
}

__device__ __forceinline__ void mma_tf32(float (&c)[4],
                                         const uint32_t (&a)[4],
                                         const uint32_t (&b)[2]) {
    asm volatile(
        "mma.sync.aligned.m16n8k8.row.col.f32.tf32.tf32.f32 "
        "{%0,%1,%2,%3}, {%4,%5,%6,%7}, {%8,%9}, {%0,%1,%2,%3};"
        : "+f"(c[0]), "+f"(c[1]), "+f"(c[2]), "+f"(c[3])
        : "r"(a[0]), "r"(a[1]), "r"(a[2]), "r"(a[3]), "r"(b[0]), "r"(b[1]));
}

__device__ __forceinline__ void mma_fp16(float (&c)[4],
                                         const uint32_t (&a)[4],
                                         const uint32_t (&b)[2]) {
    asm volatile(
        "mma.sync.aligned.m16n8k16.row.col.f32.f16.f16.f32 "
        "{%0,%1,%2,%3}, {%4,%5,%6,%7}, {%8,%9}, {%0,%1,%2,%3};"
        : "+f"(c[0]), "+f"(c[1]), "+f"(c[2]), "+f"(c[3])
        : "r"(a[0]), "r"(a[1]), "r"(a[2]), "r"(a[3]), "r"(b[0]), "r"(b[1]));
}

__device__ __forceinline__ uint32_t pack_h2(float x0, float x1) {
    __half2 h = __floats2half2_rn(x0, x1);
    return *(uint32_t*)&h;
}

#define CP16(dst, src) \
    asm volatile("cp.async.cg.shared.global [%0], [%1], 16;" \
                 :: "r"(dst), "l"(src))
#define CP_COMMIT() asm volatile("cp.async.commit_group;" ::: "memory")
#define CP_WAIT1()  asm volatile("cp.async.wait_group 1;" ::: "memory")
#define CP_WAIT0()  asm volatile("cp.async.wait_group 0;" ::: "memory")

// Fragment-layout address helpers (tile = 4096 floats = 16KB)
// A-layout within tile: idx = ((c*8+mf)*32 + lane)*4 + j, lane=g*4+tg,
//   j = khalf*2 + mhalf; m = mf*16 + mhalf*8 + g; k = c*8 + khalf*4 + tg
// B-layout within tile: idx = ((c*16+nf)*32 + lane)*2 + j, lane=g*4+tg,
//   k = c*8 + j*4 + tg; n = nf*8 + g
__device__ __forceinline__ size_t a_frag_off(int m, int k) {
    return ((size_t)((m >> 7) * 32 + (k >> 5))) * 4096
         + (size_t)(((((k >> 3) & 3) * 8 + ((m >> 4) & 7)) * 32
                     + ((m & 7) * 4 + (k & 3))) * 4
                    + (((k >> 2) & 1) * 2 + ((m >> 3) & 1)));
}

#define A_TILE_B  16384
#define STAGE_B   32768
#define GEMM_SMEM (3 * STAGE_B)   // 98304, 3-stage

// ---------------------------------------------------------------------------
// tf32 GEMM core: fragment-layout operands.
// A-frag = 1 LDS.128, B-frag = 1 LDS.64; cp.async = linear 16KB tile copies.
// 3-stage, one barrier per k-tile.
// ---------------------------------------------------------------------------
__device__ __forceinline__ void gemm_tf32_core(
    const float* __restrict__ A, const float* __restrict__ W,
    char* sm, int mblk, int nblk, float (&acc)[4][4][4])
{
    const int tid  = threadIdx.x;
    const int wid  = tid >> 5, lane = tid & 31;
    const int wm   = wid >> 2, wn = wid & 3;

    #pragma unroll
    for (int mt = 0; mt < 4; mt++)
        #pragma unroll
        for (int nt = 0; nt < 4; nt++)
            #pragma unroll
            for (int i = 0; i < 4; i++) acc[mt][nt][i] = 0.f;

    const uint32_t sm_u = smem_u32(sm);

    auto issue_tile = [&](int kt, int bf) {
        const float* srcA = A + (size_t)(mblk * 32 + kt) * 4096;
        const float* srcB = W + (size_t)(nblk * 32 + kt) * 4096;
        const uint32_t as_u = sm_u + bf * STAGE_B;
        const uint32_t bs_u = as_u + A_TILE_B;
        #pragma unroll
        for (int i = 0; i < 4; i++)
            CP16(as_u + (tid + i * 256) * 16, srcA + (tid + i * 256) * 4);
        #pragma unroll
        for (int i = 0; i < 4; i++)
            CP16(bs_u + (tid + i * 256) * 16, srcB + (tid + i * 256) * 4);
        CP_COMMIT();
    };

    issue_tile(0, 0);
    issue_tile(1, 1);

    for (int kt = 0; kt < 32; kt++) {
        const int bf = kt % 3;
        if (kt == 31) CP_WAIT0(); else CP_WAIT1();
        __syncthreads();
        if (kt + 2 < 32) issue_tile(kt + 2, (kt + 2) % 3);

        const float4* As4 = (const float4*)(sm + bf * STAGE_B);
        const uint2*  Bs2 = (const uint2*) (sm + bf * STAGE_B + A_TILE_B);

        #pragma unroll
        for (int c = 0; c < 4; c++) {
            uint32_t a[4][4];
            uint2 bv[4];
            #pragma unroll
            for (int mt = 0; mt < 4; mt++) {
                float4 t = As4[(c * 8 + wm * 4 + mt) * 32 + lane];
                a[mt][0] = __float_as_uint(t.x);
                a[mt][1] = __float_as_uint(t.y);
                a[mt][2] = __float_as_uint(t.z);
                a[mt][3] = __float_as_uint(t.w);
            }
            #pragma unroll
            for (int nt = 0; nt < 4; nt++)
                bv[nt] = Bs2[(c * 16 + wn * 4 + nt) * 32 + lane];
            #pragma unroll
            for (int mt = 0; mt < 4; mt++)
                #pragma unroll
                for (int nt = 0; nt < 4; nt++) {
                    uint32_t b2[2] = { bv[nt].x, bv[nt].y };
                    mma_tf32(acc[mt][nt], a[mt], b2);
                }
        }
        // no trailing barrier: next iteration's top barrier covers reuse
    }
    __syncthreads();   // protect smem reuse by epilogue
}

// ---------------------------------------------------------------------------
// Round prep: X -> g_x (A-layout); Wq/Wk/Wv/Wo -> B-layout. tf32-rounded.
// ---------------------------------------------------------------------------
__global__ __launch_bounds__(256) void round_prep(
    const float* __restrict__ X,  const float* __restrict__ Wq,
    const float* __restrict__ Wk, const float* __restrict__ Wv,
    const float* __restrict__ Wo)
{
    const int z = blockIdx.y;
    if (z == 0) {
        for (int f4 = blockIdx.x * 256 + threadIdx.x; f4 < MT * ND / 4;
             f4 += gridDim.x * 256) {
            const int tile = f4 >> 10, rem = f4 & 1023;
            const int c = rem >> 8, mf = (rem >> 5) & 7, lane = rem & 31;
            const int g = lane >> 2, tg = lane & 3;
            const int mb = tile >> 5, kb = tile & 31;
            const int m = mb * 128 + mf * 16 + g;
            const int k = kb * 32 + c * 8 + tg;
            float4 v;
            v.x = f_tf32r(X[(size_t)(m    ) * ND + k    ]);
            v.y = f_tf32r(X[(size_t)(m + 8) * ND + k    ]);
            v.z = f_tf32r(X[(size_t)(m    ) * ND + k + 4]);
            v.w = f_tf32r(X[(size_t)(m + 8) * ND + k + 4]);
            ((float4*)g_x)[f4] = v;
        }
    } else {
        const float* s = (z == 1) ? Wq : (z == 2) ? Wk : (z == 3) ? Wv : Wo;
        float* d = (z == 1) ? g_wq : (z == 2) ? g_wk : (z == 3) ? g_wv : g_wo;
        for (int f4 = blockIdx.x * 256 + threadIdx.x; f4 < ND * ND / 4;
             f4 += gridDim.x * 256) {
            const int tile = f4 >> 10;
            const int rem4 = (f4 & 1023) * 4;
            const int c = rem4 >> 10, nf = (rem4 >> 6) & 15;
            const int lane0 = (rem4 & 63) >> 1;          // even lane
            const int nb = tile >> 5, kb = tile & 31;
            const int g0 = lane0 >> 2, tg0 = lane0 & 3;
            const int g1 = (lane0 + 1) >> 2, tg1 = (lane0 + 1) & 3;
            const int n0 = nb * 128 + nf * 8 + g0, k0 = kb * 32 + c * 8 + tg0;
            const int n1 = nb * 128 + nf * 8 + g1, k1 = kb * 32 + c * 8 + tg1;
            float4 v;
            v.x = f_tf32r(s[(size_t)(k0    ) * ND + n0]);
            v.y = f_tf32r(s[(size_t)(k0 + 4) * ND + n0]);
            v.z = f_tf32r(s[(size_t)(k1    ) * ND + n1]);
            v.w = f_tf32r(s[(size_t)(k1 + 4) * ND + n1]);
            ((float4*)d)[f4] = v;
        }
    }
}

// ---------------------------------------------------------------------------
// QKV projection: z=0 -> Q fp32 [B,H,S,DH] (+bias+emotion);
//                 z=1 -> K fp16 [bh][s][d];
//                 z=2 -> V fp16 transposed [bh][d][s] (via smem transpose).
// ---------------------------------------------------------------------------
__global__ __launch_bounds__(256, 2) void qkv_gemm(
    const float* __restrict__ bq, const float* __restrict__ bk,
    const float* __restrict__ bv, const float* __restrict__ emo)
{
    extern __shared__ char sm[];
    const int z = blockIdx.z;
    const float* W    = (z == 0) ? g_wq : (z == 1) ? g_wk : g_wv;
    const float* bias = (z == 0) ? bq : (z == 1) ? bk : bv;

    const int m0 = blockIdx.y * 128, n0 = blockIdx.x * 128;
    float acc[4][4][4];
    gemm_tf32_core(g_x, W, sm, blockIdx.y, blockIdx.x, acc);

    const int tid = threadIdx.x, wid = tid >> 5, lane = tid & 31;
    const int wm = wid >> 2, wn = wid & 3;
    const int g = lane >> 2, tg = lane & 3;

    if (z == 0) {
        #pragma unroll
        for (int mt = 0; mt < 4; mt++) {
            #pragma unroll
            for (int nt = 0; nt < 4; nt++) {
                const int n = n0 + wn * 32 + nt * 8 + 2 * tg;
                const int h = n >> 6, dh = n & 63;
                float b0 = bias[n]     + emo[n];
                float b1 = bias[n + 1] + emo[n + 1];
                #pragma unroll
                for (int half = 0; half < 2; half++) {
                    const int r = m0 + wm * 64 + mt * 16 + g + half * 8;
                    const int bb = r >> 11, s = r & (NS - 1);
                    float2 v = make_float2(acc[mt][nt][2 * half] + b0,
                                           acc[mt][nt][2 * half + 1] + b1);
                    *(float2*)&g_q[(((size_t)bb * NH + h) * NS + s) * NDH + dh] = v;
                }
            }
        }
    } else if (z == 1) {
        #pragma unroll
        for (int mt = 0; mt < 4; mt++) {
            #pragma unroll
            for (int nt = 0; nt < 4; nt++) {
                const int n = n0 + wn * 32 + nt * 8 + 2 * tg;
                const int h = n >> 6, dh = n & 63;
                float b0 = bias[n], b1 = bias[n + 1];
                #pragma unroll
                for (int half = 0; half < 2; half++) {
                    const int r = m0 + wm * 64 + mt * 16 + g + half * 8;
                    const int bb = r >> 11, s = r & (NS - 1);
                    uint32_t v = pack_h2(acc[mt][nt][2 * half] + b0,
                                         acc[mt][nt][2 * half + 1] + b1);
                    *(uint32_t*)&g_kf16[(((size_t)bb * NH + h) * NS + s) * NDH + dh] = v;
                }
            }
        }
    } else {
        // V fp16 transposed via smem
        unsigned short* vt = (unsigned short*)sm;   // stride 136 ushorts
        #pragma unroll
        for (int mt = 0; mt < 4; mt++) {
            #pragma unroll
            for (int nt = 0; nt < 4; nt++) {
                const int nl = wn * 32 + nt * 8 + 2 * tg;
                float b0 = bias[n0 + nl], b1 = bias[n0 + nl + 1];
                #pragma unroll
                for (int half = 0; half < 2; half++) {
                    const int sl = wm * 64 + mt * 16 + g + half * 8;
                    vt[nl * 136 + sl]       = __half_as_ushort(
                        __float2half_rn(acc[mt][nt][2 * half] + b0));
                    vt[(nl + 1) * 136 + sl] = __half_as_ushort(
                        __float2half_rn(acc[mt][nt][2 * half + 1] + b1));
                }
            }
        }
        __syncthreads();
        const int bb = m0 >> 11, sbase = m0 & (NS - 1);
        for (int i = tid; i < 128 * 64; i += 256) {
            const int nl = i >> 6, s2 = (i & 63) * 2;
            const int n = n0 + nl, h = n >> 6, dh = n & 63;
            *(uint32_t*)&g_vt16[(((size_t)bb * NH + h) * NDH + dh) * NS + sbase + s2] =
                *(const uint32_t*)&vt[nl * 136 + s2];
        }
    }
}

// ---------------------------------------------------------------------------
// Output projection: g_ao (A-frag layout) @ g_wo (B-layout) + bo -> out
// ---------------------------------------------------------------------------
__global__ __launch_bounds__(256, 2) void out_gemm(
    const float* __restrict__ bo, float* __restrict__ out)
{
    extern __shared__ char sm[];
    const int m0 = blockIdx.y * 128, n0 = blockIdx.x * 128;
    float acc[4][4][4];
    gemm_tf32_core(g_ao, g_wo, sm, blockIdx.y, blockIdx.x, acc);

    const int tid = threadIdx.x, wid = tid >> 5, lane = tid & 31;
    const int wm = wid >> 2, wn = wid & 3;
    const int g = lane >> 2, tg = lane & 3;

    #pragma unroll
    for (int mt = 0; mt < 4; mt++) {
        #pragma unroll
        for (int nt = 0; nt < 4; nt++) {
            const int n = n0 + wn * 32 + nt * 8 + 2 * tg;
            float b0 = bo[n], b1 = bo[n + 1];
            #pragma unroll
            for (int half = 0; half < 2; half++) {
                const int r = m0 + wm * 64 + mt * 16 + g + half * 8;
                float2 v = make_float2(acc[mt][nt][2 * half] + b0,
                                       acc[mt][nt][2 * half + 1] + b1);
                *(float2*)&out[(size_t)r * ND + n] = v;
            }
        }
    }
}

// ---------------------------------------------------------------------------
// Flash attention (unchanged mainloop): S = QK^T fp16, O = PV fp16, log2
// softmax; epilogue writes g_ao in A-FRAGMENT layout (tf32-rounded).
// ---------------------------------------------------------------------------
#define KV_STRIDE 72
#define ARR_B     (64 * 144)
#define ATT_STAGE (2 * ARR_B)
#define ATT_SMEM  (3 * ATT_STAGE)

__global__ __launch_bounds__(256, 2) void attn_kernel(const int* __restrict__ mask)
{
    extern __shared__ char att_sm[];
    __shared__ float mb[3][64];

    const int bh = blockIdx.y;
    const int b  = bh >> 4;
    const int h  = bh & 15;
    const int q0 = blockIdx.x * 128;
    const float* Qp = g_q + (size_t)bh * NS * NDH;
    const unsigned short* KF = g_kf16 + (size_t)bh * NS * NDH;   // [s][d] fp16
    const unsigned short* VT = g_vt16 + (size_t)bh * NS * NDH;   // [d][s] fp16
    const int* mrow = mask + b * NS;

    const int tid = threadIdx.x, wid = tid >> 5, lane = tid & 31;
    const int g = lane >> 2, tg = lane & 3;
    const uint32_t sb = smem_u32(att_sm);

    auto issue = [&](int kb, int bf) {
        const int k0g = kb * 64;
        const uint32_t st = sb + bf * ATT_STAGE;
        #pragma unroll
        for (int i = 0; i < 2; i++) {
            int f = tid + i * 256;
            int row = f >> 3, q = f & 7;
            CP16(st + 0 * ARR_B + row * 144 + q * 16,
                 KF + (size_t)(k0g + row) * NDH + q * 8);
            CP16(st + 1 * ARR_B + row * 144 + q * 16,
                 VT + (size_t)row * NS + k0g + q * 8);
        }
        CP_COMMIT();
    };

    const float qs = 0.125f * LOG2E;
    uint32_t qh[4][4];
    {
        const float* q0p = Qp + (size_t)(q0 + wid * 16 + g) * NDH;
        const float* q1p = q0p + 8 * NDH;
        #pragma unroll
        for (int kk = 0; kk < 4; kk++) {
            float2 x;
            x = *(const float2*)(q0p + kk * 16 + 2 * tg);
            qh[kk][0] = pack_h2(qs * x.x, qs * x.y);
            x = *(const float2*)(q1p + kk * 16 + 2 * tg);
            qh[kk][1] = pack_h2(qs * x.x, qs * x.y);
            x = *(const float2*)(q0p + kk * 16 + 2 * tg + 8);
            qh[kk][2] = pack_h2(qs * x.x, qs * x.y);
            x = *(const float2*)(q1p + kk * 16 + 2 * tg + 8);
            qh[kk][3] = pack_h2(qs * x.x, qs * x.y);
        }
    }

    float o[8][4];
    #pragma unroll
    for (int nt = 0; nt < 8; nt++)
        #pragma unroll
        for (int i = 0; i < 4; i++) o[nt][i] = 0.f;
    float mrun[2] = {-1e30f, -1e30f}, lrun[2] = {0.f, 0.f};

    issue(0, 0);
    issue(1, 1);
    if (tid < 64) {
        mb[0][tid] = mrow[tid]      ? 0.f : -1e30f;
        mb[1][tid] = mrow[64 + tid] ? 0.f : -1e30f;
    }

    for (int kb = 0; kb < NS / 64; kb++) {
        const int bf = kb % 3;
        if (kb == NS / 64 - 1) CP_WAIT0(); else CP_WAIT1();
        __syncthreads();
        if (kb + 2 < NS / 64) {
            issue(kb + 2, (kb + 2) % 3);
            if (tid < 64)
                mb[(kb + 2) % 3][tid] = mrow[(kb + 2) * 64 + tid] ? 0.f : -1e30f;
        }

        const unsigned short* Ksm = (const unsigned short*)(att_sm + bf * ATT_STAGE);
        const unsigned short* VTs = Ksm + 64 * KV_STRIDE;

        float sc[8][4];
        #pragma unroll
        for (int nt = 0; nt < 8; nt++)
            #pragma unroll
            for (int i = 0; i < 4; i++) sc[nt][i] = 0.f;

        #pragma unroll
        for (int kk = 0; kk < 4; kk++) {
            #pragma unroll
            for (int nt = 0; nt < 8; nt++) {
                const int base = (nt * 8 + g) * KV_STRIDE + kk * 16 + 2 * tg;
                uint32_t kb2[2] = { *(const uint32_t*)&Ksm[base],
                                    *(const uint32_t*)&Ksm[base + 8] };
                mma_fp16(sc[nt], qh[kk], kb2);
            }
        }

        #pragma unroll
        for (int nt = 0; nt < 8; nt++) {
            float2 mv = *(const float2*)&mb[bf][nt * 8 + 2 * tg];
            sc[nt][0] += mv.x; sc[nt][1] += mv.y;
            sc[nt][2] += mv.x; sc[nt][3] += mv.y;
        }

        #pragma unroll
        for (int r = 0; r < 2; r++) {
            float mx = -1e30f;
            #pragma unroll
            for (int nt = 0; nt < 8; nt++)
                mx = fmaxf(mx, fmaxf(sc[nt][2 * r], sc[nt][2 * r + 1]));
            mx = fmaxf(mx, __shfl_xor_sync(0xffffffffu, mx, 1));
            mx = fmaxf(mx, __shfl_xor_sync(0xffffffffu, mx, 2));
            const float mn = fmaxf(mrun[r], mx);
            float sum = 0.f;
            #pragma unroll
            for (int nt = 0; nt < 8; nt++) {
                float p0 = ex2f(sc[nt][2 * r]     - mn);
                float p1 = ex2f(sc[nt][2 * r + 1] - mn);
                sc[nt][2 * r] = p0; sc[nt][2 * r + 1] = p1;
                sum += p0 + p1;
            }
            sum += __shfl_xor_sync(0xffffffffu, sum, 1);
            sum += __shfl_xor_sync(0xffffffffu, sum, 2);
            const float al = ex2f(mrun[r] - mn);
            lrun[r] = lrun[r] * al + sum;
            mrun[r] = mn;
            #pragma unroll
            for (int nt = 0; nt < 8; nt++) {
                o[nt][2 * r]     *= al;
                o[nt][2 * r + 1] *= al;
            }
        }

        #pragma unroll
        for (int kk = 0; kk < 4; kk++) {
            uint32_t ph[4];
            ph[0] = pack_h2(sc[2 * kk][0],     sc[2 * kk][1]);
            ph[1] = pack_h2(sc[2 * kk][2],     sc[2 * kk][3]);
            ph[2] = pack_h2(sc[2 * kk + 1][0], sc[2 * kk + 1][1]);
            ph[3] = pack_h2(sc[2 * kk + 1][2], sc[2 * kk + 1][3]);
            #pragma unroll
            for (int nt = 0; nt < 8; nt++) {
                const int base = (nt * 8 + g) * KV_STRIDE + kk * 16 + 2 * tg;
                uint32_t v2[2] = { *(const uint32_t*)&VTs[base],
                                   *(const uint32_t*)&VTs[base + 8] };
                mma_fp16(o[nt], ph, v2);
            }
        }
    }

    // ---- normalize + tf32-round + write g_ao in A-FRAGMENT layout ----
    const float inv0 = 1.0f / lrun[0];
    const float inv1 = 1.0f / lrun[1];
    const int m_lo = b * NS + q0 + wid * 16 + g;
    const int m_hi = m_lo + 8;
    #pragma unroll
    for (int nt = 0; nt < 8; nt++) {
        const int col = h * 64 + nt * 8 + 2 * tg;
        g_ao[a_frag_off(m_lo, col    )] = f_tf32r(o[nt][0] * inv0);
        g_ao[a_frag_off(m_lo, col + 1)] = f_tf32r(o[nt][1] * inv0);
        g_ao[a_frag_off(m_hi, col    )] = f_tf32r(o[nt][2] * inv1);
        g_ao[a_frag_off(m_hi, col + 1)] = f_tf32r(o[nt][3] * inv1);
    }
}

// ---------------------------------------------------------------------------
extern "C" void kernel_launch(void* const* d_in, const int* in_sizes, int n_in,
                              void* d_out, int out_size)
{
    const float* hs  = (const float*)d_in[0];
    const int*   msk = (const int*)  d_in[1];
    const float* Wq  = (const float*)d_in[2];
    const float* bq  = (const float*)d_in[3];
    const float* Wk  = (const float*)d_in[4];
    const float* bk  = (const float*)d_in[5];
    const float* Wv  = (const float*)d_in[6];
    const float* bv  = (const float*)d_in[7];
    const float* emo = (const float*)d_in[8];
    const float* Wo  = (const float*)d_in[9];
    const float* bo  = (const float*)d_in[10];
    float* out = (float*)d_out;

    cudaFuncSetAttribute(qkv_gemm, cudaFuncAttributeMaxDynamicSharedMemorySize, GEMM_SMEM);
    cudaFuncSetAttribute(out_gemm, cudaFuncAttributeMaxDynamicSharedMemorySize, GEMM_SMEM);
    cudaFuncSetAttribute(attn_kernel, cudaFuncAttributeMaxDynamicSharedMemorySize, ATT_SMEM);

    dim3 gr(128, 5);
    round_prep<<<gr, 256>>>(hs, Wq, Wk, Wv, Wo);

    dim3 gqkv(ND / 128, MT / 128, 3);
    qkv_gemm<<<gqkv, 256, GEMM_SMEM>>>(bq, bk, bv, emo);

    dim3 gatt(NS / 128, NB * NH);
    attn_kernel<<<gatt, 256, ATT_SMEM>>>(msk);

    dim3 gout(ND / 128, MT / 128);
    out_gemm<<<gout, 256, GEMM_SMEM>>>(bo, out);
}